// round 5
// baseline (speedup 1.0000x reference)
#include <cuda_runtime.h>
#include <cuda_bf16.h>
#include <math.h>

// Problem constants
#define B_  2
#define S_  2048
#define D_  1024
#define NH  16
#define HD  64
#define NTOK (B_*S_)          // 4096

// ---------------- scratch (static __device__, no allocation) ----------------
__device__ float g_xdelta[NTOK * D_];        // 16 MB
__device__ float g_xstate[B_ * D_];
__device__ float g_W[B_ * 8 * 8];
__device__ float g_normed[NTOK * D_];        // 16 MB
__device__ float g_qkv[NTOK * 3 * D_];       // 48 MB
__device__ float g_o[NTOK * D_];             // 16 MB
__device__ float g_attnres[NTOK * D_];       // 16 MB
__device__ float g_normed2[NTOK * D_];       // 16 MB
__device__ float g_h[NTOK * 4 * D_];         // 64 MB
__device__ float g_ffn[NTOK * D_];           // 16 MB

// ---------------- K1: delta EMA scan (warp-parallel affine scan) -------------
__global__ void delta_scan_kernel(const float* __restrict__ x,
                                  const float* __restrict__ decay,
                                  float* __restrict__ xd,
                                  float* __restrict__ xstate) {
    int warp = (blockIdx.x * blockDim.x + threadIdx.x) >> 5;
    int lane = threadIdx.x & 31;
    if (warp >= B_ * D_) return;
    int b = warp >> 10;
    int d = warp & (D_ - 1);
    float beta = 1.f / (1.f + __expf(-decay[d]));
    float onem = 1.f - beta;

    const float* xp = x  + (size_t)b * S_ * D_ + d;
    float*       op = xd + (size_t)b * S_ * D_ + d;

    float carry = 0.f;
    float sum = 0.f;
    for (int t0 = 0; t0 < S_; t0 += 32) {
        float xt = xp[(size_t)(t0 + lane) * D_];
        // affine map f(s) = a*s + bb
        float a = beta, bb = onem * xt;
        #pragma unroll
        for (int off = 1; off < 32; off <<= 1) {
            float pa = __shfl_up_sync(0xffffffffu, a, off);
            float pb = __shfl_up_sync(0xffffffffu, bb, off);
            if (lane >= off) { bb = a * pb + bb; a = a * pa; }
        }
        float s_incl = a * carry + bb;
        float s_prev = __shfl_up_sync(0xffffffffu, s_incl, 1);
        if (lane == 0) s_prev = carry;
        float out = xt - s_prev;
        op[(size_t)(t0 + lane) * D_] = out;
        sum += out;
        carry = __shfl_sync(0xffffffffu, s_incl, 31);
    }
    #pragma unroll
    for (int off = 16; off >= 1; off >>= 1)
        sum += __shfl_xor_sync(0xffffffffu, sum, off);
    if (lane == 0) xstate[warp] = sum * (1.f / (float)S_);
}

// ---------------- K2: gates + sinkhorn + W --------------------------------
__global__ void gate_sinkhorn_kernel(const float* __restrict__ xstate,
                                     const float* __restrict__ gate_w,
                                     const float* __restrict__ gate_b,
                                     const float* __restrict__ phi,
                                     float* __restrict__ W) {
    __shared__ float gbuf[B_][8];
    __shared__ float Km[64];
    __shared__ float tmp[64];
    int tid = threadIdx.x;
    int wid = tid >> 5, lane = tid & 31;

    // 16 dot products: g_res gates only (rows 16..23 of gate_w)
    for (int idx = wid; idx < 16; idx += 8) {
        int b = idx >> 3;
        int j = 16 + (idx & 7);
        float s = 0.f;
        for (int k = lane; k < D_; k += 32)
            s += xstate[b * D_ + k] * gate_w[j * D_ + k];
        #pragma unroll
        for (int off = 16; off >= 1; off >>= 1)
            s += __shfl_xor_sync(0xffffffffu, s, off);
        if (lane == 0)
            gbuf[b][idx & 7] = 1.f / (1.f + __expf(-(s + gate_b[j])));
    }
    if (tid < 64) Km[tid] = __expf(phi[tid]);
    __syncthreads();

    for (int it = 0; it < 15; it++) {
        if (tid < 64) {
            int m = tid >> 3;
            float rs = 0.f;
            #pragma unroll
            for (int n = 0; n < 8; n++) rs += Km[m * 8 + n];
            tmp[tid] = Km[tid] / rs;
        }
        __syncthreads();
        if (tid < 64) {
            int n = tid & 7;
            float cs = 0.f;
            #pragma unroll
            for (int m = 0; m < 8; m++) cs += tmp[m * 8 + n];
            Km[tid] = tmp[tid] / cs;
        }
        __syncthreads();
    }
    if (tid < 128) {
        int b = tid >> 6, r = tid & 63, n = r & 7;
        W[b * 64 + r] = Km[r] * gbuf[b][n];
    }
}

// ---------------- K3: RMSNorm (block per row) ------------------------------
__global__ void rmsnorm_kernel(const float* __restrict__ x,
                               const float* __restrict__ w,
                               float* __restrict__ y) {
    int row = blockIdx.x;
    int tid = threadIdx.x;
    const float4* xr = (const float4*)(x + (size_t)row * D_);
    float4 v = xr[tid];
    float ss = v.x * v.x + v.y * v.y + v.z * v.z + v.w * v.w;
    __shared__ float red[8];
    #pragma unroll
    for (int off = 16; off >= 1; off >>= 1)
        ss += __shfl_xor_sync(0xffffffffu, ss, off);
    if ((tid & 31) == 0) red[tid >> 5] = ss;
    __syncthreads();
    if (tid < 8) {
        float t = red[tid];
        #pragma unroll
        for (int off = 4; off >= 1; off >>= 1)
            t += __shfl_xor_sync(0xffu, t, off);
        if (tid == 0) red[0] = t;
    }
    __syncthreads();
    float scale = rsqrtf(red[0] * (1.f / (float)D_) + 1e-6f);
    float4 wv = ((const float4*)w)[tid];
    float4 o;
    o.x = v.x * scale * wv.x;
    o.y = v.y * scale * wv.y;
    o.z = v.z * scale * wv.z;
    o.w = v.w * scale * wv.w;
    ((float4*)(y + (size_t)row * D_))[tid] = o;
}

// ---------------- SGEMM NT: C[M,N] = A[M,K]*B[N,K]^T + bias (+res)(+gelu) ---
// EPI: 0 = bias (+ optional residual), 1 = bias + exact GELU
template <int EPI>
__global__ __launch_bounds__(256, 2)
void gemm_nt_kernel(const float* __restrict__ A, const float* __restrict__ Bm,
                    const float* __restrict__ bias, const float* __restrict__ res,
                    float* __restrict__ C, int M, int N, int K) {
    __shared__ float As[16][132];
    __shared__ float Bs[16][132];
    int bm = blockIdx.y * 128;
    int bn = blockIdx.x * 128;
    int tid = threadIdx.x;
    int tx = tid & 15, ty = tid >> 4;

    float acc[8][8];
    #pragma unroll
    for (int i = 0; i < 8; i++)
        #pragma unroll
        for (int j = 0; j < 8; j++) acc[i][j] = 0.f;

    int lr = tid >> 2;        // 0..63
    int lc = tid & 3;         // float4 column 0..3

    for (int k0 = 0; k0 < K; k0 += 16) {
        #pragma unroll
        for (int i = 0; i < 2; i++) {
            int row = lr + i * 64;
            float4 a = *(const float4*)(A + (size_t)(bm + row) * K + k0 + lc * 4);
            As[lc * 4 + 0][row] = a.x;
            As[lc * 4 + 1][row] = a.y;
            As[lc * 4 + 2][row] = a.z;
            As[lc * 4 + 3][row] = a.w;
            float4 b = *(const float4*)(Bm + (size_t)(bn + row) * K + k0 + lc * 4);
            Bs[lc * 4 + 0][row] = b.x;
            Bs[lc * 4 + 1][row] = b.y;
            Bs[lc * 4 + 2][row] = b.z;
            Bs[lc * 4 + 3][row] = b.w;
        }
        __syncthreads();
        #pragma unroll
        for (int kk = 0; kk < 16; kk++) {
            float4 a0 = *(const float4*)&As[kk][ty * 8];
            float4 a1 = *(const float4*)&As[kk][ty * 8 + 4];
            float4 b0 = *(const float4*)&Bs[kk][tx * 8];
            float4 b1 = *(const float4*)&Bs[kk][tx * 8 + 4];
            float af[8] = {a0.x, a0.y, a0.z, a0.w, a1.x, a1.y, a1.z, a1.w};
            float bf[8] = {b0.x, b0.y, b0.z, b0.w, b1.x, b1.y, b1.z, b1.w};
            #pragma unroll
            for (int i = 0; i < 8; i++)
                #pragma unroll
                for (int j = 0; j < 8; j++)
                    acc[i][j] += af[i] * bf[j];
        }
        __syncthreads();
    }

    #pragma unroll
    for (int i = 0; i < 8; i++) {
        int row = bm + ty * 8 + i;
        #pragma unroll
        for (int j4 = 0; j4 < 2; j4++) {
            int col = bn + tx * 8 + j4 * 4;
            float4 v;
            v.x = acc[i][j4 * 4 + 0] + bias[col + 0];
            v.y = acc[i][j4 * 4 + 1] + bias[col + 1];
            v.z = acc[i][j4 * 4 + 2] + bias[col + 2];
            v.w = acc[i][j4 * 4 + 3] + bias[col + 3];
            if (EPI == 1) {
                v.x = 0.5f * v.x * (1.f + erff(v.x * 0.7071067811865476f));
                v.y = 0.5f * v.y * (1.f + erff(v.y * 0.7071067811865476f));
                v.z = 0.5f * v.z * (1.f + erff(v.z * 0.7071067811865476f));
                v.w = 0.5f * v.w * (1.f + erff(v.w * 0.7071067811865476f));
            }
            if (res != nullptr) {
                float4 r = *(const float4*)(res + (size_t)row * N + col);
                v.x += r.x; v.y += r.y; v.z += r.z; v.w += r.w;
            }
            *(float4*)(C + (size_t)row * N + col) = v;
        }
    }
}

// ---------------- K5: flash-style causal attention --------------------------
// qkv: [B,S,3D] ; o: [B,S,D]. Block = (qtile, head, batch). 256 threads.
#define APAD 65
__global__ __launch_bounds__(256)
void attn_kernel(const float* __restrict__ qkv, float* __restrict__ o) {
    extern __shared__ float sm[];
    float* Qs  = sm;                 // 64 x APAD
    float* KPs = sm + 64 * APAD;     // K tile, reused as P tile
    float* Vs  = sm + 2 * 64 * APAD;

    int qt = blockIdx.x, h = blockIdx.y, b = blockIdx.z;
    int tid = threadIdx.x;
    int tx = tid & 15, ty = tid >> 4;
    int qr0 = qt * 64;
    const float* base = qkv + (size_t)b * S_ * (3 * D_);

    for (int i = tid; i < 64 * 64; i += 256) {
        int r = i >> 6, c = i & 63;
        Qs[r * APAD + c] = base[(size_t)(qr0 + r) * (3 * D_) + h * HD + c] * 0.125f;
    }

    float acc[4][4];
    float m_i[4], l_i[4];
    #pragma unroll
    for (int i = 0; i < 4; i++) {
        m_i[i] = -1e30f; l_i[i] = 0.f;
        #pragma unroll
        for (int j = 0; j < 4; j++) acc[i][j] = 0.f;
    }

    for (int jt = 0; jt <= qt; jt++) {
        int jr0 = jt * 64;
        __syncthreads();
        for (int i = tid; i < 64 * 64; i += 256) {
            int r = i >> 6, c = i & 63;
            KPs[r * APAD + c] = base[(size_t)(jr0 + r) * (3 * D_) + D_ + h * HD + c];
            Vs[r * APAD + c]  = base[(size_t)(jr0 + r) * (3 * D_) + 2 * D_ + h * HD + c];
        }
        __syncthreads();

        float s[4][4];
        #pragma unroll
        for (int i = 0; i < 4; i++)
            #pragma unroll
            for (int j = 0; j < 4; j++) s[i][j] = 0.f;

        for (int k = 0; k < 64; k++) {
            float qf[4], kf[4];
            #pragma unroll
            for (int i = 0; i < 4; i++) qf[i] = Qs[(ty * 4 + i) * APAD + k];
            #pragma unroll
            for (int j = 0; j < 4; j++) kf[j] = KPs[(tx * 4 + j) * APAD + k];
            #pragma unroll
            for (int i = 0; i < 4; i++)
                #pragma unroll
                for (int j = 0; j < 4; j++) s[i][j] += qf[i] * kf[j];
        }

        if (jt == qt) {
            #pragma unroll
            for (int i = 0; i < 4; i++)
                #pragma unroll
                for (int j = 0; j < 4; j++)
                    if (jr0 + tx * 4 + j > qr0 + ty * 4 + i) s[i][j] = -1e30f;
        }

        // online softmax (rows = ty*4+i, reduce across the 16 tx lanes = half-warp)
        #pragma unroll
        for (int i = 0; i < 4; i++) {
            float mx = fmaxf(fmaxf(s[i][0], s[i][1]), fmaxf(s[i][2], s[i][3]));
            #pragma unroll
            for (int off = 1; off < 16; off <<= 1)
                mx = fmaxf(mx, __shfl_xor_sync(0xffffffffu, mx, off));
            float nm = fmaxf(m_i[i], mx);
            float ps = 0.f;
            #pragma unroll
            for (int j = 0; j < 4; j++) {
                s[i][j] = __expf(s[i][j] - nm);
                ps += s[i][j];
            }
            #pragma unroll
            for (int off = 1; off < 16; off <<= 1)
                ps += __shfl_xor_sync(0xffffffffu, ps, off);
            float alpha = __expf(m_i[i] - nm);
            l_i[i] = l_i[i] * alpha + ps;
            m_i[i] = nm;
            #pragma unroll
            for (int j = 0; j < 4; j++) acc[i][j] *= alpha;
        }

        __syncthreads();   // done reading KPs as K
        #pragma unroll
        for (int i = 0; i < 4; i++)
            #pragma unroll
            for (int j = 0; j < 4; j++)
                KPs[(ty * 4 + i) * APAD + tx * 4 + j] = s[i][j];
        __syncthreads();

        for (int k = 0; k < 64; k++) {
            float pf[4], vf[4];
            #pragma unroll
            for (int i = 0; i < 4; i++) pf[i] = KPs[(ty * 4 + i) * APAD + k];
            #pragma unroll
            for (int j = 0; j < 4; j++) vf[j] = Vs[k * APAD + tx * 4 + j];
            #pragma unroll
            for (int i = 0; i < 4; i++)
                #pragma unroll
                for (int j = 0; j < 4; j++) acc[i][j] += pf[i] * vf[j];
        }
    }

    #pragma unroll
    for (int i = 0; i < 4; i++) {
        float inv = 1.f / l_i[i];
        #pragma unroll
        for (int j = 0; j < 4; j++)
            o[(size_t)(b * S_ + qr0 + ty * 4 + i) * D_ + h * HD + tx * 4 + j] =
                acc[i][j] * inv;
    }
}

// ---------------- K10: final sum + mhc mix ----------------------------------
__global__ void final_kernel(const float* __restrict__ attnres,
                             const float* __restrict__ ffn,
                             const float* __restrict__ xd,
                             const float* __restrict__ W,
                             float* __restrict__ out) {
    __shared__ float row[D_];
    __shared__ float Ws[64];
    int r = blockIdx.x;
    int b = r >> 11;            // r / 2048
    int tid = threadIdx.x;
    ((float4*)row)[tid] = ((const float4*)(xd + (size_t)r * D_))[tid];
    if (tid < 64) Ws[tid] = W[b * 64 + tid];
    __syncthreads();

    int c0 = tid * 4;
    int m = c0 >> 7;
    int dp = c0 & 127;
    float mh0 = 0.f, mh1 = 0.f, mh2 = 0.f, mh3 = 0.f;
    #pragma unroll
    for (int n = 0; n < 8; n++) {
        float w = Ws[m * 8 + n];
        const float* rp = row + n * 128 + dp;
        mh0 += w * rp[0]; mh1 += w * rp[1]; mh2 += w * rp[2]; mh3 += w * rp[3];
    }
    float4 a = ((const float4*)(attnres + (size_t)r * D_))[tid];
    float4 f = ((const float4*)(ffn + (size_t)r * D_))[tid];
    float4 ov;
    ov.x = a.x + f.x + mh0;
    ov.y = a.y + f.y + mh1;
    ov.z = a.z + f.z + mh2;
    ov.w = a.w + f.w + mh3;
    ((float4*)(out + (size_t)r * D_))[tid] = ov;
}

// ---------------- launch ----------------------------------------------------
extern "C" void kernel_launch(void* const* d_in, const int* in_sizes, int n_in,
                              void* d_out, int out_size) {
    const float* x        = (const float*)d_in[0];
    // d_in[1] rope_cos, d_in[2] rope_sin: unused by the reference
    const float* decay    = (const float*)d_in[3];
    const float* gate_w   = (const float*)d_in[4];
    const float* gate_b   = (const float*)d_in[5];
    const float* phi      = (const float*)d_in[6];
    const float* ln1_w    = (const float*)d_in[7];
    const float* ln2_w    = (const float*)d_in[8];
    const float* w1       = (const float*)d_in[9];
    const float* b1       = (const float*)d_in[10];
    const float* w2       = (const float*)d_in[11];
    const float* b2       = (const float*)d_in[12];
    const float* in_proj_w= (const float*)d_in[13];
    const float* in_proj_b= (const float*)d_in[14];
    const float* out_w    = (const float*)d_in[15];
    const float* out_b    = (const float*)d_in[16];
    float* out = (float*)d_out;

    void *p_xdelta, *p_xstate, *p_W, *p_normed, *p_qkv, *p_o, *p_attnres,
         *p_normed2, *p_h, *p_ffn;
    cudaGetSymbolAddress(&p_xdelta, g_xdelta);
    cudaGetSymbolAddress(&p_xstate, g_xstate);
    cudaGetSymbolAddress(&p_W, g_W);
    cudaGetSymbolAddress(&p_normed, g_normed);
    cudaGetSymbolAddress(&p_qkv, g_qkv);
    cudaGetSymbolAddress(&p_o, g_o);
    cudaGetSymbolAddress(&p_attnres, g_attnres);
    cudaGetSymbolAddress(&p_normed2, g_normed2);
    cudaGetSymbolAddress(&p_h, g_h);
    cudaGetSymbolAddress(&p_ffn, g_ffn);

    float* xdelta  = (float*)p_xdelta;
    float* xstate  = (float*)p_xstate;
    float* Wm      = (float*)p_W;
    float* normed  = (float*)p_normed;
    float* qkv     = (float*)p_qkv;
    float* ob      = (float*)p_o;
    float* attnres = (float*)p_attnres;
    float* normed2 = (float*)p_normed2;
    float* hbuf    = (float*)p_h;
    float* ffn     = (float*)p_ffn;

    // 1) delta scan
    delta_scan_kernel<<<256, 256>>>(x, decay, xdelta, xstate);
    // 2) gates + sinkhorn
    gate_sinkhorn_kernel<<<1, 256>>>(xstate, gate_w, gate_b, phi, Wm);
    // 3) rmsnorm1
    rmsnorm_kernel<<<NTOK, 256>>>(xdelta, ln1_w, normed);
    // 4) qkv projection: [4096,3072] = normed @ in_proj_w^T
    gemm_nt_kernel<0><<<dim3(3 * D_ / 128, NTOK / 128), 256>>>(
        normed, in_proj_w, in_proj_b, nullptr, qkv, NTOK, 3 * D_, D_);
    // 5) attention
    {
        int smem = 3 * 64 * APAD * (int)sizeof(float);
        cudaFuncSetAttribute(attn_kernel,
                             cudaFuncAttributeMaxDynamicSharedMemorySize, smem);
        attn_kernel<<<dim3(S_ / 64, NH, B_), 256, smem>>>(qkv, ob);
    }
    // 6) out projection + residual(x_delta): attnres = xdelta + o@out_w^T + out_b
    gemm_nt_kernel<0><<<dim3(D_ / 128, NTOK / 128), 256>>>(
        ob, out_w, out_b, xdelta, attnres, NTOK, D_, D_);
    // 7) rmsnorm2
    rmsnorm_kernel<<<NTOK, 256>>>(attnres, ln2_w, normed2);
    // 8) FFN1 + gelu
    gemm_nt_kernel<1><<<dim3(4 * D_ / 128, NTOK / 128), 256>>>(
        normed2, w1, b1, nullptr, hbuf, NTOK, 4 * D_, D_);
    // 9) FFN2
    gemm_nt_kernel<0><<<dim3(D_ / 128, NTOK / 128), 256>>>(
        hbuf, w2, b2, nullptr, ffn, NTOK, D_, 4 * D_);
    // 10) final: out = attnres + ffn + mhc
    final_kernel<<<NTOK, 256>>>(attnres, ffn, xdelta, Wm, out);
}

// round 7
// speedup vs baseline: 2.1071x; 2.1071x over previous
#include <cuda_runtime.h>
#include <cuda_bf16.h>
#include <math.h>
#include <stdint.h>

// Problem constants
#define B_  2
#define S_  2048
#define D_  1024
#define NH  16
#define HD  64
#define NTOK (B_*S_)          // 4096

// ---------------- scratch (static __device__, no allocation) ----------------
__device__ float g_xdelta[NTOK * D_];        // 16 MB
__device__ float g_xstate[B_ * D_];
__device__ float g_W[B_ * 8 * 8];
__device__ float g_normed[NTOK * D_];        // 16 MB
__device__ float g_qkv[NTOK * 3 * D_];       // 48 MB
__device__ float g_o[NTOK * D_];             // 16 MB
__device__ float g_attnres[NTOK * D_];       // 16 MB
__device__ float g_normed2[NTOK * D_];       // 16 MB
__device__ float g_h[NTOK * 4 * D_];         // 64 MB
__device__ float g_ffn[NTOK * D_];           // 16 MB

// ---------------- K1: delta EMA scan (warp-parallel affine scan) -------------
__global__ void delta_scan_kernel(const float* __restrict__ x,
                                  const float* __restrict__ decay,
                                  float* __restrict__ xd,
                                  float* __restrict__ xstate) {
    int warp = (blockIdx.x * blockDim.x + threadIdx.x) >> 5;
    int lane = threadIdx.x & 31;
    if (warp >= B_ * D_) return;
    int b = warp >> 10;
    int d = warp & (D_ - 1);
    float beta = 1.f / (1.f + __expf(-decay[d]));
    float onem = 1.f - beta;

    const float* xp = x  + (size_t)b * S_ * D_ + d;
    float*       op = xd + (size_t)b * S_ * D_ + d;

    float carry = 0.f;
    float sum = 0.f;
    for (int t0 = 0; t0 < S_; t0 += 32) {
        float xt = xp[(size_t)(t0 + lane) * D_];
        float a = beta, bb = onem * xt;
        #pragma unroll
        for (int off = 1; off < 32; off <<= 1) {
            float pa = __shfl_up_sync(0xffffffffu, a, off);
            float pb = __shfl_up_sync(0xffffffffu, bb, off);
            if (lane >= off) { bb = a * pb + bb; a = a * pa; }
        }
        float s_incl = a * carry + bb;
        float s_prev = __shfl_up_sync(0xffffffffu, s_incl, 1);
        if (lane == 0) s_prev = carry;
        float out = xt - s_prev;
        op[(size_t)(t0 + lane) * D_] = out;
        sum += out;
        carry = __shfl_sync(0xffffffffu, s_incl, 31);
    }
    #pragma unroll
    for (int off = 16; off >= 1; off >>= 1)
        sum += __shfl_xor_sync(0xffffffffu, sum, off);
    if (lane == 0) xstate[warp] = sum * (1.f / (float)S_);
}

// ---------------- K2: gates + sinkhorn + W --------------------------------
__global__ void gate_sinkhorn_kernel(const float* __restrict__ xstate,
                                     const float* __restrict__ gate_w,
                                     const float* __restrict__ gate_b,
                                     const float* __restrict__ phi,
                                     float* __restrict__ W) {
    __shared__ float gbuf[B_][8];
    __shared__ float Km[64];
    __shared__ float tmp[64];
    int tid = threadIdx.x;
    int wid = tid >> 5, lane = tid & 31;

    for (int idx = wid; idx < 16; idx += 8) {
        int b = idx >> 3;
        int j = 16 + (idx & 7);
        float s = 0.f;
        for (int k = lane; k < D_; k += 32)
            s += xstate[b * D_ + k] * gate_w[j * D_ + k];
        #pragma unroll
        for (int off = 16; off >= 1; off >>= 1)
            s += __shfl_xor_sync(0xffffffffu, s, off);
        if (lane == 0)
            gbuf[b][idx & 7] = 1.f / (1.f + __expf(-(s + gate_b[j])));
    }
    if (tid < 64) Km[tid] = __expf(phi[tid]);
    __syncthreads();

    for (int it = 0; it < 15; it++) {
        if (tid < 64) {
            int m = tid >> 3;
            float rs = 0.f;
            #pragma unroll
            for (int n = 0; n < 8; n++) rs += Km[m * 8 + n];
            tmp[tid] = Km[tid] / rs;
        }
        __syncthreads();
        if (tid < 64) {
            int n = tid & 7;
            float cs = 0.f;
            #pragma unroll
            for (int m = 0; m < 8; m++) cs += tmp[m * 8 + n];
            Km[tid] = tmp[tid] / cs;
        }
        __syncthreads();
    }
    if (tid < 128) {
        int b = tid >> 6, r = tid & 63, n = r & 7;
        W[b * 64 + r] = Km[r] * gbuf[b][n];
    }
}

// ---------------- K3: RMSNorm (block per row) ------------------------------
__global__ void rmsnorm_kernel(const float* __restrict__ x,
                               const float* __restrict__ w,
                               float* __restrict__ y) {
    int row = blockIdx.x;
    int tid = threadIdx.x;
    const float4* xr = (const float4*)(x + (size_t)row * D_);
    float4 v = xr[tid];
    float ss = v.x * v.x + v.y * v.y + v.z * v.z + v.w * v.w;
    __shared__ float red[8];
    #pragma unroll
    for (int off = 16; off >= 1; off >>= 1)
        ss += __shfl_xor_sync(0xffffffffu, ss, off);
    if ((tid & 31) == 0) red[tid >> 5] = ss;
    __syncthreads();
    if (tid < 8) {
        float t = red[tid];
        #pragma unroll
        for (int off = 4; off >= 1; off >>= 1)
            t += __shfl_xor_sync(0xffu, t, off);
        if (tid == 0) red[0] = t;
    }
    __syncthreads();
    float scale = rsqrtf(red[0] * (1.f / (float)D_) + 1e-6f);
    float4 wv = ((const float4*)w)[tid];
    float4 o;
    o.x = v.x * scale * wv.x;
    o.y = v.y * scale * wv.y;
    o.z = v.z * scale * wv.z;
    o.w = v.w * scale * wv.w;
    ((float4*)(y + (size_t)row * D_))[tid] = o;
}

// ---------------- TF32 tensor-core helpers ----------------------------------
__device__ __forceinline__ unsigned int f2tf32(float v) {
    unsigned int r;
    asm("cvt.rna.tf32.f32 %0, %1;" : "=r"(r) : "f"(v));
    return r;
}
__device__ __forceinline__ void mma_tf32(float* c, const unsigned int* a,
                                         const unsigned int* b) {
    asm volatile(
        "mma.sync.aligned.m16n8k8.row.col.f32.tf32.tf32.f32 "
        "{%0,%1,%2,%3}, {%4,%5,%6,%7}, {%8,%9}, {%0,%1,%2,%3};"
        : "+f"(c[0]), "+f"(c[1]), "+f"(c[2]), "+f"(c[3])
        : "r"(a[0]), "r"(a[1]), "r"(a[2]), "r"(a[3]), "r"(b[0]), "r"(b[1]));
}
__device__ __forceinline__ void cp_async16(void* smem, const void* gmem) {
    unsigned int s = (unsigned int)__cvta_generic_to_shared(smem);
    asm volatile("cp.async.cg.shared.global [%0], [%1], 16;\n" :: "r"(s), "l"(gmem));
}

// ---------------- TF32 SGEMM NT: C = A[M,K]*B[N,K]^T + bias (+res)(+gelu) ----
// Block 128x128x32, 8 warps each 64x32, mma m16n8k8 tf32.
// EPI: 0 = bias (+ optional residual), 1 = bias + exact GELU
#define GPITCH 36                       // 144B row pitch: 16B-aligned, conflict-free
#define GEMM_SMEM (2 * 2 * 128 * GPITCH * 4)   // 73728 bytes

template <int EPI>
__global__ __launch_bounds__(256, 2)
void gemm_tf32_kernel(const float* __restrict__ A, const float* __restrict__ Bm,
                      const float* __restrict__ bias, const float* __restrict__ res,
                      float* __restrict__ C, int M, int N, int K) {
    extern __shared__ float sm[];
    float* As = sm;                     // [2][128][GPITCH]
    float* Bs = sm + 2 * 128 * GPITCH;

    int bm = blockIdx.y * 128;
    int bn = blockIdx.x * 128;
    int tid = threadIdx.x;
    int warp = tid >> 5, lane = tid & 31;
    int wm = (warp & 1) * 64;
    int wn = (warp >> 1) * 32;
    int g = lane >> 2, t = lane & 3;

    float acc[4][4][4];
    #pragma unroll
    for (int mi = 0; mi < 4; mi++)
        #pragma unroll
        for (int ni = 0; ni < 4; ni++)
            #pragma unroll
            for (int r = 0; r < 4; r++) acc[mi][ni][r] = 0.f;

    int KT = K >> 5;

    // prologue: stage 0
    #pragma unroll
    for (int i = 0; i < 4; i++) {
        int c = i * 256 + tid;
        int row = c >> 3, cc = c & 7;
        cp_async16(&As[row * GPITCH + cc * 4], A + (size_t)(bm + row) * K + cc * 4);
        cp_async16(&Bs[row * GPITCH + cc * 4], Bm + (size_t)(bn + row) * K + cc * 4);
    }
    asm volatile("cp.async.commit_group;\n");

    int buf = 0;
    for (int kt = 0; kt < KT; kt++) {
        if (kt + 1 < KT) {
            int k0 = (kt + 1) << 5;
            int boff = (buf ^ 1) * 128 * GPITCH;
            #pragma unroll
            for (int i = 0; i < 4; i++) {
                int c = i * 256 + tid;
                int row = c >> 3, cc = c & 7;
                cp_async16(&As[boff + row * GPITCH + cc * 4],
                           A + (size_t)(bm + row) * K + k0 + cc * 4);
                cp_async16(&Bs[boff + row * GPITCH + cc * 4],
                           Bm + (size_t)(bn + row) * K + k0 + cc * 4);
            }
            asm volatile("cp.async.commit_group;\n");
            asm volatile("cp.async.wait_group 1;\n");
        } else {
            asm volatile("cp.async.wait_group 0;\n");
        }
        __syncthreads();

        const float* Ab = As + buf * 128 * GPITCH;
        const float* Bb = Bs + buf * 128 * GPITCH;
        #pragma unroll
        for (int kk = 0; kk < 32; kk += 8) {
            unsigned int af[4][4], bf[4][2];
            #pragma unroll
            for (int mi = 0; mi < 4; mi++) {
                const float* ap = Ab + (wm + mi * 16 + g) * GPITCH + kk + t;
                af[mi][0] = f2tf32(ap[0]);
                af[mi][1] = f2tf32(ap[8 * GPITCH]);
                af[mi][2] = f2tf32(ap[4]);
                af[mi][3] = f2tf32(ap[8 * GPITCH + 4]);
            }
            #pragma unroll
            for (int ni = 0; ni < 4; ni++) {
                const float* bp = Bb + (wn + ni * 8 + g) * GPITCH + kk + t;
                bf[ni][0] = f2tf32(bp[0]);
                bf[ni][1] = f2tf32(bp[4]);
            }
            #pragma unroll
            for (int mi = 0; mi < 4; mi++)
                #pragma unroll
                for (int ni = 0; ni < 4; ni++)
                    mma_tf32(acc[mi][ni], af[mi], bf[ni]);
        }
        __syncthreads();
        buf ^= 1;
    }

    // epilogue
    #pragma unroll
    for (int mi = 0; mi < 4; mi++) {
        #pragma unroll
        for (int ni = 0; ni < 4; ni++) {
            int col = bn + wn + ni * 8 + t * 2;
            #pragma unroll
            for (int half = 0; half < 2; half++) {
                int row = bm + wm + mi * 16 + g + half * 8;
                float2 v;
                v.x = acc[mi][ni][half * 2 + 0] + bias[col + 0];
                v.y = acc[mi][ni][half * 2 + 1] + bias[col + 1];
                if (EPI == 1) {
                    v.x = 0.5f * v.x * (1.f + erff(v.x * 0.7071067811865476f));
                    v.y = 0.5f * v.y * (1.f + erff(v.y * 0.7071067811865476f));
                }
                if (res != nullptr) {
                    float2 r = *(const float2*)(res + (size_t)row * N + col);
                    v.x += r.x; v.y += r.y;
                }
                *(float2*)(C + (size_t)row * N + col) = v;
            }
        }
    }
}

// ---------------- K5: flash-style causal attention --------------------------
#define APAD 65
__global__ __launch_bounds__(256)
void attn_kernel(const float* __restrict__ qkv, float* __restrict__ o) {
    extern __shared__ float sm[];
    float* Qs  = sm;
    float* KPs = sm + 64 * APAD;
    float* Vs  = sm + 2 * 64 * APAD;

    int qt = blockIdx.x, h = blockIdx.y, b = blockIdx.z;
    int tid = threadIdx.x;
    int tx = tid & 15, ty = tid >> 4;
    int qr0 = qt * 64;
    const float* base = qkv + (size_t)b * S_ * (3 * D_);

    for (int i = tid; i < 64 * 64; i += 256) {
        int r = i >> 6, c = i & 63;
        Qs[r * APAD + c] = base[(size_t)(qr0 + r) * (3 * D_) + h * HD + c] * 0.125f;
    }

    float acc[4][4];
    float m_i[4], l_i[4];
    #pragma unroll
    for (int i = 0; i < 4; i++) {
        m_i[i] = -1e30f; l_i[i] = 0.f;
        #pragma unroll
        for (int j = 0; j < 4; j++) acc[i][j] = 0.f;
    }

    for (int jt = 0; jt <= qt; jt++) {
        int jr0 = jt * 64;
        __syncthreads();
        for (int i = tid; i < 64 * 64; i += 256) {
            int r = i >> 6, c = i & 63;
            KPs[r * APAD + c] = base[(size_t)(jr0 + r) * (3 * D_) + D_ + h * HD + c];
            Vs[r * APAD + c]  = base[(size_t)(jr0 + r) * (3 * D_) + 2 * D_ + h * HD + c];
        }
        __syncthreads();

        float s[4][4];
        #pragma unroll
        for (int i = 0; i < 4; i++)
            #pragma unroll
            for (int j = 0; j < 4; j++) s[i][j] = 0.f;

        for (int k = 0; k < 64; k++) {
            float qf[4], kf[4];
            #pragma unroll
            for (int i = 0; i < 4; i++) qf[i] = Qs[(ty * 4 + i) * APAD + k];
            #pragma unroll
            for (int j = 0; j < 4; j++) kf[j] = KPs[(tx * 4 + j) * APAD + k];
            #pragma unroll
            for (int i = 0; i < 4; i++)
                #pragma unroll
                for (int j = 0; j < 4; j++) s[i][j] += qf[i] * kf[j];
        }

        if (jt == qt) {
            #pragma unroll
            for (int i = 0; i < 4; i++)
                #pragma unroll
                for (int j = 0; j < 4; j++)
                    if (jr0 + tx * 4 + j > qr0 + ty * 4 + i) s[i][j] = -1e30f;
        }

        #pragma unroll
        for (int i = 0; i < 4; i++) {
            float mx = fmaxf(fmaxf(s[i][0], s[i][1]), fmaxf(s[i][2], s[i][3]));
            #pragma unroll
            for (int off = 1; off < 16; off <<= 1)
                mx = fmaxf(mx, __shfl_xor_sync(0xffffffffu, mx, off));
            float nm = fmaxf(m_i[i], mx);
            float ps = 0.f;
            #pragma unroll
            for (int j = 0; j < 4; j++) {
                s[i][j] = __expf(s[i][j] - nm);
                ps += s[i][j];
            }
            #pragma unroll
            for (int off = 1; off < 16; off <<= 1)
                ps += __shfl_xor_sync(0xffffffffu, ps, off);
            float alpha = __expf(m_i[i] - nm);
            l_i[i] = l_i[i] * alpha + ps;
            m_i[i] = nm;
            #pragma unroll
            for (int j = 0; j < 4; j++) acc[i][j] *= alpha;
        }

        __syncthreads();
        #pragma unroll
        for (int i = 0; i < 4; i++)
            #pragma unroll
            for (int j = 0; j < 4; j++)
                KPs[(ty * 4 + i) * APAD + tx * 4 + j] = s[i][j];
        __syncthreads();

        for (int k = 0; k < 64; k++) {
            float pf[4], vf[4];
            #pragma unroll
            for (int i = 0; i < 4; i++) pf[i] = KPs[(ty * 4 + i) * APAD + k];
            #pragma unroll
            for (int j = 0; j < 4; j++) vf[j] = Vs[k * APAD + tx * 4 + j];
            #pragma unroll
            for (int i = 0; i < 4; i++)
                #pragma unroll
                for (int j = 0; j < 4; j++) acc[i][j] += pf[i] * vf[j];
        }
    }

    #pragma unroll
    for (int i = 0; i < 4; i++) {
        float inv = 1.f / l_i[i];
        #pragma unroll
        for (int j = 0; j < 4; j++)
            o[(size_t)(b * S_ + qr0 + ty * 4 + i) * D_ + h * HD + tx * 4 + j] =
                acc[i][j] * inv;
    }
}

// ---------------- K10: final sum + mhc mix ----------------------------------
__global__ void final_kernel(const float* __restrict__ attnres,
                             const float* __restrict__ ffn,
                             const float* __restrict__ xd,
                             const float* __restrict__ W,
                             float* __restrict__ out) {
    __shared__ float row[D_];
    __shared__ float Ws[64];
    int r = blockIdx.x;
    int b = r >> 11;
    int tid = threadIdx.x;
    ((float4*)row)[tid] = ((const float4*)(xd + (size_t)r * D_))[tid];
    if (tid < 64) Ws[tid] = W[b * 64 + tid];
    __syncthreads();

    int c0 = tid * 4;
    int m = c0 >> 7;
    int dp = c0 & 127;
    float mh0 = 0.f, mh1 = 0.f, mh2 = 0.f, mh3 = 0.f;
    #pragma unroll
    for (int n = 0; n < 8; n++) {
        float w = Ws[m * 8 + n];
        const float* rp = row + n * 128 + dp;
        mh0 += w * rp[0]; mh1 += w * rp[1]; mh2 += w * rp[2]; mh3 += w * rp[3];
    }
    float4 a = ((const float4*)(attnres + (size_t)r * D_))[tid];
    float4 f = ((const float4*)(ffn + (size_t)r * D_))[tid];
    float4 ov;
    ov.x = a.x + f.x + mh0;
    ov.y = a.y + f.y + mh1;
    ov.z = a.z + f.z + mh2;
    ov.w = a.w + f.w + mh3;
    ((float4*)(out + (size_t)r * D_))[tid] = ov;
}

// ---------------- launch ----------------------------------------------------
extern "C" void kernel_launch(void* const* d_in, const int* in_sizes, int n_in,
                              void* d_out, int out_size) {
    const float* x        = (const float*)d_in[0];
    const float* decay    = (const float*)d_in[3];
    const float* gate_w   = (const float*)d_in[4];
    const float* gate_b   = (const float*)d_in[5];
    const float* phi      = (const float*)d_in[6];
    const float* ln1_w    = (const float*)d_in[7];
    const float* ln2_w    = (const float*)d_in[8];
    const float* w1       = (const float*)d_in[9];
    const float* b1       = (const float*)d_in[10];
    const float* w2       = (const float*)d_in[11];
    const float* b2       = (const float*)d_in[12];
    const float* in_proj_w= (const float*)d_in[13];
    const float* in_proj_b= (const float*)d_in[14];
    const float* out_w    = (const float*)d_in[15];
    const float* out_b    = (const float*)d_in[16];
    float* out = (float*)d_out;

    void *p_xdelta, *p_xstate, *p_W, *p_normed, *p_qkv, *p_o, *p_attnres,
         *p_normed2, *p_h, *p_ffn;
    cudaGetSymbolAddress(&p_xdelta, g_xdelta);
    cudaGetSymbolAddress(&p_xstate, g_xstate);
    cudaGetSymbolAddress(&p_W, g_W);
    cudaGetSymbolAddress(&p_normed, g_normed);
    cudaGetSymbolAddress(&p_qkv, g_qkv);
    cudaGetSymbolAddress(&p_o, g_o);
    cudaGetSymbolAddress(&p_attnres, g_attnres);
    cudaGetSymbolAddress(&p_normed2, g_normed2);
    cudaGetSymbolAddress(&p_h, g_h);
    cudaGetSymbolAddress(&p_ffn, g_ffn);

    float* xdelta  = (float*)p_xdelta;
    float* xstate  = (float*)p_xstate;
    float* Wm      = (float*)p_W;
    float* normed  = (float*)p_normed;
    float* qkv     = (float*)p_qkv;
    float* ob      = (float*)p_o;
    float* attnres = (float*)p_attnres;
    float* normed2 = (float*)p_normed2;
    float* hbuf    = (float*)p_h;
    float* ffn     = (float*)p_ffn;

    cudaFuncSetAttribute(gemm_tf32_kernel<0>,
                         cudaFuncAttributeMaxDynamicSharedMemorySize, GEMM_SMEM);
    cudaFuncSetAttribute(gemm_tf32_kernel<1>,
                         cudaFuncAttributeMaxDynamicSharedMemorySize, GEMM_SMEM);

    // 1) delta scan
    delta_scan_kernel<<<256, 256>>>(x, decay, xdelta, xstate);
    // 2) gates + sinkhorn
    gate_sinkhorn_kernel<<<1, 256>>>(xstate, gate_w, gate_b, phi, Wm);
    // 3) rmsnorm1
    rmsnorm_kernel<<<NTOK, 256>>>(xdelta, ln1_w, normed);
    // 4) qkv projection
    gemm_tf32_kernel<0><<<dim3(3 * D_ / 128, NTOK / 128), 256, GEMM_SMEM>>>(
        normed, in_proj_w, in_proj_b, nullptr, qkv, NTOK, 3 * D_, D_);
    // 5) attention
    {
        int smem = 3 * 64 * APAD * (int)sizeof(float);
        cudaFuncSetAttribute(attn_kernel,
                             cudaFuncAttributeMaxDynamicSharedMemorySize, smem);
        attn_kernel<<<dim3(S_ / 64, NH, B_), 256, smem>>>(qkv, ob);
    }
    // 6) out projection + residual(x_delta)
    gemm_tf32_kernel<0><<<dim3(D_ / 128, NTOK / 128), 256, GEMM_SMEM>>>(
        ob, out_w, out_b, xdelta, attnres, NTOK, D_, D_);
    // 7) rmsnorm2
    rmsnorm_kernel<<<NTOK, 256>>>(attnres, ln2_w, normed2);
    // 8) FFN1 + gelu
    gemm_tf32_kernel<1><<<dim3(4 * D_ / 128, NTOK / 128), 256, GEMM_SMEM>>>(
        normed2, w1, b1, nullptr, hbuf, NTOK, 4 * D_, D_);
    // 9) FFN2
    gemm_tf32_kernel<0><<<dim3(D_ / 128, NTOK / 128), 256, GEMM_SMEM>>>(
        hbuf, w2, b2, nullptr, ffn, NTOK, D_, 4 * D_);
    // 10) final
    final_kernel<<<NTOK, 256>>>(attnres, ffn, xdelta, Wm, out);
}

// round 8
// speedup vs baseline: 2.7236x; 1.2926x over previous
#include <cuda_runtime.h>
#include <cuda_bf16.h>
#include <math.h>
#include <stdint.h>

// Problem constants
#define B_  2
#define S_  2048
#define D_  1024
#define NH  16
#define HD  64
#define NTOK (B_*S_)          // 4096

// ---------------- scratch (static __device__, no allocation) ----------------
__device__ float g_xdelta[NTOK * D_];
__device__ float g_xstate[B_ * D_];
__device__ float g_W[B_ * 8 * 8];
__device__ float g_normed[NTOK * D_];
__device__ float g_qkv[NTOK * 3 * D_];
__device__ float g_o[NTOK * D_];
__device__ float g_attnres[NTOK * D_];
__device__ float g_normed2[NTOK * D_];
__device__ float g_h[NTOK * 4 * D_];
__device__ float g_ffn[NTOK * D_];

// ---------------- K1: delta EMA scan (warp-parallel affine scan) -------------
__global__ void delta_scan_kernel(const float* __restrict__ x,
                                  const float* __restrict__ decay,
                                  float* __restrict__ xd,
                                  float* __restrict__ xstate) {
    int warp = (blockIdx.x * blockDim.x + threadIdx.x) >> 5;
    int lane = threadIdx.x & 31;
    if (warp >= B_ * D_) return;
    int b = warp >> 10;
    int d = warp & (D_ - 1);
    float beta = 1.f / (1.f + __expf(-decay[d]));
    float onem = 1.f - beta;

    const float* xp = x  + (size_t)b * S_ * D_ + d;
    float*       op = xd + (size_t)b * S_ * D_ + d;

    float carry = 0.f;
    float sum = 0.f;
    for (int t0 = 0; t0 < S_; t0 += 32) {
        float xt = xp[(size_t)(t0 + lane) * D_];
        float a = beta, bb = onem * xt;
        #pragma unroll
        for (int off = 1; off < 32; off <<= 1) {
            float pa = __shfl_up_sync(0xffffffffu, a, off);
            float pb = __shfl_up_sync(0xffffffffu, bb, off);
            if (lane >= off) { bb = a * pb + bb; a = a * pa; }
        }
        float s_incl = a * carry + bb;
        float s_prev = __shfl_up_sync(0xffffffffu, s_incl, 1);
        if (lane == 0) s_prev = carry;
        float out = xt - s_prev;
        op[(size_t)(t0 + lane) * D_] = out;
        sum += out;
        carry = __shfl_sync(0xffffffffu, s_incl, 31);
    }
    #pragma unroll
    for (int off = 16; off >= 1; off >>= 1)
        sum += __shfl_xor_sync(0xffffffffu, sum, off);
    if (lane == 0) xstate[warp] = sum * (1.f / (float)S_);
}

// ---------------- K2: gates + sinkhorn + W --------------------------------
__global__ void gate_sinkhorn_kernel(const float* __restrict__ xstate,
                                     const float* __restrict__ gate_w,
                                     const float* __restrict__ gate_b,
                                     const float* __restrict__ phi,
                                     float* __restrict__ W) {
    __shared__ float gbuf[B_][8];
    __shared__ float Km[64];
    __shared__ float tmp[64];
    int tid = threadIdx.x;
    int wid = tid >> 5, lane = tid & 31;

    for (int idx = wid; idx < 16; idx += 8) {
        int b = idx >> 3;
        int j = 16 + (idx & 7);
        float s = 0.f;
        for (int k = lane; k < D_; k += 32)
            s += xstate[b * D_ + k] * gate_w[j * D_ + k];
        #pragma unroll
        for (int off = 16; off >= 1; off >>= 1)
            s += __shfl_xor_sync(0xffffffffu, s, off);
        if (lane == 0)
            gbuf[b][idx & 7] = 1.f / (1.f + __expf(-(s + gate_b[j])));
    }
    if (tid < 64) Km[tid] = __expf(phi[tid]);
    __syncthreads();

    for (int it = 0; it < 15; it++) {
        if (tid < 64) {
            int m = tid >> 3;
            float rs = 0.f;
            #pragma unroll
            for (int n = 0; n < 8; n++) rs += Km[m * 8 + n];
            tmp[tid] = Km[tid] / rs;
        }
        __syncthreads();
        if (tid < 64) {
            int n = tid & 7;
            float cs = 0.f;
            #pragma unroll
            for (int m = 0; m < 8; m++) cs += tmp[m * 8 + n];
            Km[tid] = tmp[tid] / cs;
        }
        __syncthreads();
    }
    if (tid < 128) {
        int b = tid >> 6, r = tid & 63, n = r & 7;
        W[b * 64 + r] = Km[r] * gbuf[b][n];
    }
}

// ---------------- K3: RMSNorm (block per row) ------------------------------
__global__ void rmsnorm_kernel(const float* __restrict__ x,
                               const float* __restrict__ w,
                               float* __restrict__ y) {
    int row = blockIdx.x;
    int tid = threadIdx.x;
    const float4* xr = (const float4*)(x + (size_t)row * D_);
    float4 v = xr[tid];
    float ss = v.x * v.x + v.y * v.y + v.z * v.z + v.w * v.w;
    __shared__ float red[8];
    #pragma unroll
    for (int off = 16; off >= 1; off >>= 1)
        ss += __shfl_xor_sync(0xffffffffu, ss, off);
    if ((tid & 31) == 0) red[tid >> 5] = ss;
    __syncthreads();
    if (tid < 8) {
        float t = red[tid];
        #pragma unroll
        for (int off = 4; off >= 1; off >>= 1)
            t += __shfl_xor_sync(0xffu, t, off);
        if (tid == 0) red[0] = t;
    }
    __syncthreads();
    float scale = rsqrtf(red[0] * (1.f / (float)D_) + 1e-6f);
    float4 wv = ((const float4*)w)[tid];
    float4 o;
    o.x = v.x * scale * wv.x;
    o.y = v.y * scale * wv.y;
    o.z = v.z * scale * wv.z;
    o.w = v.w * scale * wv.w;
    ((float4*)(y + (size_t)row * D_))[tid] = o;
}

// ---------------- TF32 tensor-core helpers ----------------------------------
__device__ __forceinline__ unsigned int f2tf32(float v) {
    unsigned int r;
    asm("cvt.rna.tf32.f32 %0, %1;" : "=r"(r) : "f"(v));
    return r;
}
__device__ __forceinline__ float f2tf32f(float v) {
    unsigned int r;
    asm("cvt.rna.tf32.f32 %0, %1;" : "=r"(r) : "f"(v));
    return __uint_as_float(r);
}
__device__ __forceinline__ void mma_tf32(float* c, const unsigned int* a,
                                         const unsigned int* b) {
    asm volatile(
        "mma.sync.aligned.m16n8k8.row.col.f32.tf32.tf32.f32 "
        "{%0,%1,%2,%3}, {%4,%5,%6,%7}, {%8,%9}, {%0,%1,%2,%3};"
        : "+f"(c[0]), "+f"(c[1]), "+f"(c[2]), "+f"(c[3])
        : "r"(a[0]), "r"(a[1]), "r"(a[2]), "r"(a[3]), "r"(b[0]), "r"(b[1]));
}
__device__ __forceinline__ void cp_async16(void* smem, const void* gmem) {
    unsigned int s = (unsigned int)__cvta_generic_to_shared(smem);
    asm volatile("cp.async.cg.shared.global [%0], [%1], 16;\n" :: "r"(s), "l"(gmem));
}

// ---------------- TF32 SGEMM NT: C = A[M,K]*B[N,K]^T + bias (+res)(+gelu) ----
#define GPITCH 36
#define GEMM_SMEM (2 * 2 * 128 * GPITCH * 4)   // 73728 bytes

template <int EPI>
__global__ __launch_bounds__(256, 2)
void gemm_tf32_kernel(const float* __restrict__ A, const float* __restrict__ Bm,
                      const float* __restrict__ bias, const float* __restrict__ res,
                      float* __restrict__ C, int M, int N, int K) {
    extern __shared__ float sm[];
    float* As = sm;                     // [2][128][GPITCH]
    float* Bs = sm + 2 * 128 * GPITCH;

    int bm = blockIdx.y * 128;
    int bn = blockIdx.x * 128;
    int tid = threadIdx.x;
    int warp = tid >> 5, lane = tid & 31;
    int wm = (warp & 1) * 64;
    int wn = (warp >> 1) * 32;
    int g = lane >> 2, t = lane & 3;

    float acc[4][4][4];
    #pragma unroll
    for (int mi = 0; mi < 4; mi++)
        #pragma unroll
        for (int ni = 0; ni < 4; ni++)
            #pragma unroll
            for (int r = 0; r < 4; r++) acc[mi][ni][r] = 0.f;

    int KT = K >> 5;

    #pragma unroll
    for (int i = 0; i < 4; i++) {
        int c = i * 256 + tid;
        int row = c >> 3, cc = c & 7;
        cp_async16(&As[row * GPITCH + cc * 4], A + (size_t)(bm + row) * K + cc * 4);
        cp_async16(&Bs[row * GPITCH + cc * 4], Bm + (size_t)(bn + row) * K + cc * 4);
    }
    asm volatile("cp.async.commit_group;\n");

    int buf = 0;
    for (int kt = 0; kt < KT; kt++) {
        if (kt + 1 < KT) {
            int k0 = (kt + 1) << 5;
            int boff = (buf ^ 1) * 128 * GPITCH;
            #pragma unroll
            for (int i = 0; i < 4; i++) {
                int c = i * 256 + tid;
                int row = c >> 3, cc = c & 7;
                cp_async16(&As[boff + row * GPITCH + cc * 4],
                           A + (size_t)(bm + row) * K + k0 + cc * 4);
                cp_async16(&Bs[boff + row * GPITCH + cc * 4],
                           Bm + (size_t)(bn + row) * K + k0 + cc * 4);
            }
            asm volatile("cp.async.commit_group;\n");
            asm volatile("cp.async.wait_group 1;\n");
        } else {
            asm volatile("cp.async.wait_group 0;\n");
        }
        __syncthreads();

        const float* Ab = As + buf * 128 * GPITCH;
        const float* Bb = Bs + buf * 128 * GPITCH;
        #pragma unroll
        for (int kk = 0; kk < 32; kk += 8) {
            unsigned int af[4][4], bf[4][2];
            #pragma unroll
            for (int mi = 0; mi < 4; mi++) {
                const float* ap = Ab + (wm + mi * 16 + g) * GPITCH + kk + t;
                af[mi][0] = f2tf32(ap[0]);
                af[mi][1] = f2tf32(ap[8 * GPITCH]);
                af[mi][2] = f2tf32(ap[4]);
                af[mi][3] = f2tf32(ap[8 * GPITCH + 4]);
            }
            #pragma unroll
            for (int ni = 0; ni < 4; ni++) {
                const float* bp = Bb + (wn + ni * 8 + g) * GPITCH + kk + t;
                bf[ni][0] = f2tf32(bp[0]);
                bf[ni][1] = f2tf32(bp[4]);
            }
            #pragma unroll
            for (int mi = 0; mi < 4; mi++)
                #pragma unroll
                for (int ni = 0; ni < 4; ni++)
                    mma_tf32(acc[mi][ni], af[mi], bf[ni]);
        }
        __syncthreads();
        buf ^= 1;
    }

    #pragma unroll
    for (int mi = 0; mi < 4; mi++) {
        #pragma unroll
        for (int ni = 0; ni < 4; ni++) {
            int col = bn + wn + ni * 8 + t * 2;
            #pragma unroll
            for (int half = 0; half < 2; half++) {
                int row = bm + wm + mi * 16 + g + half * 8;
                float2 v;
                v.x = acc[mi][ni][half * 2 + 0] + bias[col + 0];
                v.y = acc[mi][ni][half * 2 + 1] + bias[col + 1];
                if (EPI == 1) {
                    v.x = 0.5f * v.x * (1.f + erff(v.x * 0.7071067811865476f));
                    v.y = 0.5f * v.y * (1.f + erff(v.y * 0.7071067811865476f));
                }
                if (res != nullptr) {
                    float2 r = *(const float2*)(res + (size_t)row * N + col);
                    v.x += r.x; v.y += r.y;
                }
                *(float2*)(C + (size_t)row * N + col) = v;
            }
        }
    }
}

// ---------------- K5: TF32 tensor-core flash causal attention ----------------
// q-tile 128, kv-tile 64, 8 warps x 16 q-rows. Pitch 72 (72%32==8) makes
// fragment LDS patterns (8g+t / 8t+g) bank-conflict-free. P tile is
// warp-private (each warp reads only its own 16 rows) -> no block barrier
// around the P smem round-trip. TF32 rounding applied once at smem fill.
#define ATP 72
#define ATT_SMEM ((128*ATP + 64*ATP + 64*ATP + 128*ATP) * 4)   // 110592 B

__global__ __launch_bounds__(256, 1)
void attn_tc_kernel(const float* __restrict__ qkv, float* __restrict__ o) {
    extern __shared__ float sm[];
    float* Qs = sm;                      // [128][ATP]
    float* Ks = sm + 128 * ATP;          // [64][ATP]
    float* Vs = sm + 192 * ATP;          // [64][ATP]
    float* Ps = sm + 256 * ATP;          // [128][ATP]

    int qt = blockIdx.x, h = blockIdx.y, b = blockIdx.z;
    int tid = threadIdx.x;
    int warp = tid >> 5, lane = tid & 31;
    int g = lane >> 2, t = lane & 3;
    int qr0 = qt * 128;
    const float* base = qkv + (size_t)b * S_ * (3 * D_);

    // load Q tile (scaled by 1/sqrt(64), tf32-rounded)
    for (int i = tid; i < 128 * 64; i += 256) {
        int r = i >> 6, c = i & 63;
        Qs[r * ATP + c] =
            f2tf32f(base[(size_t)(qr0 + r) * (3 * D_) + h * HD + c] * 0.125f);
    }

    int row0 = warp * 16 + g;           // within q tile
    int row1 = row0 + 8;

    float oacc[8][4];
    float m0 = -1e30f, m1 = -1e30f, l0 = 0.f, l1 = 0.f;
    #pragma unroll
    for (int ni = 0; ni < 8; ni++)
        #pragma unroll
        for (int r = 0; r < 4; r++) oacc[ni][r] = 0.f;

    int jt_max = 2 * qt + 1;
    for (int jt = 0; jt <= jt_max; jt++) {
        int jr0 = jt * 64;
        __syncthreads();                 // protect Ks/Vs from previous iter
        for (int i = tid; i < 64 * 64; i += 256) {
            int r = i >> 6, c = i & 63;
            Ks[r * ATP + c] =
                f2tf32f(base[(size_t)(jr0 + r) * (3 * D_) + D_ + h * HD + c]);
            Vs[r * ATP + c] =
                f2tf32f(base[(size_t)(jr0 + r) * (3 * D_) + 2 * D_ + h * HD + c]);
        }
        __syncthreads();

        // warp fully above this kv tile -> nothing visible, skip all math
        if (jr0 > qr0 + warp * 16 + 15) continue;

        // S = Q @ K^T   (sacc[ni] covers cols jr0+ni*8 .. +7)
        float sacc[8][4];
        #pragma unroll
        for (int ni = 0; ni < 8; ni++)
            #pragma unroll
            for (int r = 0; r < 4; r++) sacc[ni][r] = 0.f;

        #pragma unroll
        for (int kc = 0; kc < 8; kc++) {
            unsigned int aq[4];
            const float* qp0 = Qs + row0 * ATP + kc * 8 + t;
            const float* qp1 = Qs + row1 * ATP + kc * 8 + t;
            aq[0] = __float_as_uint(qp0[0]);
            aq[1] = __float_as_uint(qp1[0]);
            aq[2] = __float_as_uint(qp0[4]);
            aq[3] = __float_as_uint(qp1[4]);
            #pragma unroll
            for (int ni = 0; ni < 8; ni++) {
                unsigned int bk[2];
                const float* kp = Ks + (ni * 8 + g) * ATP + kc * 8 + t;
                bk[0] = __float_as_uint(kp[0]);
                bk[1] = __float_as_uint(kp[4]);
                mma_tf32(sacc[ni], aq, bk);
            }
        }

        // causal mask (only needed when the tile straddles the diagonal)
        if (jr0 + 63 > qr0 + warp * 16) {
            int gr0 = qr0 + row0, gr1 = qr0 + row1;
            #pragma unroll
            for (int ni = 0; ni < 8; ni++) {
                int c0 = jr0 + ni * 8 + 2 * t;
                if (c0 > gr0)     sacc[ni][0] = -1e30f;
                if (c0 + 1 > gr0) sacc[ni][1] = -1e30f;
                if (c0 > gr1)     sacc[ni][2] = -1e30f;
                if (c0 + 1 > gr1) sacc[ni][3] = -1e30f;
            }
        }

        // online softmax; row0 in (c0,c1), row1 in (c2,c3); reduce over t-lanes
        float mx0 = -1e30f, mx1 = -1e30f;
        #pragma unroll
        for (int ni = 0; ni < 8; ni++) {
            mx0 = fmaxf(mx0, fmaxf(sacc[ni][0], sacc[ni][1]));
            mx1 = fmaxf(mx1, fmaxf(sacc[ni][2], sacc[ni][3]));
        }
        #pragma unroll
        for (int off = 1; off < 4; off <<= 1) {
            mx0 = fmaxf(mx0, __shfl_xor_sync(0xffffffffu, mx0, off));
            mx1 = fmaxf(mx1, __shfl_xor_sync(0xffffffffu, mx1, off));
        }
        float nm0 = fmaxf(m0, mx0), nm1 = fmaxf(m1, mx1);
        float ps0 = 0.f, ps1 = 0.f;
        #pragma unroll
        for (int ni = 0; ni < 8; ni++) {
            sacc[ni][0] = __expf(sacc[ni][0] - nm0);
            sacc[ni][1] = __expf(sacc[ni][1] - nm0);
            sacc[ni][2] = __expf(sacc[ni][2] - nm1);
            sacc[ni][3] = __expf(sacc[ni][3] - nm1);
            ps0 += sacc[ni][0] + sacc[ni][1];
            ps1 += sacc[ni][2] + sacc[ni][3];
        }
        #pragma unroll
        for (int off = 1; off < 4; off <<= 1) {
            ps0 += __shfl_xor_sync(0xffffffffu, ps0, off);
            ps1 += __shfl_xor_sync(0xffffffffu, ps1, off);
        }
        float al0 = __expf(m0 - nm0), al1 = __expf(m1 - nm1);
        l0 = l0 * al0 + ps0;  m0 = nm0;
        l1 = l1 * al1 + ps1;  m1 = nm1;
        #pragma unroll
        for (int ni = 0; ni < 8; ni++) {
            oacc[ni][0] *= al0; oacc[ni][1] *= al0;
            oacc[ni][2] *= al1; oacc[ni][3] *= al1;
        }

        // P -> smem (tf32-rounded); warp-private rows, warp-synchronous reuse
        #pragma unroll
        for (int ni = 0; ni < 8; ni++) {
            Ps[row0 * ATP + ni * 8 + 2 * t]     = f2tf32f(sacc[ni][0]);
            Ps[row0 * ATP + ni * 8 + 2 * t + 1] = f2tf32f(sacc[ni][1]);
            Ps[row1 * ATP + ni * 8 + 2 * t]     = f2tf32f(sacc[ni][2]);
            Ps[row1 * ATP + ni * 8 + 2 * t + 1] = f2tf32f(sacc[ni][3]);
        }
        __syncwarp();

        // O += P @ V
        #pragma unroll
        for (int kc = 0; kc < 8; kc++) {
            unsigned int ap[4];
            const float* pp0 = Ps + row0 * ATP + kc * 8 + t;
            const float* pp1 = Ps + row1 * ATP + kc * 8 + t;
            ap[0] = __float_as_uint(pp0[0]);
            ap[1] = __float_as_uint(pp1[0]);
            ap[2] = __float_as_uint(pp0[4]);
            ap[3] = __float_as_uint(pp1[4]);
            #pragma unroll
            for (int ni = 0; ni < 8; ni++) {
                unsigned int bv[2];
                const float* vp = Vs + (kc * 8 + t) * ATP + ni * 8 + g;
                bv[0] = __float_as_uint(vp[0]);
                bv[1] = __float_as_uint(vp[4 * ATP]);
                mma_tf32(oacc[ni], ap, bv);
            }
        }
        __syncwarp();   // P reads done before next iteration overwrites
    }

    float inv0 = 1.f / l0, inv1 = 1.f / l1;
    size_t gr0 = (size_t)(b * S_ + qr0 + row0) * D_ + h * HD;
    size_t gr1 = (size_t)(b * S_ + qr0 + row1) * D_ + h * HD;
    #pragma unroll
    for (int ni = 0; ni < 8; ni++) {
        int c = ni * 8 + 2 * t;
        o[gr0 + c]     = oacc[ni][0] * inv0;
        o[gr0 + c + 1] = oacc[ni][1] * inv0;
        o[gr1 + c]     = oacc[ni][2] * inv1;
        o[gr1 + c + 1] = oacc[ni][3] * inv1;
    }
}

// ---------------- K10: final sum + mhc mix ----------------------------------
__global__ void final_kernel(const float* __restrict__ attnres,
                             const float* __restrict__ ffn,
                             const float* __restrict__ xd,
                             const float* __restrict__ W,
                             float* __restrict__ out) {
    __shared__ float row[D_];
    __shared__ float Ws[64];
    int r = blockIdx.x;
    int b = r >> 11;
    int tid = threadIdx.x;
    ((float4*)row)[tid] = ((const float4*)(xd + (size_t)r * D_))[tid];
    if (tid < 64) Ws[tid] = W[b * 64 + tid];
    __syncthreads();

    int c0 = tid * 4;
    int m = c0 >> 7;
    int dp = c0 & 127;
    float mh0 = 0.f, mh1 = 0.f, mh2 = 0.f, mh3 = 0.f;
    #pragma unroll
    for (int n = 0; n < 8; n++) {
        float w = Ws[m * 8 + n];
        const float* rp = row + n * 128 + dp;
        mh0 += w * rp[0]; mh1 += w * rp[1]; mh2 += w * rp[2]; mh3 += w * rp[3];
    }
    float4 a = ((const float4*)(attnres + (size_t)r * D_))[tid];
    float4 f = ((const float4*)(ffn + (size_t)r * D_))[tid];
    float4 ov;
    ov.x = a.x + f.x + mh0;
    ov.y = a.y + f.y + mh1;
    ov.z = a.z + f.z + mh2;
    ov.w = a.w + f.w + mh3;
    ((float4*)(out + (size_t)r * D_))[tid] = ov;
}

// ---------------- launch ----------------------------------------------------
extern "C" void kernel_launch(void* const* d_in, const int* in_sizes, int n_in,
                              void* d_out, int out_size) {
    const float* x        = (const float*)d_in[0];
    const float* decay    = (const float*)d_in[3];
    const float* gate_w   = (const float*)d_in[4];
    const float* gate_b   = (const float*)d_in[5];
    const float* phi      = (const float*)d_in[6];
    const float* ln1_w    = (const float*)d_in[7];
    const float* ln2_w    = (const float*)d_in[8];
    const float* w1       = (const float*)d_in[9];
    const float* b1       = (const float*)d_in[10];
    const float* w2       = (const float*)d_in[11];
    const float* b2       = (const float*)d_in[12];
    const float* in_proj_w= (const float*)d_in[13];
    const float* in_proj_b= (const float*)d_in[14];
    const float* out_w    = (const float*)d_in[15];
    const float* out_b    = (const float*)d_in[16];
    float* out = (float*)d_out;

    void *p_xdelta, *p_xstate, *p_W, *p_normed, *p_qkv, *p_o, *p_attnres,
         *p_normed2, *p_h, *p_ffn;
    cudaGetSymbolAddress(&p_xdelta, g_xdelta);
    cudaGetSymbolAddress(&p_xstate, g_xstate);
    cudaGetSymbolAddress(&p_W, g_W);
    cudaGetSymbolAddress(&p_normed, g_normed);
    cudaGetSymbolAddress(&p_qkv, g_qkv);
    cudaGetSymbolAddress(&p_o, g_o);
    cudaGetSymbolAddress(&p_attnres, g_attnres);
    cudaGetSymbolAddress(&p_normed2, g_normed2);
    cudaGetSymbolAddress(&p_h, g_h);
    cudaGetSymbolAddress(&p_ffn, g_ffn);

    float* xdelta  = (float*)p_xdelta;
    float* xstate  = (float*)p_xstate;
    float* Wm      = (float*)p_W;
    float* normed  = (float*)p_normed;
    float* qkv     = (float*)p_qkv;
    float* ob      = (float*)p_o;
    float* attnres = (float*)p_attnres;
    float* normed2 = (float*)p_normed2;
    float* hbuf    = (float*)p_h;
    float* ffn     = (float*)p_ffn;

    cudaFuncSetAttribute(gemm_tf32_kernel<0>,
                         cudaFuncAttributeMaxDynamicSharedMemorySize, GEMM_SMEM);
    cudaFuncSetAttribute(gemm_tf32_kernel<1>,
                         cudaFuncAttributeMaxDynamicSharedMemorySize, GEMM_SMEM);
    cudaFuncSetAttribute(attn_tc_kernel,
                         cudaFuncAttributeMaxDynamicSharedMemorySize, ATT_SMEM);

    // 1) delta scan
    delta_scan_kernel<<<256, 256>>>(x, decay, xdelta, xstate);
    // 2) gates + sinkhorn
    gate_sinkhorn_kernel<<<1, 256>>>(xstate, gate_w, gate_b, phi, Wm);
    // 3) rmsnorm1
    rmsnorm_kernel<<<NTOK, 256>>>(xdelta, ln1_w, normed);
    // 4) qkv projection
    gemm_tf32_kernel<0><<<dim3(3 * D_ / 128, NTOK / 128), 256, GEMM_SMEM>>>(
        normed, in_proj_w, in_proj_b, nullptr, qkv, NTOK, 3 * D_, D_);
    // 5) attention (tensor-core flash)
    attn_tc_kernel<<<dim3(S_ / 128, NH, B_), 256, ATT_SMEM>>>(qkv, ob);
    // 6) out projection + residual(x_delta)
    gemm_tf32_kernel<0><<<dim3(D_ / 128, NTOK / 128), 256, GEMM_SMEM>>>(
        ob, out_w, out_b, xdelta, attnres, NTOK, D_, D_);
    // 7) rmsnorm2
    rmsnorm_kernel<<<NTOK, 256>>>(attnres, ln2_w, normed2);
    // 8) FFN1 + gelu
    gemm_tf32_kernel<1><<<dim3(4 * D_ / 128, NTOK / 128), 256, GEMM_SMEM>>>(
        normed2, w1, b1, nullptr, hbuf, NTOK, 4 * D_, D_);
    // 9) FFN2
    gemm_tf32_kernel<0><<<dim3(D_ / 128, NTOK / 128), 256, GEMM_SMEM>>>(
        hbuf, w2, b2, nullptr, ffn, NTOK, D_, 4 * D_);
    // 10) final
    final_kernel<<<NTOK, 256>>>(attnres, ffn, xdelta, Wm, out);
}

// round 9
// speedup vs baseline: 2.7286x; 1.0018x over previous
#include <cuda_runtime.h>
#include <cuda_bf16.h>
#include <math.h>
#include <stdint.h>

// Problem constants
#define B_  2
#define S_  2048
#define D_  1024
#define NH  16
#define HD  64
#define NTOK (B_*S_)          // 4096

// ---------------- scratch (static __device__, no allocation) ----------------
__device__ float g_xdelta[NTOK * D_];
__device__ float g_xstate[B_ * D_];
__device__ float g_W[B_ * 8 * 8];
__device__ float g_normed[NTOK * D_];
__device__ float g_qkv[NTOK * 3 * D_];
__device__ float g_o[NTOK * D_];
__device__ float g_attnres[NTOK * D_];
__device__ float g_normed2[NTOK * D_];
__device__ float g_h[NTOK * 4 * D_];
__device__ float g_ffn[NTOK * D_];
// tf32-pre-rounded weight copies
__device__ float g_wqkv_r[3 * D_ * D_];      // 12.6 MB
__device__ float g_wout_r[D_ * D_];          // 4.2 MB
__device__ float g_w1_r[4 * D_ * D_];        // 16.8 MB
__device__ float g_w2_r[4 * D_ * D_];        // 16.8 MB

// ---------------- TF32 helpers ----------------------------------------------
__device__ __forceinline__ float f2tf32f(float v) {
    unsigned int r;
    asm("cvt.rna.tf32.f32 %0, %1;" : "=r"(r) : "f"(v));
    return __uint_as_float(r);
}
__device__ __forceinline__ void mma_tf32(float* c, const unsigned int* a,
                                         const unsigned int* b) {
    asm volatile(
        "mma.sync.aligned.m16n8k8.row.col.f32.tf32.tf32.f32 "
        "{%0,%1,%2,%3}, {%4,%5,%6,%7}, {%8,%9}, {%0,%1,%2,%3};"
        : "+f"(c[0]), "+f"(c[1]), "+f"(c[2]), "+f"(c[3])
        : "r"(a[0]), "r"(a[1]), "r"(a[2]), "r"(a[3]), "r"(b[0]), "r"(b[1]));
}
__device__ __forceinline__ void cp_async16(void* smem, const void* gmem) {
    unsigned int s = (unsigned int)__cvta_generic_to_shared(smem);
    asm volatile("cp.async.cg.shared.global [%0], [%1], 16;\n" :: "r"(s), "l"(gmem));
}

// ---------------- K0: pre-round weights to tf32 ------------------------------
__global__ void round_tf32_kernel(const float4* __restrict__ src,
                                  float4* __restrict__ dst, int n4) {
    int i = blockIdx.x * blockDim.x + threadIdx.x;
    int stride = gridDim.x * blockDim.x;
    for (; i < n4; i += stride) {
        float4 v = src[i];
        v.x = f2tf32f(v.x); v.y = f2tf32f(v.y);
        v.z = f2tf32f(v.z); v.w = f2tf32f(v.w);
        dst[i] = v;
    }
}

// ---------------- K1: delta EMA scan (warp-parallel affine scan) -------------
__global__ void delta_scan_kernel(const float* __restrict__ x,
                                  const float* __restrict__ decay,
                                  float* __restrict__ xd,
                                  float* __restrict__ xstate) {
    int warp = (blockIdx.x * blockDim.x + threadIdx.x) >> 5;
    int lane = threadIdx.x & 31;
    if (warp >= B_ * D_) return;
    int b = warp >> 10;
    int d = warp & (D_ - 1);
    float beta = 1.f / (1.f + __expf(-decay[d]));
    float onem = 1.f - beta;

    const float* xp = x  + (size_t)b * S_ * D_ + d;
    float*       op = xd + (size_t)b * S_ * D_ + d;

    float carry = 0.f;
    float sum = 0.f;
    for (int t0 = 0; t0 < S_; t0 += 32) {
        float xt = xp[(size_t)(t0 + lane) * D_];
        float a = beta, bb = onem * xt;
        #pragma unroll
        for (int off = 1; off < 32; off <<= 1) {
            float pa = __shfl_up_sync(0xffffffffu, a, off);
            float pb = __shfl_up_sync(0xffffffffu, bb, off);
            if (lane >= off) { bb = a * pb + bb; a = a * pa; }
        }
        float s_incl = a * carry + bb;
        float s_prev = __shfl_up_sync(0xffffffffu, s_incl, 1);
        if (lane == 0) s_prev = carry;
        float out = xt - s_prev;
        op[(size_t)(t0 + lane) * D_] = out;
        sum += out;
        carry = __shfl_sync(0xffffffffu, s_incl, 31);
    }
    #pragma unroll
    for (int off = 16; off >= 1; off >>= 1)
        sum += __shfl_xor_sync(0xffffffffu, sum, off);
    if (lane == 0) xstate[warp] = sum * (1.f / (float)S_);
}

// ---------------- K2: gates + sinkhorn + W --------------------------------
__global__ void gate_sinkhorn_kernel(const float* __restrict__ xstate,
                                     const float* __restrict__ gate_w,
                                     const float* __restrict__ gate_b,
                                     const float* __restrict__ phi,
                                     float* __restrict__ W) {
    __shared__ float gbuf[B_][8];
    __shared__ float Km[64];
    __shared__ float tmp[64];
    int tid = threadIdx.x;
    int wid = tid >> 5, lane = tid & 31;

    for (int idx = wid; idx < 16; idx += 8) {
        int b = idx >> 3;
        int j = 16 + (idx & 7);
        float s = 0.f;
        for (int k = lane; k < D_; k += 32)
            s += xstate[b * D_ + k] * gate_w[j * D_ + k];
        #pragma unroll
        for (int off = 16; off >= 1; off >>= 1)
            s += __shfl_xor_sync(0xffffffffu, s, off);
        if (lane == 0)
            gbuf[b][idx & 7] = 1.f / (1.f + __expf(-(s + gate_b[j])));
    }
    if (tid < 64) Km[tid] = __expf(phi[tid]);
    __syncthreads();

    for (int it = 0; it < 15; it++) {
        if (tid < 64) {
            int m = tid >> 3;
            float rs = 0.f;
            #pragma unroll
            for (int n = 0; n < 8; n++) rs += Km[m * 8 + n];
            tmp[tid] = Km[tid] / rs;
        }
        __syncthreads();
        if (tid < 64) {
            int n = tid & 7;
            float cs = 0.f;
            #pragma unroll
            for (int m = 0; m < 8; m++) cs += tmp[m * 8 + n];
            Km[tid] = tmp[tid] / cs;
        }
        __syncthreads();
    }
    if (tid < 128) {
        int b = tid >> 6, r = tid & 63, n = r & 7;
        W[b * 64 + r] = Km[r] * gbuf[b][n];
    }
}

// ---------------- K3: RMSNorm (block per row, tf32-rounded output) -----------
__global__ void rmsnorm_kernel(const float* __restrict__ x,
                               const float* __restrict__ w,
                               float* __restrict__ y) {
    int row = blockIdx.x;
    int tid = threadIdx.x;
    const float4* xr = (const float4*)(x + (size_t)row * D_);
    float4 v = xr[tid];
    float ss = v.x * v.x + v.y * v.y + v.z * v.z + v.w * v.w;
    __shared__ float red[8];
    #pragma unroll
    for (int off = 16; off >= 1; off >>= 1)
        ss += __shfl_xor_sync(0xffffffffu, ss, off);
    if ((tid & 31) == 0) red[tid >> 5] = ss;
    __syncthreads();
    if (tid < 8) {
        float t = red[tid];
        #pragma unroll
        for (int off = 4; off >= 1; off >>= 1)
            t += __shfl_xor_sync(0xffu, t, off);
        if (tid == 0) red[0] = t;
    }
    __syncthreads();
    float scale = rsqrtf(red[0] * (1.f / (float)D_) + 1e-6f);
    float4 wv = ((const float4*)w)[tid];
    float4 o;
    o.x = f2tf32f(v.x * scale * wv.x);
    o.y = f2tf32f(v.y * scale * wv.y);
    o.z = f2tf32f(v.z * scale * wv.z);
    o.w = f2tf32f(v.w * scale * wv.w);
    ((float4*)(y + (size_t)row * D_))[tid] = o;
}

// ---------------- TF32 SGEMM NT: C = A[M,K]*B[N,K]^T + bias (+res)(+gelu) ----
// Operands are pre-rounded to tf32 in gmem; inner loop uses raw bits (no CVT).
// EPI: 0 = bias (+ optional residual), 1 = bias + exact GELU, output tf32-rounded
#define GPITCH 36
#define GEMM_SMEM (2 * 2 * 128 * GPITCH * 4)   // 73728 bytes

template <int EPI>
__global__ __launch_bounds__(256, 2)
void gemm_tf32_kernel(const float* __restrict__ A, const float* __restrict__ Bm,
                      const float* __restrict__ bias, const float* __restrict__ res,
                      float* __restrict__ C, int M, int N, int K) {
    extern __shared__ float sm[];
    float* As = sm;                     // [2][128][GPITCH]
    float* Bs = sm + 2 * 128 * GPITCH;

    int bm = blockIdx.y * 128;
    int bn = blockIdx.x * 128;
    int tid = threadIdx.x;
    int warp = tid >> 5, lane = tid & 31;
    int wm = (warp & 1) * 64;
    int wn = (warp >> 1) * 32;
    int g = lane >> 2, t = lane & 3;

    float acc[4][4][4];
    #pragma unroll
    for (int mi = 0; mi < 4; mi++)
        #pragma unroll
        for (int ni = 0; ni < 4; ni++)
            #pragma unroll
            for (int r = 0; r < 4; r++) acc[mi][ni][r] = 0.f;

    int KT = K >> 5;

    #pragma unroll
    for (int i = 0; i < 4; i++) {
        int c = i * 256 + tid;
        int row = c >> 3, cc = c & 7;
        cp_async16(&As[row * GPITCH + cc * 4], A + (size_t)(bm + row) * K + cc * 4);
        cp_async16(&Bs[row * GPITCH + cc * 4], Bm + (size_t)(bn + row) * K + cc * 4);
    }
    asm volatile("cp.async.commit_group;\n");

    int buf = 0;
    for (int kt = 0; kt < KT; kt++) {
        if (kt + 1 < KT) {
            int k0 = (kt + 1) << 5;
            int boff = (buf ^ 1) * 128 * GPITCH;
            #pragma unroll
            for (int i = 0; i < 4; i++) {
                int c = i * 256 + tid;
                int row = c >> 3, cc = c & 7;
                cp_async16(&As[boff + row * GPITCH + cc * 4],
                           A + (size_t)(bm + row) * K + k0 + cc * 4);
                cp_async16(&Bs[boff + row * GPITCH + cc * 4],
                           Bm + (size_t)(bn + row) * K + k0 + cc * 4);
            }
            asm volatile("cp.async.commit_group;\n");
            asm volatile("cp.async.wait_group 1;\n");
        } else {
            asm volatile("cp.async.wait_group 0;\n");
        }
        __syncthreads();

        const float* Ab = As + buf * 128 * GPITCH;
        const float* Bb = Bs + buf * 128 * GPITCH;
        #pragma unroll
        for (int kk = 0; kk < 32; kk += 8) {
            unsigned int af[4][4], bf[4][2];
            #pragma unroll
            for (int mi = 0; mi < 4; mi++) {
                const float* ap = Ab + (wm + mi * 16 + g) * GPITCH + kk + t;
                af[mi][0] = __float_as_uint(ap[0]);
                af[mi][1] = __float_as_uint(ap[8 * GPITCH]);
                af[mi][2] = __float_as_uint(ap[4]);
                af[mi][3] = __float_as_uint(ap[8 * GPITCH + 4]);
            }
            #pragma unroll
            for (int ni = 0; ni < 4; ni++) {
                const float* bp = Bb + (wn + ni * 8 + g) * GPITCH + kk + t;
                bf[ni][0] = __float_as_uint(bp[0]);
                bf[ni][1] = __float_as_uint(bp[4]);
            }
            #pragma unroll
            for (int mi = 0; mi < 4; mi++)
                #pragma unroll
                for (int ni = 0; ni < 4; ni++)
                    mma_tf32(acc[mi][ni], af[mi], bf[ni]);
        }
        __syncthreads();
        buf ^= 1;
    }

    #pragma unroll
    for (int mi = 0; mi < 4; mi++) {
        #pragma unroll
        for (int ni = 0; ni < 4; ni++) {
            int col = bn + wn + ni * 8 + t * 2;
            #pragma unroll
            for (int half = 0; half < 2; half++) {
                int row = bm + wm + mi * 16 + g + half * 8;
                float2 v;
                v.x = acc[mi][ni][half * 2 + 0] + bias[col + 0];
                v.y = acc[mi][ni][half * 2 + 1] + bias[col + 1];
                if (EPI == 1) {
                    v.x = f2tf32f(0.5f * v.x * (1.f + erff(v.x * 0.7071067811865476f)));
                    v.y = f2tf32f(0.5f * v.y * (1.f + erff(v.y * 0.7071067811865476f)));
                }
                if (res != nullptr) {
                    float2 r = *(const float2*)(res + (size_t)row * N + col);
                    v.x += r.x; v.y += r.y;
                }
                *(float2*)(C + (size_t)row * N + col) = v;
            }
        }
    }
}

// ---------------- K5: TF32 tensor-core flash causal attention ----------------
#define ATP 72
#define ATT_SMEM ((128*ATP + 64*ATP + 64*ATP + 128*ATP) * 4)   // 110592 B

__global__ __launch_bounds__(256, 1)
void attn_tc_kernel(const float* __restrict__ qkv, float* __restrict__ o) {
    extern __shared__ float sm[];
    float* Qs = sm;                      // [128][ATP]
    float* Ks = sm + 128 * ATP;          // [64][ATP]
    float* Vs = sm + 192 * ATP;          // [64][ATP]
    float* Ps = sm + 256 * ATP;          // [128][ATP]

    int qt = blockIdx.x, h = blockIdx.y, b = blockIdx.z;
    int tid = threadIdx.x;
    int warp = tid >> 5, lane = tid & 31;
    int g = lane >> 2, t = lane & 3;
    int qr0 = qt * 128;
    const float* base = qkv + (size_t)b * S_ * (3 * D_);

    for (int i = tid; i < 128 * 64; i += 256) {
        int r = i >> 6, c = i & 63;
        Qs[r * ATP + c] =
            f2tf32f(base[(size_t)(qr0 + r) * (3 * D_) + h * HD + c] * 0.125f);
    }

    int row0 = warp * 16 + g;
    int row1 = row0 + 8;

    float oacc[8][4];
    float m0 = -1e30f, m1 = -1e30f, l0 = 0.f, l1 = 0.f;
    #pragma unroll
    for (int ni = 0; ni < 8; ni++)
        #pragma unroll
        for (int r = 0; r < 4; r++) oacc[ni][r] = 0.f;

    int jt_max = 2 * qt + 1;
    for (int jt = 0; jt <= jt_max; jt++) {
        int jr0 = jt * 64;
        __syncthreads();
        for (int i = tid; i < 64 * 64; i += 256) {
            int r = i >> 6, c = i & 63;
            Ks[r * ATP + c] =
                f2tf32f(base[(size_t)(jr0 + r) * (3 * D_) + D_ + h * HD + c]);
            Vs[r * ATP + c] =
                f2tf32f(base[(size_t)(jr0 + r) * (3 * D_) + 2 * D_ + h * HD + c]);
        }
        __syncthreads();

        if (jr0 > qr0 + warp * 16 + 15) continue;

        float sacc[8][4];
        #pragma unroll
        for (int ni = 0; ni < 8; ni++)
            #pragma unroll
            for (int r = 0; r < 4; r++) sacc[ni][r] = 0.f;

        #pragma unroll
        for (int kc = 0; kc < 8; kc++) {
            unsigned int aq[4];
            const float* qp0 = Qs + row0 * ATP + kc * 8 + t;
            const float* qp1 = Qs + row1 * ATP + kc * 8 + t;
            aq[0] = __float_as_uint(qp0[0]);
            aq[1] = __float_as_uint(qp1[0]);
            aq[2] = __float_as_uint(qp0[4]);
            aq[3] = __float_as_uint(qp1[4]);
            #pragma unroll
            for (int ni = 0; ni < 8; ni++) {
                unsigned int bk[2];
                const float* kp = Ks + (ni * 8 + g) * ATP + kc * 8 + t;
                bk[0] = __float_as_uint(kp[0]);
                bk[1] = __float_as_uint(kp[4]);
                mma_tf32(sacc[ni], aq, bk);
            }
        }

        if (jr0 + 63 > qr0 + warp * 16) {
            int gr0 = qr0 + row0, gr1 = qr0 + row1;
            #pragma unroll
            for (int ni = 0; ni < 8; ni++) {
                int c0 = jr0 + ni * 8 + 2 * t;
                if (c0 > gr0)     sacc[ni][0] = -1e30f;
                if (c0 + 1 > gr0) sacc[ni][1] = -1e30f;
                if (c0 > gr1)     sacc[ni][2] = -1e30f;
                if (c0 + 1 > gr1) sacc[ni][3] = -1e30f;
            }
        }

        float mx0 = -1e30f, mx1 = -1e30f;
        #pragma unroll
        for (int ni = 0; ni < 8; ni++) {
            mx0 = fmaxf(mx0, fmaxf(sacc[ni][0], sacc[ni][1]));
            mx1 = fmaxf(mx1, fmaxf(sacc[ni][2], sacc[ni][3]));
        }
        #pragma unroll
        for (int off = 1; off < 4; off <<= 1) {
            mx0 = fmaxf(mx0, __shfl_xor_sync(0xffffffffu, mx0, off));
            mx1 = fmaxf(mx1, __shfl_xor_sync(0xffffffffu, mx1, off));
        }
        float nm0 = fmaxf(m0, mx0), nm1 = fmaxf(m1, mx1);
        float ps0 = 0.f, ps1 = 0.f;
        #pragma unroll
        for (int ni = 0; ni < 8; ni++) {
            sacc[ni][0] = __expf(sacc[ni][0] - nm0);
            sacc[ni][1] = __expf(sacc[ni][1] - nm0);
            sacc[ni][2] = __expf(sacc[ni][2] - nm1);
            sacc[ni][3] = __expf(sacc[ni][3] - nm1);
            ps0 += sacc[ni][0] + sacc[ni][1];
            ps1 += sacc[ni][2] + sacc[ni][3];
        }
        #pragma unroll
        for (int off = 1; off < 4; off <<= 1) {
            ps0 += __shfl_xor_sync(0xffffffffu, ps0, off);
            ps1 += __shfl_xor_sync(0xffffffffu, ps1, off);
        }
        float al0 = __expf(m0 - nm0), al1 = __expf(m1 - nm1);
        l0 = l0 * al0 + ps0;  m0 = nm0;
        l1 = l1 * al1 + ps1;  m1 = nm1;
        #pragma unroll
        for (int ni = 0; ni < 8; ni++) {
            oacc[ni][0] *= al0; oacc[ni][1] *= al0;
            oacc[ni][2] *= al1; oacc[ni][3] *= al1;
        }

        #pragma unroll
        for (int ni = 0; ni < 8; ni++) {
            Ps[row0 * ATP + ni * 8 + 2 * t]     = f2tf32f(sacc[ni][0]);
            Ps[row0 * ATP + ni * 8 + 2 * t + 1] = f2tf32f(sacc[ni][1]);
            Ps[row1 * ATP + ni * 8 + 2 * t]     = f2tf32f(sacc[ni][2]);
            Ps[row1 * ATP + ni * 8 + 2 * t + 1] = f2tf32f(sacc[ni][3]);
        }
        __syncwarp();

        #pragma unroll
        for (int kc = 0; kc < 8; kc++) {
            unsigned int ap[4];
            const float* pp0 = Ps + row0 * ATP + kc * 8 + t;
            const float* pp1 = Ps + row1 * ATP + kc * 8 + t;
            ap[0] = __float_as_uint(pp0[0]);
            ap[1] = __float_as_uint(pp1[0]);
            ap[2] = __float_as_uint(pp0[4]);
            ap[3] = __float_as_uint(pp1[4]);
            #pragma unroll
            for (int ni = 0; ni < 8; ni++) {
                unsigned int bv[2];
                const float* vp = Vs + (kc * 8 + t) * ATP + ni * 8 + g;
                bv[0] = __float_as_uint(vp[0]);
                bv[1] = __float_as_uint(vp[4 * ATP]);
                mma_tf32(oacc[ni], ap, bv);
            }
        }
        __syncwarp();
    }

    // O feeds the out-proj GEMM as A -> round to tf32 here
    float inv0 = 1.f / l0, inv1 = 1.f / l1;
    size_t gr0 = (size_t)(b * S_ + qr0 + row0) * D_ + h * HD;
    size_t gr1 = (size_t)(b * S_ + qr0 + row1) * D_ + h * HD;
    #pragma unroll
    for (int ni = 0; ni < 8; ni++) {
        int c = ni * 8 + 2 * t;
        o[gr0 + c]     = f2tf32f(oacc[ni][0] * inv0);
        o[gr0 + c + 1] = f2tf32f(oacc[ni][1] * inv0);
        o[gr1 + c]     = f2tf32f(oacc[ni][2] * inv1);
        o[gr1 + c + 1] = f2tf32f(oacc[ni][3] * inv1);
    }
}

// ---------------- K10: final sum + mhc mix ----------------------------------
__global__ void final_kernel(const float* __restrict__ attnres,
                             const float* __restrict__ ffn,
                             const float* __restrict__ xd,
                             const float* __restrict__ W,
                             float* __restrict__ out) {
    __shared__ float row[D_];
    __shared__ float Ws[64];
    int r = blockIdx.x;
    int b = r >> 11;
    int tid = threadIdx.x;
    ((float4*)row)[tid] = ((const float4*)(xd + (size_t)r * D_))[tid];
    if (tid < 64) Ws[tid] = W[b * 64 + tid];
    __syncthreads();

    int c0 = tid * 4;
    int m = c0 >> 7;
    int dp = c0 & 127;
    float mh0 = 0.f, mh1 = 0.f, mh2 = 0.f, mh3 = 0.f;
    #pragma unroll
    for (int n = 0; n < 8; n++) {
        float w = Ws[m * 8 + n];
        const float* rp = row + n * 128 + dp;
        mh0 += w * rp[0]; mh1 += w * rp[1]; mh2 += w * rp[2]; mh3 += w * rp[3];
    }
    float4 a = ((const float4*)(attnres + (size_t)r * D_))[tid];
    float4 f = ((const float4*)(ffn + (size_t)r * D_))[tid];
    float4 ov;
    ov.x = a.x + f.x + mh0;
    ov.y = a.y + f.y + mh1;
    ov.z = a.z + f.z + mh2;
    ov.w = a.w + f.w + mh3;
    ((float4*)(out + (size_t)r * D_))[tid] = ov;
}

// ---------------- launch ----------------------------------------------------
extern "C" void kernel_launch(void* const* d_in, const int* in_sizes, int n_in,
                              void* d_out, int out_size) {
    const float* x        = (const float*)d_in[0];
    const float* decay    = (const float*)d_in[3];
    const float* gate_w   = (const float*)d_in[4];
    const float* gate_b   = (const float*)d_in[5];
    const float* phi      = (const float*)d_in[6];
    const float* ln1_w    = (const float*)d_in[7];
    const float* ln2_w    = (const float*)d_in[8];
    const float* w1       = (const float*)d_in[9];
    const float* b1       = (const float*)d_in[10];
    const float* w2       = (const float*)d_in[11];
    const float* b2       = (const float*)d_in[12];
    const float* in_proj_w= (const float*)d_in[13];
    const float* in_proj_b= (const float*)d_in[14];
    const float* out_w    = (const float*)d_in[15];
    const float* out_b    = (const float*)d_in[16];
    float* out = (float*)d_out;

    void *p_xdelta, *p_xstate, *p_W, *p_normed, *p_qkv, *p_o, *p_attnres,
         *p_normed2, *p_h, *p_ffn, *p_wqkv, *p_wout, *p_w1, *p_w2;
    cudaGetSymbolAddress(&p_xdelta, g_xdelta);
    cudaGetSymbolAddress(&p_xstate, g_xstate);
    cudaGetSymbolAddress(&p_W, g_W);
    cudaGetSymbolAddress(&p_normed, g_normed);
    cudaGetSymbolAddress(&p_qkv, g_qkv);
    cudaGetSymbolAddress(&p_o, g_o);
    cudaGetSymbolAddress(&p_attnres, g_attnres);
    cudaGetSymbolAddress(&p_normed2, g_normed2);
    cudaGetSymbolAddress(&p_h, g_h);
    cudaGetSymbolAddress(&p_ffn, g_ffn);
    cudaGetSymbolAddress(&p_wqkv, g_wqkv_r);
    cudaGetSymbolAddress(&p_wout, g_wout_r);
    cudaGetSymbolAddress(&p_w1, g_w1_r);
    cudaGetSymbolAddress(&p_w2, g_w2_r);

    float* xdelta  = (float*)p_xdelta;
    float* xstate  = (float*)p_xstate;
    float* Wm      = (float*)p_W;
    float* normed  = (float*)p_normed;
    float* qkv     = (float*)p_qkv;
    float* ob      = (float*)p_o;
    float* attnres = (float*)p_attnres;
    float* normed2 = (float*)p_normed2;
    float* hbuf    = (float*)p_h;
    float* ffn     = (float*)p_ffn;
    float* wqkv_r  = (float*)p_wqkv;
    float* wout_r  = (float*)p_wout;
    float* w1_r    = (float*)p_w1;
    float* w2_r    = (float*)p_w2;

    cudaFuncSetAttribute(gemm_tf32_kernel<0>,
                         cudaFuncAttributeMaxDynamicSharedMemorySize, GEMM_SMEM);
    cudaFuncSetAttribute(gemm_tf32_kernel<1>,
                         cudaFuncAttributeMaxDynamicSharedMemorySize, GEMM_SMEM);
    cudaFuncSetAttribute(attn_tc_kernel,
                         cudaFuncAttributeMaxDynamicSharedMemorySize, ATT_SMEM);

    // 0) pre-round weights to tf32 (mem-bound, ~20us total)
    round_tf32_kernel<<<1024, 256>>>((const float4*)in_proj_w, (float4*)wqkv_r,
                                     3 * D_ * D_ / 4);
    round_tf32_kernel<<<1024, 256>>>((const float4*)out_w, (float4*)wout_r,
                                     D_ * D_ / 4);
    round_tf32_kernel<<<1024, 256>>>((const float4*)w1, (float4*)w1_r,
                                     4 * D_ * D_ / 4);
    round_tf32_kernel<<<1024, 256>>>((const float4*)w2, (float4*)w2_r,
                                     4 * D_ * D_ / 4);

    // 1) delta scan
    delta_scan_kernel<<<256, 256>>>(x, decay, xdelta, xstate);
    // 2) gates + sinkhorn
    gate_sinkhorn_kernel<<<1, 256>>>(xstate, gate_w, gate_b, phi, Wm);
    // 3) rmsnorm1 (tf32-rounded output)
    rmsnorm_kernel<<<NTOK, 256>>>(xdelta, ln1_w, normed);
    // 4) qkv projection
    gemm_tf32_kernel<0><<<dim3(3 * D_ / 128, NTOK / 128), 256, GEMM_SMEM>>>(
        normed, wqkv_r, in_proj_b, nullptr, qkv, NTOK, 3 * D_, D_);
    // 5) attention (tensor-core flash)
    attn_tc_kernel<<<dim3(S_ / 128, NH, B_), 256, ATT_SMEM>>>(qkv, ob);
    // 6) out projection + residual(x_delta)
    gemm_tf32_kernel<0><<<dim3(D_ / 128, NTOK / 128), 256, GEMM_SMEM>>>(
        ob, wout_r, out_b, xdelta, attnres, NTOK, D_, D_);
    // 7) rmsnorm2 (tf32-rounded output)
    rmsnorm_kernel<<<NTOK, 256>>>(attnres, ln2_w, normed2);
    // 8) FFN1 + gelu (tf32-rounded output)
    gemm_tf32_kernel<1><<<dim3(4 * D_ / 128, NTOK / 128), 256, GEMM_SMEM>>>(
        normed2, w1_r, b1, nullptr, hbuf, NTOK, 4 * D_, D_);
    // 9) FFN2
    gemm_tf32_kernel<0><<<dim3(D_ / 128, NTOK / 128), 256, GEMM_SMEM>>>(
        hbuf, w2_r, b2, nullptr, ffn, NTOK, D_, 4 * D_);
    // 10) final
    final_kernel<<<NTOK, 256>>>(attnres, ffn, xdelta, Wm, out);
}

// round 11
// speedup vs baseline: 2.7542x; 1.0094x over previous
#include <cuda_runtime.h>
#include <cuda_bf16.h>
#include <math.h>
#include <stdint.h>

// Problem constants
#define B_  2
#define S_  2048
#define D_  1024
#define NH  16
#define HD  64
#define NTOK (B_*S_)          // 4096

// ---------------- scratch (static __device__, no allocation) ----------------
__device__ float g_xdelta[NTOK * D_];
__device__ float g_xstate[B_ * D_];
__device__ float g_W[B_ * 8 * 8];
__device__ float g_normed[NTOK * D_];
__device__ float g_qkv[NTOK * 3 * D_];
__device__ float g_o[NTOK * D_];
__device__ float g_attnres[NTOK * D_];
__device__ float g_normed2[NTOK * D_];
__device__ float g_h[NTOK * 4 * D_];
__device__ float g_ffn[NTOK * D_];
// tf32-pre-rounded weight copies
__device__ float g_wqkv_r[3 * D_ * D_];
__device__ float g_wout_r[D_ * D_];
__device__ float g_w1_r[4 * D_ * D_];
__device__ float g_w2_r[4 * D_ * D_];

// ---------------- TF32 helpers ----------------------------------------------
__device__ __forceinline__ float f2tf32f(float v) {
    unsigned int r;
    asm("cvt.rna.tf32.f32 %0, %1;" : "=r"(r) : "f"(v));
    return __uint_as_float(r);
}
__device__ __forceinline__ void mma_tf32(float* c, const unsigned int* a,
                                         const unsigned int* b) {
    asm volatile(
        "mma.sync.aligned.m16n8k8.row.col.f32.tf32.tf32.f32 "
        "{%0,%1,%2,%3}, {%4,%5,%6,%7}, {%8,%9}, {%0,%1,%2,%3};"
        : "+f"(c[0]), "+f"(c[1]), "+f"(c[2]), "+f"(c[3])
        : "r"(a[0]), "r"(a[1]), "r"(a[2]), "r"(a[3]), "r"(b[0]), "r"(b[1]));
}
__device__ __forceinline__ void cp_async16(void* smem, const void* gmem) {
    unsigned int s = (unsigned int)__cvta_generic_to_shared(smem);
    asm volatile("cp.async.cg.shared.global [%0], [%1], 16;\n" :: "r"(s), "l"(gmem));
}

// ---------------- K0: pre-round weights to tf32 ------------------------------
__global__ void round_tf32_kernel(const float4* __restrict__ src,
                                  float4* __restrict__ dst, int n4) {
    int i = blockIdx.x * blockDim.x + threadIdx.x;
    int stride = gridDim.x * blockDim.x;
    for (; i < n4; i += stride) {
        float4 v = src[i];
        v.x = f2tf32f(v.x); v.y = f2tf32f(v.y);
        v.z = f2tf32f(v.z); v.w = f2tf32f(v.w);
        dst[i] = v;
    }
}

// ---------------- K1: delta EMA scan (warp-parallel affine scan) -------------
__global__ void delta_scan_kernel(const float* __restrict__ x,
                                  const float* __restrict__ decay,
                                  float* __restrict__ xd,
                                  float* __restrict__ xstate) {
    int warp = (blockIdx.x * blockDim.x + threadIdx.x) >> 5;
    int lane = threadIdx.x & 31;
    if (warp >= B_ * D_) return;
    int b = warp >> 10;
    int d = warp & (D_ - 1);
    float beta = 1.f / (1.f + __expf(-decay[d]));
    float onem = 1.f - beta;

    const float* xp = x  + (size_t)b * S_ * D_ + d;
    float*       op = xd + (size_t)b * S_ * D_ + d;

    float carry = 0.f;
    float sum = 0.f;
    for (int t0 = 0; t0 < S_; t0 += 32) {
        float xt = xp[(size_t)(t0 + lane) * D_];
        float a = beta, bb = onem * xt;
        #pragma unroll
        for (int off = 1; off < 32; off <<= 1) {
            float pa = __shfl_up_sync(0xffffffffu, a, off);
            float pb = __shfl_up_sync(0xffffffffu, bb, off);
            if (lane >= off) { bb = a * pb + bb; a = a * pa; }
        }
        float s_incl = a * carry + bb;
        float s_prev = __shfl_up_sync(0xffffffffu, s_incl, 1);
        if (lane == 0) s_prev = carry;
        float out = xt - s_prev;
        op[(size_t)(t0 + lane) * D_] = out;
        sum += out;
        carry = __shfl_sync(0xffffffffu, s_incl, 31);
    }
    #pragma unroll
    for (int off = 16; off >= 1; off >>= 1)
        sum += __shfl_xor_sync(0xffffffffu, sum, off);
    if (lane == 0) xstate[warp] = sum * (1.f / (float)S_);
}

// ---------------- K2: gates + sinkhorn + W --------------------------------
__global__ void gate_sinkhorn_kernel(const float* __restrict__ xstate,
                                     const float* __restrict__ gate_w,
                                     const float* __restrict__ gate_b,
                                     const float* __restrict__ phi,
                                     float* __restrict__ W) {
    __shared__ float gbuf[B_][8];
    __shared__ float Km[64];
    __shared__ float tmp[64];
    int tid = threadIdx.x;
    int wid = tid >> 5, lane = tid & 31;

    for (int idx = wid; idx < 16; idx += 8) {
        int b = idx >> 3;
        int j = 16 + (idx & 7);
        float s = 0.f;
        for (int k = lane; k < D_; k += 32)
            s += xstate[b * D_ + k] * gate_w[j * D_ + k];
        #pragma unroll
        for (int off = 16; off >= 1; off >>= 1)
            s += __shfl_xor_sync(0xffffffffu, s, off);
        if (lane == 0)
            gbuf[b][idx & 7] = 1.f / (1.f + __expf(-(s + gate_b[j])));
    }
    if (tid < 64) Km[tid] = __expf(phi[tid]);
    __syncthreads();

    for (int it = 0; it < 15; it++) {
        if (tid < 64) {
            int m = tid >> 3;
            float rs = 0.f;
            #pragma unroll
            for (int n = 0; n < 8; n++) rs += Km[m * 8 + n];
            tmp[tid] = Km[tid] / rs;
        }
        __syncthreads();
        if (tid < 64) {
            int n = tid & 7;
            float cs = 0.f;
            #pragma unroll
            for (int m = 0; m < 8; m++) cs += tmp[m * 8 + n];
            Km[tid] = tmp[tid] / cs;
        }
        __syncthreads();
    }
    if (tid < 128) {
        int b = tid >> 6, r = tid & 63, n = r & 7;
        W[b * 64 + r] = Km[r] * gbuf[b][n];
    }
}

// ---------------- K3: RMSNorm (block per row, tf32-rounded output) -----------
__global__ void rmsnorm_kernel(const float* __restrict__ x,
                               const float* __restrict__ w,
                               float* __restrict__ y) {
    int row = blockIdx.x;
    int tid = threadIdx.x;
    const float4* xr = (const float4*)(x + (size_t)row * D_);
    float4 v = xr[tid];
    float ss = v.x * v.x + v.y * v.y + v.z * v.z + v.w * v.w;
    __shared__ float red[8];
    #pragma unroll
    for (int off = 16; off >= 1; off >>= 1)
        ss += __shfl_xor_sync(0xffffffffu, ss, off);
    if ((tid & 31) == 0) red[tid >> 5] = ss;
    __syncthreads();
    if (tid < 8) {
        float t = red[tid];
        #pragma unroll
        for (int off = 4; off >= 1; off >>= 1)
            t += __shfl_xor_sync(0xffu, t, off);
        if (tid == 0) red[0] = t;
    }
    __syncthreads();
    float scale = rsqrtf(red[0] * (1.f / (float)D_) + 1e-6f);
    float4 wv = ((const float4*)w)[tid];
    float4 o;
    o.x = f2tf32f(v.x * scale * wv.x);
    o.y = f2tf32f(v.y * scale * wv.y);
    o.z = f2tf32f(v.z * scale * wv.z);
    o.w = f2tf32f(v.w * scale * wv.w);
    ((float4*)(y + (size_t)row * D_))[tid] = o;
}

// ---------------- TF32 SGEMM NT: C = A[M,K]*B[N,K]^T + bias (+res)(+gelu) ----
// Block 128x128x32, 4 warps each 64x64 (2x2), mma m16n8k8 tf32.
// 128 B of smem traffic per MMA (vs 192 with 64x32 warp tiles).
// Operands pre-rounded to tf32 in gmem; inner loop uses raw bits.
#define GPITCH 36
#define GEMM_SMEM (2 * 2 * 128 * GPITCH * 4)   // 73728 bytes

template <int EPI>
__global__ __launch_bounds__(128, 2)
void gemm_tf32_kernel(const float* __restrict__ A, const float* __restrict__ Bm,
                      const float* __restrict__ bias, const float* __restrict__ res,
                      float* __restrict__ C, int M, int N, int K) {
    extern __shared__ float sm[];
    float* As = sm;                     // [2][128][GPITCH]
    float* Bs = sm + 2 * 128 * GPITCH;

    int bm = blockIdx.y * 128;
    int bn = blockIdx.x * 128;
    int tid = threadIdx.x;
    int warp = tid >> 5, lane = tid & 31;
    int wm = (warp & 1) * 64;
    int wn = (warp >> 1) * 64;
    int g = lane >> 2, t = lane & 3;

    float acc[4][8][4];
    #pragma unroll
    for (int mi = 0; mi < 4; mi++)
        #pragma unroll
        for (int ni = 0; ni < 8; ni++)
            #pragma unroll
            for (int r = 0; r < 4; r++) acc[mi][ni][r] = 0.f;

    int KT = K >> 5;

    // prologue: stage 0 (128 threads, 8 cp16 per tile-row-group)
    #pragma unroll
    for (int i = 0; i < 8; i++) {
        int c = i * 128 + tid;
        int row = c >> 3, cc = c & 7;
        cp_async16(&As[row * GPITCH + cc * 4], A + (size_t)(bm + row) * K + cc * 4);
        cp_async16(&Bs[row * GPITCH + cc * 4], Bm + (size_t)(bn + row) * K + cc * 4);
    }
    asm volatile("cp.async.commit_group;\n");

    int buf = 0;
    for (int kt = 0; kt < KT; kt++) {
        if (kt + 1 < KT) {
            int k0 = (kt + 1) << 5;
            int boff = (buf ^ 1) * 128 * GPITCH;
            #pragma unroll
            for (int i = 0; i < 8; i++) {
                int c = i * 128 + tid;
                int row = c >> 3, cc = c & 7;
                cp_async16(&As[boff + row * GPITCH + cc * 4],
                           A + (size_t)(bm + row) * K + k0 + cc * 4);
                cp_async16(&Bs[boff + row * GPITCH + cc * 4],
                           Bm + (size_t)(bn + row) * K + k0 + cc * 4);
            }
            asm volatile("cp.async.commit_group;\n");
            asm volatile("cp.async.wait_group 1;\n");
        } else {
            asm volatile("cp.async.wait_group 0;\n");
        }
        __syncthreads();

        const float* Ab = As + buf * 128 * GPITCH;
        const float* Bb = Bs + buf * 128 * GPITCH;
        #pragma unroll
        for (int kk = 0; kk < 32; kk += 8) {
            unsigned int af[4][4], bf[8][2];
            #pragma unroll
            for (int mi = 0; mi < 4; mi++) {
                const float* ap = Ab + (wm + mi * 16 + g) * GPITCH + kk + t;
                af[mi][0] = __float_as_uint(ap[0]);
                af[mi][1] = __float_as_uint(ap[8 * GPITCH]);
                af[mi][2] = __float_as_uint(ap[4]);
                af[mi][3] = __float_as_uint(ap[8 * GPITCH + 4]);
            }
            #pragma unroll
            for (int ni = 0; ni < 8; ni++) {
                const float* bp = Bb + (wn + ni * 8 + g) * GPITCH + kk + t;
                bf[ni][0] = __float_as_uint(bp[0]);
                bf[ni][1] = __float_as_uint(bp[4]);
            }
            #pragma unroll
            for (int mi = 0; mi < 4; mi++)
                #pragma unroll
                for (int ni = 0; ni < 8; ni++)
                    mma_tf32(acc[mi][ni], af[mi], bf[ni]);
        }
        __syncthreads();
        buf ^= 1;
    }

    // epilogue
    #pragma unroll
    for (int mi = 0; mi < 4; mi++) {
        #pragma unroll
        for (int ni = 0; ni < 8; ni++) {
            int col = bn + wn + ni * 8 + t * 2;
            #pragma unroll
            for (int half = 0; half < 2; half++) {
                int row = bm + wm + mi * 16 + g + half * 8;
                float2 v;
                v.x = acc[mi][ni][half * 2 + 0] + bias[col + 0];
                v.y = acc[mi][ni][half * 2 + 1] + bias[col + 1];
                if (EPI == 1) {
                    v.x = f2tf32f(0.5f * v.x * (1.f + erff(v.x * 0.7071067811865476f)));
                    v.y = f2tf32f(0.5f * v.y * (1.f + erff(v.y * 0.7071067811865476f)));
                }
                if (res != nullptr) {
                    float2 r = *(const float2*)(res + (size_t)row * N + col);
                    v.x += r.x; v.y += r.y;
                }
                *(float2*)(C + (size_t)row * N + col) = v;
            }
        }
    }
}

// ---------------- K5: TF32 tensor-core flash causal attention ----------------
#define ATP 72
#define ATT_SMEM ((128*ATP + 64*ATP + 64*ATP + 128*ATP) * 4)   // 110592 B

__global__ __launch_bounds__(256, 1)
void attn_tc_kernel(const float* __restrict__ qkv, float* __restrict__ o) {
    extern __shared__ float sm[];
    float* Qs = sm;                      // [128][ATP]
    float* Ks = sm + 128 * ATP;          // [64][ATP]
    float* Vs = sm + 192 * ATP;          // [64][ATP]
    float* Ps = sm + 256 * ATP;          // [128][ATP]

    int qt = blockIdx.x, h = blockIdx.y, b = blockIdx.z;
    int tid = threadIdx.x;
    int warp = tid >> 5, lane = tid & 31;
    int g = lane >> 2, t = lane & 3;
    int qr0 = qt * 128;
    const float* base = qkv + (size_t)b * S_ * (3 * D_);

    for (int i = tid; i < 128 * 64; i += 256) {
        int r = i >> 6, c = i & 63;
        Qs[r * ATP + c] =
            f2tf32f(base[(size_t)(qr0 + r) * (3 * D_) + h * HD + c] * 0.125f);
    }

    int row0 = warp * 16 + g;
    int row1 = row0 + 8;

    float oacc[8][4];
    float m0 = -1e30f, m1 = -1e30f, l0 = 0.f, l1 = 0.f;
    #pragma unroll
    for (int ni = 0; ni < 8; ni++)
        #pragma unroll
        for (int r = 0; r < 4; r++) oacc[ni][r] = 0.f;

    int jt_max = 2 * qt + 1;
    for (int jt = 0; jt <= jt_max; jt++) {
        int jr0 = jt * 64;
        __syncthreads();
        for (int i = tid; i < 64 * 64; i += 256) {
            int r = i >> 6, c = i & 63;
            Ks[r * ATP + c] =
                f2tf32f(base[(size_t)(jr0 + r) * (3 * D_) + D_ + h * HD + c]);
            Vs[r * ATP + c] =
                f2tf32f(base[(size_t)(jr0 + r) * (3 * D_) + 2 * D_ + h * HD + c]);
        }
        __syncthreads();

        if (jr0 > qr0 + warp * 16 + 15) continue;

        float sacc[8][4];
        #pragma unroll
        for (int ni = 0; ni < 8; ni++)
            #pragma unroll
            for (int r = 0; r < 4; r++) sacc[ni][r] = 0.f;

        #pragma unroll
        for (int kc = 0; kc < 8; kc++) {
            unsigned int aq[4];
            const float* qp0 = Qs + row0 * ATP + kc * 8 + t;
            const float* qp1 = Qs + row1 * ATP + kc * 8 + t;
            aq[0] = __float_as_uint(qp0[0]);
            aq[1] = __float_as_uint(qp1[0]);
            aq[2] = __float_as_uint(qp0[4]);
            aq[3] = __float_as_uint(qp1[4]);
            #pragma unroll
            for (int ni = 0; ni < 8; ni++) {
                unsigned int bk[2];
                const float* kp = Ks + (ni * 8 + g) * ATP + kc * 8 + t;
                bk[0] = __float_as_uint(kp[0]);
                bk[1] = __float_as_uint(kp[4]);
                mma_tf32(sacc[ni], aq, bk);
            }
        }

        if (jr0 + 63 > qr0 + warp * 16) {
            int gr0 = qr0 + row0, gr1 = qr0 + row1;
            #pragma unroll
            for (int ni = 0; ni < 8; ni++) {
                int c0 = jr0 + ni * 8 + 2 * t;
                if (c0 > gr0)     sacc[ni][0] = -1e30f;
                if (c0 + 1 > gr0) sacc[ni][1] = -1e30f;
                if (c0 > gr1)     sacc[ni][2] = -1e30f;
                if (c0 + 1 > gr1) sacc[ni][3] = -1e30f;
            }
        }

        float mx0 = -1e30f, mx1 = -1e30f;
        #pragma unroll
        for (int ni = 0; ni < 8; ni++) {
            mx0 = fmaxf(mx0, fmaxf(sacc[ni][0], sacc[ni][1]));
            mx1 = fmaxf(mx1, fmaxf(sacc[ni][2], sacc[ni][3]));
        }
        #pragma unroll
        for (int off = 1; off < 4; off <<= 1) {
            mx0 = fmaxf(mx0, __shfl_xor_sync(0xffffffffu, mx0, off));
            mx1 = fmaxf(mx1, __shfl_xor_sync(0xffffffffu, mx1, off));
        }
        float nm0 = fmaxf(m0, mx0), nm1 = fmaxf(m1, mx1);
        float ps0 = 0.f, ps1 = 0.f;
        #pragma unroll
        for (int ni = 0; ni < 8; ni++) {
            sacc[ni][0] = __expf(sacc[ni][0] - nm0);
            sacc[ni][1] = __expf(sacc[ni][1] - nm0);
            sacc[ni][2] = __expf(sacc[ni][2] - nm1);
            sacc[ni][3] = __expf(sacc[ni][3] - nm1);
            ps0 += sacc[ni][0] + sacc[ni][1];
            ps1 += sacc[ni][2] + sacc[ni][3];
        }
        #pragma unroll
        for (int off = 1; off < 4; off <<= 1) {
            ps0 += __shfl_xor_sync(0xffffffffu, ps0, off);
            ps1 += __shfl_xor_sync(0xffffffffu, ps1, off);
        }
        float al0 = __expf(m0 - nm0), al1 = __expf(m1 - nm1);
        l0 = l0 * al0 + ps0;  m0 = nm0;
        l1 = l1 * al1 + ps1;  m1 = nm1;
        #pragma unroll
        for (int ni = 0; ni < 8; ni++) {
            oacc[ni][0] *= al0; oacc[ni][1] *= al0;
            oacc[ni][2] *= al1; oacc[ni][3] *= al1;
        }

        #pragma unroll
        for (int ni = 0; ni < 8; ni++) {
            Ps[row0 * ATP + ni * 8 + 2 * t]     = f2tf32f(sacc[ni][0]);
            Ps[row0 * ATP + ni * 8 + 2 * t + 1] = f2tf32f(sacc[ni][1]);
            Ps[row1 * ATP + ni * 8 + 2 * t]     = f2tf32f(sacc[ni][2]);
            Ps[row1 * ATP + ni * 8 + 2 * t + 1] = f2tf32f(sacc[ni][3]);
        }
        __syncwarp();

        #pragma unroll
        for (int kc = 0; kc < 8; kc++) {
            unsigned int ap[4];
            const float* pp0 = Ps + row0 * ATP + kc * 8 + t;
            const float* pp1 = Ps + row1 * ATP + kc * 8 + t;
            ap[0] = __float_as_uint(pp0[0]);
            ap[1] = __float_as_uint(pp1[0]);
            ap[2] = __float_as_uint(pp0[4]);
            ap[3] = __float_as_uint(pp1[4]);
            #pragma unroll
            for (int ni = 0; ni < 8; ni++) {
                unsigned int bv[2];
                const float* vp = Vs + (kc * 8 + t) * ATP + ni * 8 + g;
                bv[0] = __float_as_uint(vp[0]);
                bv[1] = __float_as_uint(vp[4 * ATP]);
                mma_tf32(oacc[ni], ap, bv);
            }
        }
        __syncwarp();
    }

    float inv0 = 1.f / l0, inv1 = 1.f / l1;
    size_t gr0 = (size_t)(b * S_ + qr0 + row0) * D_ + h * HD;
    size_t gr1 = (size_t)(b * S_ + qr0 + row1) * D_ + h * HD;
    #pragma unroll
    for (int ni = 0; ni < 8; ni++) {
        int c = ni * 8 + 2 * t;
        o[gr0 + c]     = f2tf32f(oacc[ni][0] * inv0);
        o[gr0 + c + 1] = f2tf32f(oacc[ni][1] * inv0);
        o[gr1 + c]     = f2tf32f(oacc[ni][2] * inv1);
        o[gr1 + c + 1] = f2tf32f(oacc[ni][3] * inv1);
    }
}

// ---------------- K10: final sum + mhc mix ----------------------------------
__global__ void final_kernel(const float* __restrict__ attnres,
                             const float* __restrict__ ffn,
                             const float* __restrict__ xd,
                             const float* __restrict__ W,
                             float* __restrict__ out) {
    __shared__ float row[D_];
    __shared__ float Ws[64];
    int r = blockIdx.x;
    int b = r >> 11;
    int tid = threadIdx.x;
    ((float4*)row)[tid] = ((const float4*)(xd + (size_t)r * D_))[tid];
    if (tid < 64) Ws[tid] = W[b * 64 + tid];
    __syncthreads();

    int c0 = tid * 4;
    int m = c0 >> 7;
    int dp = c0 & 127;
    float mh0 = 0.f, mh1 = 0.f, mh2 = 0.f, mh3 = 0.f;
    #pragma unroll
    for (int n = 0; n < 8; n++) {
        float w = Ws[m * 8 + n];
        const float* rp = row + n * 128 + dp;
        mh0 += w * rp[0]; mh1 += w * rp[1]; mh2 += w * rp[2]; mh3 += w * rp[3];
    }
    float4 a = ((const float4*)(attnres + (size_t)r * D_))[tid];
    float4 f = ((const float4*)(ffn + (size_t)r * D_))[tid];
    float4 ov;
    ov.x = a.x + f.x + mh0;
    ov.y = a.y + f.y + mh1;
    ov.z = a.z + f.z + mh2;
    ov.w = a.w + f.w + mh3;
    ((float4*)(out + (size_t)r * D_))[tid] = ov;
}

// ---------------- launch ----------------------------------------------------
extern "C" void kernel_launch(void* const* d_in, const int* in_sizes, int n_in,
                              void* d_out, int out_size) {
    const float* x        = (const float*)d_in[0];
    const float* decay    = (const float*)d_in[3];
    const float* gate_w   = (const float*)d_in[4];
    const float* gate_b   = (const float*)d_in[5];
    const float* phi      = (const float*)d_in[6];
    const float* ln1_w    = (const float*)d_in[7];
    const float* ln2_w    = (const float*)d_in[8];
    const float* w1       = (const float*)d_in[9];
    const float* b1       = (const float*)d_in[10];
    const float* w2       = (const float*)d_in[11];
    const float* b2       = (const float*)d_in[12];
    const float* in_proj_w= (const float*)d_in[13];
    const float* in_proj_b= (const float*)d_in[14];
    const float* out_w    = (const float*)d_in[15];
    const float* out_b    = (const float*)d_in[16];
    float* out = (float*)d_out;

    void *p_xdelta, *p_xstate, *p_W, *p_normed, *p_qkv, *p_o, *p_attnres,
         *p_normed2, *p_h, *p_ffn, *p_wqkv, *p_wout, *p_w1, *p_w2;
    cudaGetSymbolAddress(&p_xdelta, g_xdelta);
    cudaGetSymbolAddress(&p_xstate, g_xstate);
    cudaGetSymbolAddress(&p_W, g_W);
    cudaGetSymbolAddress(&p_normed, g_normed);
    cudaGetSymbolAddress(&p_qkv, g_qkv);
    cudaGetSymbolAddress(&p_o, g_o);
    cudaGetSymbolAddress(&p_attnres, g_attnres);
    cudaGetSymbolAddress(&p_normed2, g_normed2);
    cudaGetSymbolAddress(&p_h, g_h);
    cudaGetSymbolAddress(&p_ffn, g_ffn);
    cudaGetSymbolAddress(&p_wqkv, g_wqkv_r);
    cudaGetSymbolAddress(&p_wout, g_wout_r);
    cudaGetSymbolAddress(&p_w1, g_w1_r);
    cudaGetSymbolAddress(&p_w2, g_w2_r);

    float* xdelta  = (float*)p_xdelta;
    float* xstate  = (float*)p_xstate;
    float* Wm      = (float*)p_W;
    float* normed  = (float*)p_normed;
    float* qkv     = (float*)p_qkv;
    float* ob      = (float*)p_o;
    float* attnres = (float*)p_attnres;
    float* normed2 = (float*)p_normed2;
    float* hbuf    = (float*)p_h;
    float* ffn     = (float*)p_ffn;
    float* wqkv_r  = (float*)p_wqkv;
    float* wout_r  = (float*)p_wout;
    float* w1_r    = (float*)p_w1;
    float* w2_r    = (float*)p_w2;

    cudaFuncSetAttribute(gemm_tf32_kernel<0>,
                         cudaFuncAttributeMaxDynamicSharedMemorySize, GEMM_SMEM);
    cudaFuncSetAttribute(gemm_tf32_kernel<1>,
                         cudaFuncAttributeMaxDynamicSharedMemorySize, GEMM_SMEM);
    cudaFuncSetAttribute(attn_tc_kernel,
                         cudaFuncAttributeMaxDynamicSharedMemorySize, ATT_SMEM);

    // 0) pre-round weights to tf32
    round_tf32_kernel<<<1024, 256>>>((const float4*)in_proj_w, (float4*)wqkv_r,
                                     3 * D_ * D_ / 4);
    round_tf32_kernel<<<1024, 256>>>((const float4*)out_w, (float4*)wout_r,
                                     D_ * D_ / 4);
    round_tf32_kernel<<<1024, 256>>>((const float4*)w1, (float4*)w1_r,
                                     4 * D_ * D_ / 4);
    round_tf32_kernel<<<1024, 256>>>((const float4*)w2, (float4*)w2_r,
                                     4 * D_ * D_ / 4);

    // 1) delta scan
    delta_scan_kernel<<<256, 256>>>(x, decay, xdelta, xstate);
    // 2) gates + sinkhorn
    gate_sinkhorn_kernel<<<1, 256>>>(xstate, gate_w, gate_b, phi, Wm);
    // 3) rmsnorm1 (tf32-rounded output)
    rmsnorm_kernel<<<NTOK, 256>>>(xdelta, ln1_w, normed);
    // 4) qkv projection
    gemm_tf32_kernel<0><<<dim3(3 * D_ / 128, NTOK / 128), 128, GEMM_SMEM>>>(
        normed, wqkv_r, in_proj_b, nullptr, qkv, NTOK, 3 * D_, D_);
    // 5) attention (tensor-core flash)
    attn_tc_kernel<<<dim3(S_ / 128, NH, B_), 256, ATT_SMEM>>>(qkv, ob);
    // 6) out projection + residual(x_delta)
    gemm_tf32_kernel<0><<<dim3(D_ / 128, NTOK / 128), 128, GEMM_SMEM>>>(
        ob, wout_r, out_b, xdelta, attnres, NTOK, D_, D_);
    // 7) rmsnorm2 (tf32-rounded output)
    rmsnorm_kernel<<<NTOK, 256>>>(attnres, ln2_w, normed2);
    // 8) FFN1 + gelu (tf32-rounded output)
    gemm_tf32_kernel<1><<<dim3(4 * D_ / 128, NTOK / 128), 128, GEMM_SMEM>>>(
        normed2, w1_r, b1, nullptr, hbuf, NTOK, 4 * D_, D_);
    // 9) FFN2
    gemm_tf32_kernel<0><<<dim3(D_ / 128, NTOK / 128), 128, GEMM_SMEM>>>(
        hbuf, w2_r, b2, nullptr, ffn, NTOK, D_, 4 * D_);
    // 10) final
    final_kernel<<<NTOK, 256>>>(attnres, ffn, xdelta, Wm, out);
}

// round 13
// speedup vs baseline: 3.6929x; 1.3408x over previous
#include <cuda_runtime.h>
#include <cuda_fp16.h>
#include <cuda_bf16.h>
#include <math.h>
#include <stdint.h>

// Problem constants
#define B_  2
#define S_  2048
#define D_  1024
#define NH  16
#define HD  64
#define NTOK (B_*S_)          // 4096

// ---------------- scratch (static __device__, no allocation) ----------------
__device__ float  g_xdelta[NTOK * D_];
__device__ float  g_xstate[B_ * D_];
__device__ float  g_W[B_ * 8 * 8];
__device__ float  g_qkv[NTOK * 3 * D_];
__device__ float  g_attnres[NTOK * D_];
__device__ float  g_ffn[NTOK * D_];
// fp16 activations (GEMM operands)
__device__ __half g_normed_h[NTOK * D_];
__device__ __half g_normed2_h[NTOK * D_];
__device__ __half g_o_h[NTOK * D_];
__device__ __half g_h_h[NTOK * 4 * D_];
// fp16 weight copies
__device__ __half g_wqkv_h[3 * D_ * D_];
__device__ __half g_wout_h[D_ * D_];
__device__ __half g_w1_h[4 * D_ * D_];
__device__ __half g_w2_h[4 * D_ * D_];

// ---------------- helpers ----------------------------------------------------
__device__ __forceinline__ float f2tf32f(float v) {
    unsigned int r;
    asm("cvt.rna.tf32.f32 %0, %1;" : "=r"(r) : "f"(v));
    return __uint_as_float(r);
}
__device__ __forceinline__ void mma_tf32(float* c, const unsigned int* a,
                                         const unsigned int* b) {
    asm volatile(
        "mma.sync.aligned.m16n8k8.row.col.f32.tf32.tf32.f32 "
        "{%0,%1,%2,%3}, {%4,%5,%6,%7}, {%8,%9}, {%0,%1,%2,%3};"
        : "+f"(c[0]), "+f"(c[1]), "+f"(c[2]), "+f"(c[3])
        : "r"(a[0]), "r"(a[1]), "r"(a[2]), "r"(a[3]), "r"(b[0]), "r"(b[1]));
}
__device__ __forceinline__ void mma_f16(float* c, const unsigned int* a,
                                        const unsigned int* b) {
    asm volatile(
        "mma.sync.aligned.m16n8k16.row.col.f32.f16.f16.f32 "
        "{%0,%1,%2,%3}, {%4,%5,%6,%7}, {%8,%9}, {%0,%1,%2,%3};"
        : "+f"(c[0]), "+f"(c[1]), "+f"(c[2]), "+f"(c[3])
        : "r"(a[0]), "r"(a[1]), "r"(a[2]), "r"(a[3]), "r"(b[0]), "r"(b[1]));
}
__device__ __forceinline__ void cp_async16s(unsigned int saddr, const void* g) {
    asm volatile("cp.async.cg.shared.global [%0], [%1], 16;\n" :: "r"(saddr), "l"(g));
}

// ---------------- K0: convert weights to fp16 --------------------------------
__global__ void tohalf_kernel(const float4* __restrict__ src,
                              __half2* __restrict__ dst, int n4) {
    int i = blockIdx.x * blockDim.x + threadIdx.x;
    int stride = gridDim.x * blockDim.x;
    for (; i < n4; i += stride) {
        float4 v = src[i];
        dst[2 * i]     = __floats2half2_rn(v.x, v.y);
        dst[2 * i + 1] = __floats2half2_rn(v.z, v.w);
    }
}

// ---------------- K1: delta EMA scan (warp-parallel affine scan) -------------
__global__ void delta_scan_kernel(const float* __restrict__ x,
                                  const float* __restrict__ decay,
                                  float* __restrict__ xd,
                                  float* __restrict__ xstate) {
    int warp = (blockIdx.x * blockDim.x + threadIdx.x) >> 5;
    int lane = threadIdx.x & 31;
    if (warp >= B_ * D_) return;
    int b = warp >> 10;
    int d = warp & (D_ - 1);
    float beta = 1.f / (1.f + __expf(-decay[d]));
    float onem = 1.f - beta;

    const float* xp = x  + (size_t)b * S_ * D_ + d;
    float*       op = xd + (size_t)b * S_ * D_ + d;

    float carry = 0.f;
    float sum = 0.f;
    for (int t0 = 0; t0 < S_; t0 += 32) {
        float xt = xp[(size_t)(t0 + lane) * D_];
        float a = beta, bb = onem * xt;
        #pragma unroll
        for (int off = 1; off < 32; off <<= 1) {
            float pa = __shfl_up_sync(0xffffffffu, a, off);
            float pb = __shfl_up_sync(0xffffffffu, bb, off);
            if (lane >= off) { bb = a * pb + bb; a = a * pa; }
        }
        float s_incl = a * carry + bb;
        float s_prev = __shfl_up_sync(0xffffffffu, s_incl, 1);
        if (lane == 0) s_prev = carry;
        float out = xt - s_prev;
        op[(size_t)(t0 + lane) * D_] = out;
        sum += out;
        carry = __shfl_sync(0xffffffffu, s_incl, 31);
    }
    #pragma unroll
    for (int off = 16; off >= 1; off >>= 1)
        sum += __shfl_xor_sync(0xffffffffu, sum, off);
    if (lane == 0) xstate[warp] = sum * (1.f / (float)S_);
}

// ---------------- K2: gates + sinkhorn + W --------------------------------
__global__ void gate_sinkhorn_kernel(const float* __restrict__ xstate,
                                     const float* __restrict__ gate_w,
                                     const float* __restrict__ gate_b,
                                     const float* __restrict__ phi,
                                     float* __restrict__ W) {
    __shared__ float gbuf[B_][8];
    __shared__ float Km[64];
    __shared__ float tmp[64];
    int tid = threadIdx.x;
    int wid = tid >> 5, lane = tid & 31;

    for (int idx = wid; idx < 16; idx += 8) {
        int b = idx >> 3;
        int j = 16 + (idx & 7);
        float s = 0.f;
        for (int k = lane; k < D_; k += 32)
            s += xstate[b * D_ + k] * gate_w[j * D_ + k];
        #pragma unroll
        for (int off = 16; off >= 1; off >>= 1)
            s += __shfl_xor_sync(0xffffffffu, s, off);
        if (lane == 0)
            gbuf[b][idx & 7] = 1.f / (1.f + __expf(-(s + gate_b[j])));
    }
    if (tid < 64) Km[tid] = __expf(phi[tid]);
    __syncthreads();

    for (int it = 0; it < 15; it++) {
        if (tid < 64) {
            int m = tid >> 3;
            float rs = 0.f;
            #pragma unroll
            for (int n = 0; n < 8; n++) rs += Km[m * 8 + n];
            tmp[tid] = Km[tid] / rs;
        }
        __syncthreads();
        if (tid < 64) {
            int n = tid & 7;
            float cs = 0.f;
            #pragma unroll
            for (int m = 0; m < 8; m++) cs += tmp[m * 8 + n];
            Km[tid] = tmp[tid] / cs;
        }
        __syncthreads();
    }
    if (tid < 128) {
        int b = tid >> 6, r = tid & 63, n = r & 7;
        W[b * 64 + r] = Km[r] * gbuf[b][n];
    }
}

// ---------------- K3: RMSNorm (block per row, fp16 output) -------------------
__global__ void rmsnorm_kernel(const float* __restrict__ x,
                               const float* __restrict__ w,
                               __half* __restrict__ y) {
    int row = blockIdx.x;
    int tid = threadIdx.x;
    const float4* xr = (const float4*)(x + (size_t)row * D_);
    float4 v = xr[tid];
    float ss = v.x * v.x + v.y * v.y + v.z * v.z + v.w * v.w;
    __shared__ float red[8];
    #pragma unroll
    for (int off = 16; off >= 1; off >>= 1)
        ss += __shfl_xor_sync(0xffffffffu, ss, off);
    if ((tid & 31) == 0) red[tid >> 5] = ss;
    __syncthreads();
    if (tid < 8) {
        float t = red[tid];
        #pragma unroll
        for (int off = 4; off >= 1; off >>= 1)
            t += __shfl_xor_sync(0xffu, t, off);
        if (tid == 0) red[0] = t;
    }
    __syncthreads();
    float scale = rsqrtf(red[0] * (1.f / (float)D_) + 1e-6f);
    float4 wv = ((const float4*)w)[tid];
    __half2* yp = (__half2*)(y + (size_t)row * D_);
    yp[2 * tid]     = __floats2half2_rn(v.x * scale * wv.x, v.y * scale * wv.y);
    yp[2 * tid + 1] = __floats2half2_rn(v.z * scale * wv.z, v.w * scale * wv.w);
}

// ---------------- FP16 GEMM NT: C = A[M,K]*B[N,K]^T + bias (+res)(+gelu) -----
// Block 128x128, 4 warps each 64x64, mma m16n8k16 f16 (fp32 accum).
// K chunk = 32 halves (64B/row), double-buffered cp.async.
// smem pitch 80B/row -> fragment bank map 20g+t: conflict-free.
// EPI: 0 = fp32 out, bias (+res); 1 = fp16 out, bias + exact GELU.
#define HP  40          // halves per smem row
#define HSTG 5120       // halves per stage (128 * 40)
#define GEMM_SMEM_H (4 * HSTG * 2)     // 40960 bytes

__device__ __forceinline__ void ld_chunk_f16(unsigned int abuf, unsigned int bbuf,
                                             const __half* __restrict__ A,
                                             const __half* __restrict__ Bm,
                                             int bm, int bn, int K, int k0, int tid) {
    #pragma unroll
    for (int i = 0; i < 4; i++) {
        int c = i * 128 + tid;
        int r = c >> 2, q = c & 3;
        cp_async16s(abuf + r * 80 + q * 16, A + (size_t)(bm + r) * K + k0 + q * 8);
        cp_async16s(bbuf + r * 80 + q * 16, Bm + (size_t)(bn + r) * K + k0 + q * 8);
    }
    asm volatile("cp.async.commit_group;\n" ::: "memory");
}

template <int EPI>
__global__ __launch_bounds__(128, 2)
void gemm_f16_kernel(const __half* __restrict__ A, const __half* __restrict__ Bm,
                     const float* __restrict__ bias, const float* __restrict__ res,
                     void* __restrict__ Cv, int M, int N, int K) {
    extern __shared__ __align__(16) char smemc[];
    unsigned int sbase = (unsigned int)__cvta_generic_to_shared(smemc);
    const __half* Sh = (const __half*)smemc;

    int bm = blockIdx.y * 128;
    int bn = blockIdx.x * 128;
    int tid = threadIdx.x;
    int warp = tid >> 5, lane = tid & 31;
    int wm = (warp & 1) * 64;
    int wn = (warp >> 1) * 64;
    int g = lane >> 2, t = lane & 3;

    float acc[4][8][4];
    #pragma unroll
    for (int mi = 0; mi < 4; mi++)
        #pragma unroll
        for (int ni = 0; ni < 8; ni++)
            #pragma unroll
            for (int r = 0; r < 4; r++) acc[mi][ni][r] = 0.f;

    int KT = K >> 5;
    // byte offsets: A0=0, A1=10240, B0=20480, B1=30720
    ld_chunk_f16(sbase, sbase + 20480, A, Bm, bm, bn, K, 0, tid);

    int buf = 0;
    for (int kt = 0; kt < KT; kt++) {
        if (kt + 1 < KT) {
            int boff = (buf ^ 1) * 10240;
            ld_chunk_f16(sbase + boff, sbase + 20480 + boff,
                         A, Bm, bm, bn, K, (kt + 1) << 5, tid);
            asm volatile("cp.async.wait_group 1;\n" ::: "memory");
        } else {
            asm volatile("cp.async.wait_group 0;\n" ::: "memory");
        }
        __syncthreads();

        const __half* Ah = Sh + buf * HSTG;
        const __half* Bh = Sh + 2 * HSTG + buf * HSTG;
        #pragma unroll
        for (int s = 0; s < 2; s++) {
            unsigned int af[4][4], bf[8][2];
            #pragma unroll
            for (int mi = 0; mi < 4; mi++) {
                const __half* ap = Ah + (wm + mi * 16 + g) * HP + s * 16 + 2 * t;
                af[mi][0] = *(const unsigned int*)ap;
                af[mi][1] = *(const unsigned int*)(ap + 8 * HP);
                af[mi][2] = *(const unsigned int*)(ap + 8);
                af[mi][3] = *(const unsigned int*)(ap + 8 * HP + 8);
            }
            #pragma unroll
            for (int ni = 0; ni < 8; ni++) {
                const __half* bp = Bh + (wn + ni * 8 + g) * HP + s * 16 + 2 * t;
                bf[ni][0] = *(const unsigned int*)bp;
                bf[ni][1] = *(const unsigned int*)(bp + 8);
            }
            #pragma unroll
            for (int mi = 0; mi < 4; mi++)
                #pragma unroll
                for (int ni = 0; ni < 8; ni++)
                    mma_f16(acc[mi][ni], af[mi], bf[ni]);
        }
        __syncthreads();
        buf ^= 1;
    }

    // epilogue
    #pragma unroll
    for (int mi = 0; mi < 4; mi++) {
        #pragma unroll
        for (int ni = 0; ni < 8; ni++) {
            int col = bn + wn + ni * 8 + t * 2;
            #pragma unroll
            for (int half = 0; half < 2; half++) {
                int row = bm + wm + mi * 16 + g + half * 8;
                float vx = acc[mi][ni][half * 2 + 0] + bias[col + 0];
                float vy = acc[mi][ni][half * 2 + 1] + bias[col + 1];
                if (EPI == 1) {
                    vx = 0.5f * vx * (1.f + erff(vx * 0.7071067811865476f));
                    vy = 0.5f * vy * (1.f + erff(vy * 0.7071067811865476f));
                    __half2* C = (__half2*)((__half*)Cv + (size_t)row * N + col);
                    *C = __floats2half2_rn(vx, vy);
                } else {
                    if (res != nullptr) {
                        float2 r = *(const float2*)(res + (size_t)row * N + col);
                        vx += r.x; vy += r.y;
                    }
                    float2 v; v.x = vx; v.y = vy;
                    *(float2*)((float*)Cv + (size_t)row * N + col) = v;
                }
            }
        }
    }
}

// ---------------- K5: TF32 tensor-core flash causal attention ----------------
#define ATP 72
#define ATT_SMEM ((128*ATP + 64*ATP + 64*ATP + 128*ATP) * 4)   // 110592 B

__global__ __launch_bounds__(256, 1)
void attn_tc_kernel(const float* __restrict__ qkv, __half* __restrict__ o) {
    extern __shared__ float sm[];
    float* Qs = sm;                      // [128][ATP]
    float* Ks = sm + 128 * ATP;          // [64][ATP]
    float* Vs = sm + 192 * ATP;          // [64][ATP]
    float* Ps = sm + 256 * ATP;          // [128][ATP]

    int qt = blockIdx.x, h = blockIdx.y, b = blockIdx.z;
    int tid = threadIdx.x;
    int warp = tid >> 5, lane = tid & 31;
    int g = lane >> 2, t = lane & 3;
    int qr0 = qt * 128;
    const float* base = qkv + (size_t)b * S_ * (3 * D_);

    for (int i = tid; i < 128 * 64; i += 256) {
        int r = i >> 6, c = i & 63;
        Qs[r * ATP + c] =
            f2tf32f(base[(size_t)(qr0 + r) * (3 * D_) + h * HD + c] * 0.125f);
    }

    int row0 = warp * 16 + g;
    int row1 = row0 + 8;

    float oacc[8][4];
    float m0 = -1e30f, m1 = -1e30f, l0 = 0.f, l1 = 0.f;
    #pragma unroll
    for (int ni = 0; ni < 8; ni++)
        #pragma unroll
        for (int r = 0; r < 4; r++) oacc[ni][r] = 0.f;

    int jt_max = 2 * qt + 1;
    for (int jt = 0; jt <= jt_max; jt++) {
        int jr0 = jt * 64;
        __syncthreads();
        for (int i = tid; i < 64 * 64; i += 256) {
            int r = i >> 6, c = i & 63;
            Ks[r * ATP + c] =
                f2tf32f(base[(size_t)(jr0 + r) * (3 * D_) + D_ + h * HD + c]);
            Vs[r * ATP + c] =
                f2tf32f(base[(size_t)(jr0 + r) * (3 * D_) + 2 * D_ + h * HD + c]);
        }
        __syncthreads();

        if (jr0 > qr0 + warp * 16 + 15) continue;

        float sacc[8][4];
        #pragma unroll
        for (int ni = 0; ni < 8; ni++)
            #pragma unroll
            for (int r = 0; r < 4; r++) sacc[ni][r] = 0.f;

        #pragma unroll
        for (int kc = 0; kc < 8; kc++) {
            unsigned int aq[4];
            const float* qp0 = Qs + row0 * ATP + kc * 8 + t;
            const float* qp1 = Qs + row1 * ATP + kc * 8 + t;
            aq[0] = __float_as_uint(qp0[0]);
            aq[1] = __float_as_uint(qp1[0]);
            aq[2] = __float_as_uint(qp0[4]);
            aq[3] = __float_as_uint(qp1[4]);
            #pragma unroll
            for (int ni = 0; ni < 8; ni++) {
                unsigned int bk[2];
                const float* kp = Ks + (ni * 8 + g) * ATP + kc * 8 + t;
                bk[0] = __float_as_uint(kp[0]);
                bk[1] = __float_as_uint(kp[4]);
                mma_tf32(sacc[ni], aq, bk);
            }
        }

        if (jr0 + 63 > qr0 + warp * 16) {
            int gr0 = qr0 + row0, gr1 = qr0 + row1;
            #pragma unroll
            for (int ni = 0; ni < 8; ni++) {
                int c0 = jr0 + ni * 8 + 2 * t;
                if (c0 > gr0)     sacc[ni][0] = -1e30f;
                if (c0 + 1 > gr0) sacc[ni][1] = -1e30f;
                if (c0 > gr1)     sacc[ni][2] = -1e30f;
                if (c0 + 1 > gr1) sacc[ni][3] = -1e30f;
            }
        }

        float mx0 = -1e30f, mx1 = -1e30f;
        #pragma unroll
        for (int ni = 0; ni < 8; ni++) {
            mx0 = fmaxf(mx0, fmaxf(sacc[ni][0], sacc[ni][1]));
            mx1 = fmaxf(mx1, fmaxf(sacc[ni][2], sacc[ni][3]));
        }
        #pragma unroll
        for (int off = 1; off < 4; off <<= 1) {
            mx0 = fmaxf(mx0, __shfl_xor_sync(0xffffffffu, mx0, off));
            mx1 = fmaxf(mx1, __shfl_xor_sync(0xffffffffu, mx1, off));
        }
        float nm0 = fmaxf(m0, mx0), nm1 = fmaxf(m1, mx1);
        float ps0 = 0.f, ps1 = 0.f;
        #pragma unroll
        for (int ni = 0; ni < 8; ni++) {
            sacc[ni][0] = __expf(sacc[ni][0] - nm0);
            sacc[ni][1] = __expf(sacc[ni][1] - nm0);
            sacc[ni][2] = __expf(sacc[ni][2] - nm1);
            sacc[ni][3] = __expf(sacc[ni][3] - nm1);
            ps0 += sacc[ni][0] + sacc[ni][1];
            ps1 += sacc[ni][2] + sacc[ni][3];
        }
        #pragma unroll
        for (int off = 1; off < 4; off <<= 1) {
            ps0 += __shfl_xor_sync(0xffffffffu, ps0, off);
            ps1 += __shfl_xor_sync(0xffffffffu, ps1, off);
        }
        float al0 = __expf(m0 - nm0), al1 = __expf(m1 - nm1);
        l0 = l0 * al0 + ps0;  m0 = nm0;
        l1 = l1 * al1 + ps1;  m1 = nm1;
        #pragma unroll
        for (int ni = 0; ni < 8; ni++) {
            oacc[ni][0] *= al0; oacc[ni][1] *= al0;
            oacc[ni][2] *= al1; oacc[ni][3] *= al1;
        }

        #pragma unroll
        for (int ni = 0; ni < 8; ni++) {
            Ps[row0 * ATP + ni * 8 + 2 * t]     = f2tf32f(sacc[ni][0]);
            Ps[row0 * ATP + ni * 8 + 2 * t + 1] = f2tf32f(sacc[ni][1]);
            Ps[row1 * ATP + ni * 8 + 2 * t]     = f2tf32f(sacc[ni][2]);
            Ps[row1 * ATP + ni * 8 + 2 * t + 1] = f2tf32f(sacc[ni][3]);
        }
        __syncwarp();

        #pragma unroll
        for (int kc = 0; kc < 8; kc++) {
            unsigned int ap[4];
            const float* pp0 = Ps + row0 * ATP + kc * 8 + t;
            const float* pp1 = Ps + row1 * ATP + kc * 8 + t;
            ap[0] = __float_as_uint(pp0[0]);
            ap[1] = __float_as_uint(pp1[0]);
            ap[2] = __float_as_uint(pp0[4]);
            ap[3] = __float_as_uint(pp1[4]);
            #pragma unroll
            for (int ni = 0; ni < 8; ni++) {
                unsigned int bv[2];
                const float* vp = Vs + (kc * 8 + t) * ATP + ni * 8 + g;
                bv[0] = __float_as_uint(vp[0]);
                bv[1] = __float_as_uint(vp[4 * ATP]);
                mma_tf32(oacc[ni], ap, bv);
            }
        }
        __syncwarp();
    }

    // O feeds the fp16 out-proj GEMM -> write half2
    float inv0 = 1.f / l0, inv1 = 1.f / l1;
    size_t gr0 = (size_t)(b * S_ + qr0 + row0) * D_ + h * HD;
    size_t gr1 = (size_t)(b * S_ + qr0 + row1) * D_ + h * HD;
    #pragma unroll
    for (int ni = 0; ni < 8; ni++) {
        int c = ni * 8 + 2 * t;
        *(__half2*)(o + gr0 + c) = __floats2half2_rn(oacc[ni][0] * inv0,
                                                     oacc[ni][1] * inv0);
        *(__half2*)(o + gr1 + c) = __floats2half2_rn(oacc[ni][2] * inv1,
                                                     oacc[ni][3] * inv1);
    }
}

// ---------------- K10: final sum + mhc mix ----------------------------------
__global__ void final_kernel(const float* __restrict__ attnres,
                             const float* __restrict__ ffn,
                             const float* __restrict__ xd,
                             const float* __restrict__ W,
                             float* __restrict__ out) {
    __shared__ float row[D_];
    __shared__ float Ws[64];
    int r = blockIdx.x;
    int b = r >> 11;
    int tid = threadIdx.x;
    ((float4*)row)[tid] = ((const float4*)(xd + (size_t)r * D_))[tid];
    if (tid < 64) Ws[tid] = W[b * 64 + tid];
    __syncthreads();

    int c0 = tid * 4;
    int m = c0 >> 7;
    int dp = c0 & 127;
    float mh0 = 0.f, mh1 = 0.f, mh2 = 0.f, mh3 = 0.f;
    #pragma unroll
    for (int n = 0; n < 8; n++) {
        float w = Ws[m * 8 + n];
        const float* rp = row + n * 128 + dp;
        mh0 += w * rp[0]; mh1 += w * rp[1]; mh2 += w * rp[2]; mh3 += w * rp[3];
    }
    float4 a = ((const float4*)(attnres + (size_t)r * D_))[tid];
    float4 f = ((const float4*)(ffn + (size_t)r * D_))[tid];
    float4 ov;
    ov.x = a.x + f.x + mh0;
    ov.y = a.y + f.y + mh1;
    ov.z = a.z + f.z + mh2;
    ov.w = a.w + f.w + mh3;
    ((float4*)(out + (size_t)r * D_))[tid] = ov;
}

// ---------------- launch ----------------------------------------------------
extern "C" void kernel_launch(void* const* d_in, const int* in_sizes, int n_in,
                              void* d_out, int out_size) {
    const float* x        = (const float*)d_in[0];
    const float* decay    = (const float*)d_in[3];
    const float* gate_w   = (const float*)d_in[4];
    const float* gate_b   = (const float*)d_in[5];
    const float* phi      = (const float*)d_in[6];
    const float* ln1_w    = (const float*)d_in[7];
    const float* ln2_w    = (const float*)d_in[8];
    const float* w1       = (const float*)d_in[9];
    const float* b1       = (const float*)d_in[10];
    const float* w2       = (const float*)d_in[11];
    const float* b2       = (const float*)d_in[12];
    const float* in_proj_w= (const float*)d_in[13];
    const float* in_proj_b= (const float*)d_in[14];
    const float* out_w    = (const float*)d_in[15];
    const float* out_b    = (const float*)d_in[16];
    float* out = (float*)d_out;

    void *p_xdelta, *p_xstate, *p_W, *p_qkv, *p_attnres, *p_ffn,
         *p_normed, *p_normed2, *p_oh, *p_hh, *p_wqkv, *p_wout, *p_w1, *p_w2;
    cudaGetSymbolAddress(&p_xdelta, g_xdelta);
    cudaGetSymbolAddress(&p_xstate, g_xstate);
    cudaGetSymbolAddress(&p_W, g_W);
    cudaGetSymbolAddress(&p_qkv, g_qkv);
    cudaGetSymbolAddress(&p_attnres, g_attnres);
    cudaGetSymbolAddress(&p_ffn, g_ffn);
    cudaGetSymbolAddress(&p_normed, g_normed_h);
    cudaGetSymbolAddress(&p_normed2, g_normed2_h);
    cudaGetSymbolAddress(&p_oh, g_o_h);
    cudaGetSymbolAddress(&p_hh, g_h_h);
    cudaGetSymbolAddress(&p_wqkv, g_wqkv_h);
    cudaGetSymbolAddress(&p_wout, g_wout_h);
    cudaGetSymbolAddress(&p_w1, g_w1_h);
    cudaGetSymbolAddress(&p_w2, g_w2_h);

    float*  xdelta   = (float*)p_xdelta;
    float*  xstate   = (float*)p_xstate;
    float*  Wm       = (float*)p_W;
    float*  qkv      = (float*)p_qkv;
    float*  attnres  = (float*)p_attnres;
    float*  ffn      = (float*)p_ffn;
    __half* normed_h = (__half*)p_normed;
    __half* normed2_h= (__half*)p_normed2;
    __half* o_h      = (__half*)p_oh;
    __half* h_h      = (__half*)p_hh;
    __half* wqkv_h   = (__half*)p_wqkv;
    __half* wout_h   = (__half*)p_wout;
    __half* w1_h     = (__half*)p_w1;
    __half* w2_h     = (__half*)p_w2;

    cudaFuncSetAttribute(gemm_f16_kernel<0>,
                         cudaFuncAttributeMaxDynamicSharedMemorySize, GEMM_SMEM_H);
    cudaFuncSetAttribute(gemm_f16_kernel<1>,
                         cudaFuncAttributeMaxDynamicSharedMemorySize, GEMM_SMEM_H);
    cudaFuncSetAttribute(attn_tc_kernel,
                         cudaFuncAttributeMaxDynamicSharedMemorySize, ATT_SMEM);

    // 0) convert weights to fp16
    tohalf_kernel<<<1024, 256>>>((const float4*)in_proj_w, (__half2*)wqkv_h,
                                 3 * D_ * D_ / 4);
    tohalf_kernel<<<1024, 256>>>((const float4*)out_w, (__half2*)wout_h,
                                 D_ * D_ / 4);
    tohalf_kernel<<<1024, 256>>>((const float4*)w1, (__half2*)w1_h,
                                 4 * D_ * D_ / 4);
    tohalf_kernel<<<1024, 256>>>((const float4*)w2, (__half2*)w2_h,
                                 4 * D_ * D_ / 4);

    // 1) delta scan
    delta_scan_kernel<<<256, 256>>>(x, decay, xdelta, xstate);
    // 2) gates + sinkhorn
    gate_sinkhorn_kernel<<<1, 256>>>(xstate, gate_w, gate_b, phi, Wm);
    // 3) rmsnorm1 (fp16 output)
    rmsnorm_kernel<<<NTOK, 256>>>(xdelta, ln1_w, normed_h);
    // 4) qkv projection (fp16 mma, fp32 out)
    gemm_f16_kernel<0><<<dim3(3 * D_ / 128, NTOK / 128), 128, GEMM_SMEM_H>>>(
        normed_h, wqkv_h, in_proj_b, nullptr, qkv, NTOK, 3 * D_, D_);
    // 5) attention (tf32 flash), fp16 output
    attn_tc_kernel<<<dim3(S_ / 128, NH, B_), 256, ATT_SMEM>>>(qkv, o_h);
    // 6) out projection + residual(x_delta), fp32 out
    gemm_f16_kernel<0><<<dim3(D_ / 128, NTOK / 128), 128, GEMM_SMEM_H>>>(
        o_h, wout_h, out_b, xdelta, attnres, NTOK, D_, D_);
    // 7) rmsnorm2 (fp16 output)
    rmsnorm_kernel<<<NTOK, 256>>>(attnres, ln2_w, normed2_h);
    // 8) FFN1 + gelu (fp16 out)
    gemm_f16_kernel<1><<<dim3(4 * D_ / 128, NTOK / 128), 128, GEMM_SMEM_H>>>(
        normed2_h, w1_h, b1, nullptr, h_h, NTOK, 4 * D_, D_);
    // 9) FFN2 (fp32 out)
    gemm_f16_kernel<0><<<dim3(D_ / 128, NTOK / 128), 128, GEMM_SMEM_H>>>(
        h_h, w2_h, b2, nullptr, ffn, NTOK, D_, 4 * D_);
    // 10) final
    final_kernel<<<NTOK, 256>>>(attnres, ffn, xdelta, Wm, out);
}

// round 14
// speedup vs baseline: 4.4645x; 1.2089x over previous
#include <cuda_runtime.h>
#include <cuda_fp16.h>
#include <cuda_bf16.h>
#include <math.h>
#include <stdint.h>

// Problem constants
#define B_  2
#define S_  2048
#define D_  1024
#define NH  16
#define HD  64
#define NTOK (B_*S_)          // 4096

// ---------------- scratch (static __device__, no allocation) ----------------
__device__ float  g_xdelta[NTOK * D_];
__device__ float  g_xstate[B_ * D_];
__device__ float  g_W[B_ * 8 * 8];
__device__ float  g_attnres[NTOK * D_];
__device__ float  g_ffn[NTOK * D_];
// fp16 activations
__device__ __half g_qkv_h[NTOK * 3 * D_];
__device__ __half g_normed_h[NTOK * D_];
__device__ __half g_normed2_h[NTOK * D_];
__device__ __half g_o_h[NTOK * D_];
__device__ __half g_h_h[NTOK * 4 * D_];
// fp16 weight copies
__device__ __half g_wqkv_h[3 * D_ * D_];
__device__ __half g_wout_h[D_ * D_];
__device__ __half g_w1_h[4 * D_ * D_];
__device__ __half g_w2_h[4 * D_ * D_];

// ---------------- helpers ----------------------------------------------------
__device__ __forceinline__ void mma_f16(float* c, const unsigned int* a,
                                        const unsigned int* b) {
    asm volatile(
        "mma.sync.aligned.m16n8k16.row.col.f32.f16.f16.f32 "
        "{%0,%1,%2,%3}, {%4,%5,%6,%7}, {%8,%9}, {%0,%1,%2,%3};"
        : "+f"(c[0]), "+f"(c[1]), "+f"(c[2]), "+f"(c[3])
        : "r"(a[0]), "r"(a[1]), "r"(a[2]), "r"(a[3]), "r"(b[0]), "r"(b[1]));
}
__device__ __forceinline__ void cp_async16s(unsigned int saddr, const void* g) {
    asm volatile("cp.async.cg.shared.global [%0], [%1], 16;\n" :: "r"(saddr), "l"(g));
}

// ---------------- K0: convert weights to fp16 --------------------------------
__global__ void tohalf_kernel(const float4* __restrict__ src,
                              __half2* __restrict__ dst, int n4) {
    int i = blockIdx.x * blockDim.x + threadIdx.x;
    int stride = gridDim.x * blockDim.x;
    for (; i < n4; i += stride) {
        float4 v = src[i];
        dst[2 * i]     = __floats2half2_rn(v.x, v.y);
        dst[2 * i + 1] = __floats2half2_rn(v.z, v.w);
    }
}

// ---------------- K1: delta EMA scan (warp-parallel affine scan) -------------
__global__ void delta_scan_kernel(const float* __restrict__ x,
                                  const float* __restrict__ decay,
                                  float* __restrict__ xd,
                                  float* __restrict__ xstate) {
    int warp = (blockIdx.x * blockDim.x + threadIdx.x) >> 5;
    int lane = threadIdx.x & 31;
    if (warp >= B_ * D_) return;
    int b = warp >> 10;
    int d = warp & (D_ - 1);
    float beta = 1.f / (1.f + __expf(-decay[d]));
    float onem = 1.f - beta;

    const float* xp = x  + (size_t)b * S_ * D_ + d;
    float*       op = xd + (size_t)b * S_ * D_ + d;

    float carry = 0.f;
    float sum = 0.f;
    for (int t0 = 0; t0 < S_; t0 += 32) {
        float xt = xp[(size_t)(t0 + lane) * D_];
        float a = beta, bb = onem * xt;
        #pragma unroll
        for (int off = 1; off < 32; off <<= 1) {
            float pa = __shfl_up_sync(0xffffffffu, a, off);
            float pb = __shfl_up_sync(0xffffffffu, bb, off);
            if (lane >= off) { bb = a * pb + bb; a = a * pa; }
        }
        float s_incl = a * carry + bb;
        float s_prev = __shfl_up_sync(0xffffffffu, s_incl, 1);
        if (lane == 0) s_prev = carry;
        float out = xt - s_prev;
        op[(size_t)(t0 + lane) * D_] = out;
        sum += out;
        carry = __shfl_sync(0xffffffffu, s_incl, 31);
    }
    #pragma unroll
    for (int off = 16; off >= 1; off >>= 1)
        sum += __shfl_xor_sync(0xffffffffu, sum, off);
    if (lane == 0) xstate[warp] = sum * (1.f / (float)S_);
}

// ---------------- K2: gates + sinkhorn + W --------------------------------
__global__ void gate_sinkhorn_kernel(const float* __restrict__ xstate,
                                     const float* __restrict__ gate_w,
                                     const float* __restrict__ gate_b,
                                     const float* __restrict__ phi,
                                     float* __restrict__ W) {
    __shared__ float gbuf[B_][8];
    __shared__ float Km[64];
    __shared__ float tmp[64];
    int tid = threadIdx.x;
    int wid = tid >> 5, lane = tid & 31;

    for (int idx = wid; idx < 16; idx += 8) {
        int b = idx >> 3;
        int j = 16 + (idx & 7);
        float s = 0.f;
        for (int k = lane; k < D_; k += 32)
            s += xstate[b * D_ + k] * gate_w[j * D_ + k];
        #pragma unroll
        for (int off = 16; off >= 1; off >>= 1)
            s += __shfl_xor_sync(0xffffffffu, s, off);
        if (lane == 0)
            gbuf[b][idx & 7] = 1.f / (1.f + __expf(-(s + gate_b[j])));
    }
    if (tid < 64) Km[tid] = __expf(phi[tid]);
    __syncthreads();

    for (int it = 0; it < 15; it++) {
        if (tid < 64) {
            int m = tid >> 3;
            float rs = 0.f;
            #pragma unroll
            for (int n = 0; n < 8; n++) rs += Km[m * 8 + n];
            tmp[tid] = Km[tid] / rs;
        }
        __syncthreads();
        if (tid < 64) {
            int n = tid & 7;
            float cs = 0.f;
            #pragma unroll
            for (int m = 0; m < 8; m++) cs += tmp[m * 8 + n];
            Km[tid] = tmp[tid] / cs;
        }
        __syncthreads();
    }
    if (tid < 128) {
        int b = tid >> 6, r = tid & 63, n = r & 7;
        W[b * 64 + r] = Km[r] * gbuf[b][n];
    }
}

// ---------------- K3: RMSNorm (block per row, fp16 output) -------------------
__global__ void rmsnorm_kernel(const float* __restrict__ x,
                               const float* __restrict__ w,
                               __half* __restrict__ y) {
    int row = blockIdx.x;
    int tid = threadIdx.x;
    const float4* xr = (const float4*)(x + (size_t)row * D_);
    float4 v = xr[tid];
    float ss = v.x * v.x + v.y * v.y + v.z * v.z + v.w * v.w;
    __shared__ float red[8];
    #pragma unroll
    for (int off = 16; off >= 1; off >>= 1)
        ss += __shfl_xor_sync(0xffffffffu, ss, off);
    if ((tid & 31) == 0) red[tid >> 5] = ss;
    __syncthreads();
    if (tid < 8) {
        float t = red[tid];
        #pragma unroll
        for (int off = 4; off >= 1; off >>= 1)
            t += __shfl_xor_sync(0xffu, t, off);
        if (tid == 0) red[0] = t;
    }
    __syncthreads();
    float scale = rsqrtf(red[0] * (1.f / (float)D_) + 1e-6f);
    float4 wv = ((const float4*)w)[tid];
    __half2* yp = (__half2*)(y + (size_t)row * D_);
    yp[2 * tid]     = __floats2half2_rn(v.x * scale * wv.x, v.y * scale * wv.y);
    yp[2 * tid + 1] = __floats2half2_rn(v.z * scale * wv.z, v.w * scale * wv.w);
}

// ---------------- FP16 GEMM NT: C = A[M,K]*B[N,K]^T + bias (+res)(+gelu) -----
// Block 128x128, 4 warps each 64x64, mma m16n8k16 f16 (fp32 accum).
// EPI: 0 = fp32 out, bias (+res); 1 = fp16 out, bias+GELU; 2 = fp16 out, bias.
#define HP  40          // halves per smem row
#define HSTG 5120       // halves per stage (128 * 40)
#define GEMM_SMEM_H (4 * HSTG * 2)     // 40960 bytes

__device__ __forceinline__ void ld_chunk_f16(unsigned int abuf, unsigned int bbuf,
                                             const __half* __restrict__ A,
                                             const __half* __restrict__ Bm,
                                             int bm, int bn, int K, int k0, int tid) {
    #pragma unroll
    for (int i = 0; i < 4; i++) {
        int c = i * 128 + tid;
        int r = c >> 2, q = c & 3;
        cp_async16s(abuf + r * 80 + q * 16, A + (size_t)(bm + r) * K + k0 + q * 8);
        cp_async16s(bbuf + r * 80 + q * 16, Bm + (size_t)(bn + r) * K + k0 + q * 8);
    }
    asm volatile("cp.async.commit_group;\n" ::: "memory");
}

template <int EPI>
__global__ __launch_bounds__(128, 2)
void gemm_f16_kernel(const __half* __restrict__ A, const __half* __restrict__ Bm,
                     const float* __restrict__ bias, const float* __restrict__ res,
                     void* __restrict__ Cv, int M, int N, int K) {
    extern __shared__ __align__(16) char smemc[];
    unsigned int sbase = (unsigned int)__cvta_generic_to_shared(smemc);
    const __half* Sh = (const __half*)smemc;

    int bm = blockIdx.y * 128;
    int bn = blockIdx.x * 128;
    int tid = threadIdx.x;
    int warp = tid >> 5, lane = tid & 31;
    int wm = (warp & 1) * 64;
    int wn = (warp >> 1) * 64;
    int g = lane >> 2, t = lane & 3;

    float acc[4][8][4];
    #pragma unroll
    for (int mi = 0; mi < 4; mi++)
        #pragma unroll
        for (int ni = 0; ni < 8; ni++)
            #pragma unroll
            for (int r = 0; r < 4; r++) acc[mi][ni][r] = 0.f;

    int KT = K >> 5;
    ld_chunk_f16(sbase, sbase + 20480, A, Bm, bm, bn, K, 0, tid);

    int buf = 0;
    for (int kt = 0; kt < KT; kt++) {
        if (kt + 1 < KT) {
            int boff = (buf ^ 1) * 10240;
            ld_chunk_f16(sbase + boff, sbase + 20480 + boff,
                         A, Bm, bm, bn, K, (kt + 1) << 5, tid);
            asm volatile("cp.async.wait_group 1;\n" ::: "memory");
        } else {
            asm volatile("cp.async.wait_group 0;\n" ::: "memory");
        }
        __syncthreads();

        const __half* Ah = Sh + buf * HSTG;
        const __half* Bh = Sh + 2 * HSTG + buf * HSTG;
        #pragma unroll
        for (int s = 0; s < 2; s++) {
            unsigned int af[4][4], bf[8][2];
            #pragma unroll
            for (int mi = 0; mi < 4; mi++) {
                const __half* ap = Ah + (wm + mi * 16 + g) * HP + s * 16 + 2 * t;
                af[mi][0] = *(const unsigned int*)ap;
                af[mi][1] = *(const unsigned int*)(ap + 8 * HP);
                af[mi][2] = *(const unsigned int*)(ap + 8);
                af[mi][3] = *(const unsigned int*)(ap + 8 * HP + 8);
            }
            #pragma unroll
            for (int ni = 0; ni < 8; ni++) {
                const __half* bp = Bh + (wn + ni * 8 + g) * HP + s * 16 + 2 * t;
                bf[ni][0] = *(const unsigned int*)bp;
                bf[ni][1] = *(const unsigned int*)(bp + 8);
            }
            #pragma unroll
            for (int mi = 0; mi < 4; mi++)
                #pragma unroll
                for (int ni = 0; ni < 8; ni++)
                    mma_f16(acc[mi][ni], af[mi], bf[ni]);
        }
        __syncthreads();
        buf ^= 1;
    }

    // epilogue
    #pragma unroll
    for (int mi = 0; mi < 4; mi++) {
        #pragma unroll
        for (int ni = 0; ni < 8; ni++) {
            int col = bn + wn + ni * 8 + t * 2;
            #pragma unroll
            for (int half = 0; half < 2; half++) {
                int row = bm + wm + mi * 16 + g + half * 8;
                float vx = acc[mi][ni][half * 2 + 0] + bias[col + 0];
                float vy = acc[mi][ni][half * 2 + 1] + bias[col + 1];
                if (EPI == 1) {
                    vx = 0.5f * vx * (1.f + erff(vx * 0.7071067811865476f));
                    vy = 0.5f * vy * (1.f + erff(vy * 0.7071067811865476f));
                }
                if (EPI >= 1) {
                    __half2* C = (__half2*)((__half*)Cv + (size_t)row * N + col);
                    *C = __floats2half2_rn(vx, vy);
                } else {
                    if (res != nullptr) {
                        float2 r = *(const float2*)(res + (size_t)row * N + col);
                        vx += r.x; vy += r.y;
                    }
                    float2 v; v.x = vx; v.y = vy;
                    *(float2*)((float*)Cv + (size_t)row * N + col) = v;
                }
            }
        }
    }
}

// ---------------- K5: FP16 tensor-core flash causal attention ----------------
// q-tile 128, kv-tile 64, 8 warps x 16 q-rows, mma m16n8k16 f16, fp32 softmax.
// Tiles in half, pitch 72 halves (144 B): fragment bank map 4g+t conflict-free.
// V stored transposed [hd][kv] so the P@V B-fragment gets contiguous k-pairs.
#define AHP 72
#define ATT_SMEM ((128*AHP + 64*AHP + 64*AHP + 128*AHP) * 2)   // 55296 B

__global__ __launch_bounds__(256)
void attn_f16_kernel(const __half* __restrict__ qkv, __half* __restrict__ o) {
    extern __shared__ __align__(16) char smc[];
    __half* Qh = (__half*)smc;               // [128][AHP]
    __half* Kh = Qh + 128 * AHP;             // [64][AHP]
    __half* Vt = Kh + 64 * AHP;              // [64][AHP]  (V transposed: [hd][kv])
    __half* Ph = Vt + 64 * AHP;              // [128][AHP]

    int qt = blockIdx.x, h = blockIdx.y, b = blockIdx.z;
    int tid = threadIdx.x;
    int warp = tid >> 5, lane = tid & 31;
    int g = lane >> 2, t = lane & 3;
    int qr0 = qt * 128;
    const __half* base = qkv + (size_t)b * S_ * (3 * D_);

    // load Q tile (scaled by 1/8)
    {
        __half2 sc = __floats2half2_rn(0.125f, 0.125f);
        for (int i = tid; i < 128 * 32; i += 256) {
            int r = i >> 5, c2 = i & 31;
            __half2 v = *(const __half2*)(base + (size_t)(qr0 + r) * (3 * D_)
                                          + h * HD + 2 * c2);
            *(__half2*)(Qh + r * AHP + 2 * c2) = __hmul2(v, sc);
        }
    }

    int row0 = warp * 16 + g;
    int row1 = row0 + 8;

    float oacc[8][4];
    float m0 = -1e30f, m1 = -1e30f, l0 = 0.f, l1 = 0.f;
    #pragma unroll
    for (int ni = 0; ni < 8; ni++)
        #pragma unroll
        for (int r = 0; r < 4; r++) oacc[ni][r] = 0.f;

    int jt_max = 2 * qt + 1;
    for (int jt = 0; jt <= jt_max; jt++) {
        int jr0 = jt * 64;
        __syncthreads();
        // K tile [kv][hd]
        for (int i = tid; i < 64 * 32; i += 256) {
            int r = i >> 5, c2 = i & 31;
            *(__half2*)(Kh + r * AHP + 2 * c2) =
                *(const __half2*)(base + (size_t)(jr0 + r) * (3 * D_) + D_
                                  + h * HD + 2 * c2);
        }
        // V tile transposed -> Vt[hd][kv]
        for (int i = tid; i < 64 * 64; i += 256) {
            int r = i >> 6, c = i & 63;
            Vt[c * AHP + r] = base[(size_t)(jr0 + r) * (3 * D_) + 2 * D_
                                   + h * HD + c];
        }
        __syncthreads();

        if (jr0 > qr0 + warp * 16 + 15) continue;

        // S = Q @ K^T
        float sacc[8][4];
        #pragma unroll
        for (int ni = 0; ni < 8; ni++)
            #pragma unroll
            for (int r = 0; r < 4; r++) sacc[ni][r] = 0.f;

        #pragma unroll
        for (int s = 0; s < 4; s++) {
            unsigned int aq[4];
            const __half* qp0 = Qh + row0 * AHP + s * 16 + 2 * t;
            const __half* qp1 = Qh + row1 * AHP + s * 16 + 2 * t;
            aq[0] = *(const unsigned int*)qp0;
            aq[1] = *(const unsigned int*)qp1;
            aq[2] = *(const unsigned int*)(qp0 + 8);
            aq[3] = *(const unsigned int*)(qp1 + 8);
            #pragma unroll
            for (int ni = 0; ni < 8; ni++) {
                unsigned int bk[2];
                const __half* kp = Kh + (ni * 8 + g) * AHP + s * 16 + 2 * t;
                bk[0] = *(const unsigned int*)kp;
                bk[1] = *(const unsigned int*)(kp + 8);
                mma_f16(sacc[ni], aq, bk);
            }
        }

        // causal mask
        if (jr0 + 63 > qr0 + warp * 16) {
            int gr0 = qr0 + row0, gr1 = qr0 + row1;
            #pragma unroll
            for (int ni = 0; ni < 8; ni++) {
                int c0 = jr0 + ni * 8 + 2 * t;
                if (c0 > gr0)     sacc[ni][0] = -1e30f;
                if (c0 + 1 > gr0) sacc[ni][1] = -1e30f;
                if (c0 > gr1)     sacc[ni][2] = -1e30f;
                if (c0 + 1 > gr1) sacc[ni][3] = -1e30f;
            }
        }

        // online softmax (fp32)
        float mx0 = -1e30f, mx1 = -1e30f;
        #pragma unroll
        for (int ni = 0; ni < 8; ni++) {
            mx0 = fmaxf(mx0, fmaxf(sacc[ni][0], sacc[ni][1]));
            mx1 = fmaxf(mx1, fmaxf(sacc[ni][2], sacc[ni][3]));
        }
        #pragma unroll
        for (int off = 1; off < 4; off <<= 1) {
            mx0 = fmaxf(mx0, __shfl_xor_sync(0xffffffffu, mx0, off));
            mx1 = fmaxf(mx1, __shfl_xor_sync(0xffffffffu, mx1, off));
        }
        float nm0 = fmaxf(m0, mx0), nm1 = fmaxf(m1, mx1);
        float ps0 = 0.f, ps1 = 0.f;
        #pragma unroll
        for (int ni = 0; ni < 8; ni++) {
            sacc[ni][0] = __expf(sacc[ni][0] - nm0);
            sacc[ni][1] = __expf(sacc[ni][1] - nm0);
            sacc[ni][2] = __expf(sacc[ni][2] - nm1);
            sacc[ni][3] = __expf(sacc[ni][3] - nm1);
            ps0 += sacc[ni][0] + sacc[ni][1];
            ps1 += sacc[ni][2] + sacc[ni][3];
        }
        #pragma unroll
        for (int off = 1; off < 4; off <<= 1) {
            ps0 += __shfl_xor_sync(0xffffffffu, ps0, off);
            ps1 += __shfl_xor_sync(0xffffffffu, ps1, off);
        }
        float al0 = __expf(m0 - nm0), al1 = __expf(m1 - nm1);
        l0 = l0 * al0 + ps0;  m0 = nm0;
        l1 = l1 * al1 + ps1;  m1 = nm1;
        #pragma unroll
        for (int ni = 0; ni < 8; ni++) {
            oacc[ni][0] *= al0; oacc[ni][1] *= al0;
            oacc[ni][2] *= al1; oacc[ni][3] *= al1;
        }

        // P -> smem (fp16); warp-private rows
        #pragma unroll
        for (int ni = 0; ni < 8; ni++) {
            *(__half2*)(Ph + row0 * AHP + ni * 8 + 2 * t) =
                __floats2half2_rn(sacc[ni][0], sacc[ni][1]);
            *(__half2*)(Ph + row1 * AHP + ni * 8 + 2 * t) =
                __floats2half2_rn(sacc[ni][2], sacc[ni][3]);
        }
        __syncwarp();

        // O += P @ V  (V transposed in smem)
        #pragma unroll
        for (int s = 0; s < 4; s++) {
            unsigned int ap[4];
            const __half* pp0 = Ph + row0 * AHP + s * 16 + 2 * t;
            const __half* pp1 = Ph + row1 * AHP + s * 16 + 2 * t;
            ap[0] = *(const unsigned int*)pp0;
            ap[1] = *(const unsigned int*)pp1;
            ap[2] = *(const unsigned int*)(pp0 + 8);
            ap[3] = *(const unsigned int*)(pp1 + 8);
            #pragma unroll
            for (int ni = 0; ni < 8; ni++) {
                unsigned int bv[2];
                const __half* vp = Vt + (ni * 8 + g) * AHP + s * 16 + 2 * t;
                bv[0] = *(const unsigned int*)vp;
                bv[1] = *(const unsigned int*)(vp + 8);
                mma_f16(oacc[ni], ap, bv);
            }
        }
        __syncwarp();
    }

    // O feeds the fp16 out-proj GEMM -> write half2
    float inv0 = 1.f / l0, inv1 = 1.f / l1;
    size_t gr0 = (size_t)(b * S_ + qr0 + row0) * D_ + h * HD;
    size_t gr1 = (size_t)(b * S_ + qr0 + row1) * D_ + h * HD;
    #pragma unroll
    for (int ni = 0; ni < 8; ni++) {
        int c = ni * 8 + 2 * t;
        *(__half2*)(o + gr0 + c) = __floats2half2_rn(oacc[ni][0] * inv0,
                                                     oacc[ni][1] * inv0);
        *(__half2*)(o + gr1 + c) = __floats2half2_rn(oacc[ni][2] * inv1,
                                                     oacc[ni][3] * inv1);
    }
}

// ---------------- K10: final sum + mhc mix ----------------------------------
__global__ void final_kernel(const float* __restrict__ attnres,
                             const float* __restrict__ ffn,
                             const float* __restrict__ xd,
                             const float* __restrict__ W,
                             float* __restrict__ out) {
    __shared__ float row[D_];
    __shared__ float Ws[64];
    int r = blockIdx.x;
    int b = r >> 11;
    int tid = threadIdx.x;
    ((float4*)row)[tid] = ((const float4*)(xd + (size_t)r * D_))[tid];
    if (tid < 64) Ws[tid] = W[b * 64 + tid];
    __syncthreads();

    int c0 = tid * 4;
    int m = c0 >> 7;
    int dp = c0 & 127;
    float mh0 = 0.f, mh1 = 0.f, mh2 = 0.f, mh3 = 0.f;
    #pragma unroll
    for (int n = 0; n < 8; n++) {
        float w = Ws[m * 8 + n];
        const float* rp = row + n * 128 + dp;
        mh0 += w * rp[0]; mh1 += w * rp[1]; mh2 += w * rp[2]; mh3 += w * rp[3];
    }
    float4 a = ((const float4*)(attnres + (size_t)r * D_))[tid];
    float4 f = ((const float4*)(ffn + (size_t)r * D_))[tid];
    float4 ov;
    ov.x = a.x + f.x + mh0;
    ov.y = a.y + f.y + mh1;
    ov.z = a.z + f.z + mh2;
    ov.w = a.w + f.w + mh3;
    ((float4*)(out + (size_t)r * D_))[tid] = ov;
}

// ---------------- launch ----------------------------------------------------
extern "C" void kernel_launch(void* const* d_in, const int* in_sizes, int n_in,
                              void* d_out, int out_size) {
    const float* x        = (const float*)d_in[0];
    const float* decay    = (const float*)d_in[3];
    const float* gate_w   = (const float*)d_in[4];
    const float* gate_b   = (const float*)d_in[5];
    const float* phi      = (const float*)d_in[6];
    const float* ln1_w    = (const float*)d_in[7];
    const float* ln2_w    = (const float*)d_in[8];
    const float* w1       = (const float*)d_in[9];
    const float* b1       = (const float*)d_in[10];
    const float* w2       = (const float*)d_in[11];
    const float* b2       = (const float*)d_in[12];
    const float* in_proj_w= (const float*)d_in[13];
    const float* in_proj_b= (const float*)d_in[14];
    const float* out_w    = (const float*)d_in[15];
    const float* out_b    = (const float*)d_in[16];
    float* out = (float*)d_out;

    void *p_xdelta, *p_xstate, *p_W, *p_qkvh, *p_attnres, *p_ffn,
         *p_normed, *p_normed2, *p_oh, *p_hh, *p_wqkv, *p_wout, *p_w1, *p_w2;
    cudaGetSymbolAddress(&p_xdelta, g_xdelta);
    cudaGetSymbolAddress(&p_xstate, g_xstate);
    cudaGetSymbolAddress(&p_W, g_W);
    cudaGetSymbolAddress(&p_qkvh, g_qkv_h);
    cudaGetSymbolAddress(&p_attnres, g_attnres);
    cudaGetSymbolAddress(&p_ffn, g_ffn);
    cudaGetSymbolAddress(&p_normed, g_normed_h);
    cudaGetSymbolAddress(&p_normed2, g_normed2_h);
    cudaGetSymbolAddress(&p_oh, g_o_h);
    cudaGetSymbolAddress(&p_hh, g_h_h);
    cudaGetSymbolAddress(&p_wqkv, g_wqkv_h);
    cudaGetSymbolAddress(&p_wout, g_wout_h);
    cudaGetSymbolAddress(&p_w1, g_w1_h);
    cudaGetSymbolAddress(&p_w2, g_w2_h);

    float*  xdelta   = (float*)p_xdelta;
    float*  xstate   = (float*)p_xstate;
    float*  Wm       = (float*)p_W;
    __half* qkv_h    = (__half*)p_qkvh;
    float*  attnres  = (float*)p_attnres;
    float*  ffn      = (float*)p_ffn;
    __half* normed_h = (__half*)p_normed;
    __half* normed2_h= (__half*)p_normed2;
    __half* o_h      = (__half*)p_oh;
    __half* h_h      = (__half*)p_hh;
    __half* wqkv_h   = (__half*)p_wqkv;
    __half* wout_h   = (__half*)p_wout;
    __half* w1_h     = (__half*)p_w1;
    __half* w2_h     = (__half*)p_w2;

    cudaFuncSetAttribute(gemm_f16_kernel<0>,
                         cudaFuncAttributeMaxDynamicSharedMemorySize, GEMM_SMEM_H);
    cudaFuncSetAttribute(gemm_f16_kernel<1>,
                         cudaFuncAttributeMaxDynamicSharedMemorySize, GEMM_SMEM_H);
    cudaFuncSetAttribute(gemm_f16_kernel<2>,
                         cudaFuncAttributeMaxDynamicSharedMemorySize, GEMM_SMEM_H);
    cudaFuncSetAttribute(attn_f16_kernel,
                         cudaFuncAttributeMaxDynamicSharedMemorySize, ATT_SMEM);

    // 0) convert weights to fp16
    tohalf_kernel<<<1024, 256>>>((const float4*)in_proj_w, (__half2*)wqkv_h,
                                 3 * D_ * D_ / 4);
    tohalf_kernel<<<1024, 256>>>((const float4*)out_w, (__half2*)wout_h,
                                 D_ * D_ / 4);
    tohalf_kernel<<<1024, 256>>>((const float4*)w1, (__half2*)w1_h,
                                 4 * D_ * D_ / 4);
    tohalf_kernel<<<1024, 256>>>((const float4*)w2, (__half2*)w2_h,
                                 4 * D_ * D_ / 4);

    // 1) delta scan
    delta_scan_kernel<<<256, 256>>>(x, decay, xdelta, xstate);
    // 2) gates + sinkhorn
    gate_sinkhorn_kernel<<<1, 256>>>(xstate, gate_w, gate_b, phi, Wm);
    // 3) rmsnorm1 (fp16 output)
    rmsnorm_kernel<<<NTOK, 256>>>(xdelta, ln1_w, normed_h);
    // 4) qkv projection (fp16 mma, fp16 out)
    gemm_f16_kernel<2><<<dim3(3 * D_ / 128, NTOK / 128), 128, GEMM_SMEM_H>>>(
        normed_h, wqkv_h, in_proj_b, nullptr, qkv_h, NTOK, 3 * D_, D_);
    // 5) attention (fp16 flash), fp16 output
    attn_f16_kernel<<<dim3(S_ / 128, NH, B_), 256, ATT_SMEM>>>(qkv_h, o_h);
    // 6) out projection + residual(x_delta), fp32 out
    gemm_f16_kernel<0><<<dim3(D_ / 128, NTOK / 128), 128, GEMM_SMEM_H>>>(
        o_h, wout_h, out_b, xdelta, attnres, NTOK, D_, D_);
    // 7) rmsnorm2 (fp16 output)
    rmsnorm_kernel<<<NTOK, 256>>>(attnres, ln2_w, normed2_h);
    // 8) FFN1 + gelu (fp16 out)
    gemm_f16_kernel<1><<<dim3(4 * D_ / 128, NTOK / 128), 128, GEMM_SMEM_H>>>(
        normed2_h, w1_h, b1, nullptr, h_h, NTOK, 4 * D_, D_);
    // 9) FFN2 (fp32 out)
    gemm_f16_kernel<0><<<dim3(D_ / 128, NTOK / 128), 128, GEMM_SMEM_H>>>(
        h_h, w2_h, b2, nullptr, ffn, NTOK, D_, 4 * D_);
    // 10) final
    final_kernel<<<NTOK, 256>>>(attnres, ffn, xdelta, Wm, out);
}

// round 15
// speedup vs baseline: 5.3626x; 1.2012x over previous
#include <cuda_runtime.h>
#include <cuda_fp16.h>
#include <cuda_bf16.h>
#include <math.h>
#include <stdint.h>

// Problem constants
#define B_  2
#define S_  2048
#define D_  1024
#define NH  16
#define HD  64
#define NTOK (B_*S_)          // 4096

// ---------------- scratch (static __device__, no allocation) ----------------
__device__ float  g_xdelta[NTOK * D_];
__device__ float  g_xstate[B_ * D_];
__device__ float  g_W[B_ * 8 * 8];
__device__ float  g_attnres[NTOK * D_];
__device__ float  g_ffn[NTOK * D_];
// fp16 activations
__device__ __half g_qkv_h[NTOK * 3 * D_];
__device__ __half g_normed_h[NTOK * D_];
__device__ __half g_normed2_h[NTOK * D_];
__device__ __half g_o_h[NTOK * D_];
__device__ __half g_h_h[NTOK * 4 * D_];
// fp16 weight copies
__device__ __half g_wqkv_h[3 * D_ * D_];
__device__ __half g_wout_h[D_ * D_];
__device__ __half g_w1_h[4 * D_ * D_];
__device__ __half g_w2_h[4 * D_ * D_];

// ---------------- helpers ----------------------------------------------------
__device__ __forceinline__ void mma_f16(float* c, const unsigned int* a,
                                        const unsigned int* b) {
    asm volatile(
        "mma.sync.aligned.m16n8k16.row.col.f32.f16.f16.f32 "
        "{%0,%1,%2,%3}, {%4,%5,%6,%7}, {%8,%9}, {%0,%1,%2,%3};"
        : "+f"(c[0]), "+f"(c[1]), "+f"(c[2]), "+f"(c[3])
        : "r"(a[0]), "r"(a[1]), "r"(a[2]), "r"(a[3]), "r"(b[0]), "r"(b[1]));
}
__device__ __forceinline__ void ldsm_x4(unsigned int& r0, unsigned int& r1,
                                        unsigned int& r2, unsigned int& r3,
                                        unsigned int addr) {
    asm volatile("ldmatrix.sync.aligned.m8n8.x4.shared.b16 {%0,%1,%2,%3}, [%4];"
                 : "=r"(r0), "=r"(r1), "=r"(r2), "=r"(r3) : "r"(addr));
}
__device__ __forceinline__ void ldsm_x4_t(unsigned int& r0, unsigned int& r1,
                                          unsigned int& r2, unsigned int& r3,
                                          unsigned int addr) {
    asm volatile("ldmatrix.sync.aligned.m8n8.x4.trans.shared.b16 {%0,%1,%2,%3}, [%4];"
                 : "=r"(r0), "=r"(r1), "=r"(r2), "=r"(r3) : "r"(addr));
}
__device__ __forceinline__ void cp_async16s(unsigned int saddr, const void* g) {
    asm volatile("cp.async.cg.shared.global [%0], [%1], 16;\n" :: "r"(saddr), "l"(g));
}

// ---------------- K0: convert weights to fp16 --------------------------------
__global__ void tohalf_kernel(const float4* __restrict__ src,
                              __half2* __restrict__ dst, int n4) {
    int i = blockIdx.x * blockDim.x + threadIdx.x;
    int stride = gridDim.x * blockDim.x;
    for (; i < n4; i += stride) {
        float4 v = src[i];
        dst[2 * i]     = __floats2half2_rn(v.x, v.y);
        dst[2 * i + 1] = __floats2half2_rn(v.z, v.w);
    }
}

// ---------------- K1: delta EMA scan (warp-parallel affine scan) -------------
__global__ void delta_scan_kernel(const float* __restrict__ x,
                                  const float* __restrict__ decay,
                                  float* __restrict__ xd,
                                  float* __restrict__ xstate) {
    int warp = (blockIdx.x * blockDim.x + threadIdx.x) >> 5;
    int lane = threadIdx.x & 31;
    if (warp >= B_ * D_) return;
    int b = warp >> 10;
    int d = warp & (D_ - 1);
    float beta = 1.f / (1.f + __expf(-decay[d]));
    float onem = 1.f - beta;

    const float* xp = x  + (size_t)b * S_ * D_ + d;
    float*       op = xd + (size_t)b * S_ * D_ + d;

    float carry = 0.f;
    float sum = 0.f;
    for (int t0 = 0; t0 < S_; t0 += 32) {
        float xt = xp[(size_t)(t0 + lane) * D_];
        float a = beta, bb = onem * xt;
        #pragma unroll
        for (int off = 1; off < 32; off <<= 1) {
            float pa = __shfl_up_sync(0xffffffffu, a, off);
            float pb = __shfl_up_sync(0xffffffffu, bb, off);
            if (lane >= off) { bb = a * pb + bb; a = a * pa; }
        }
        float s_incl = a * carry + bb;
        float s_prev = __shfl_up_sync(0xffffffffu, s_incl, 1);
        if (lane == 0) s_prev = carry;
        float out = xt - s_prev;
        op[(size_t)(t0 + lane) * D_] = out;
        sum += out;
        carry = __shfl_sync(0xffffffffu, s_incl, 31);
    }
    #pragma unroll
    for (int off = 16; off >= 1; off >>= 1)
        sum += __shfl_xor_sync(0xffffffffu, sum, off);
    if (lane == 0) xstate[warp] = sum * (1.f / (float)S_);
}

// ---------------- K2: gates + sinkhorn + W --------------------------------
__global__ void gate_sinkhorn_kernel(const float* __restrict__ xstate,
                                     const float* __restrict__ gate_w,
                                     const float* __restrict__ gate_b,
                                     const float* __restrict__ phi,
                                     float* __restrict__ W) {
    __shared__ float gbuf[B_][8];
    __shared__ float Km[64];
    __shared__ float tmp[64];
    int tid = threadIdx.x;
    int wid = tid >> 5, lane = tid & 31;

    for (int idx = wid; idx < 16; idx += 8) {
        int b = idx >> 3;
        int j = 16 + (idx & 7);
        float s = 0.f;
        for (int k = lane; k < D_; k += 32)
            s += xstate[b * D_ + k] * gate_w[j * D_ + k];
        #pragma unroll
        for (int off = 16; off >= 1; off >>= 1)
            s += __shfl_xor_sync(0xffffffffu, s, off);
        if (lane == 0)
            gbuf[b][idx & 7] = 1.f / (1.f + __expf(-(s + gate_b[j])));
    }
    if (tid < 64) Km[tid] = __expf(phi[tid]);
    __syncthreads();

    for (int it = 0; it < 15; it++) {
        if (tid < 64) {
            int m = tid >> 3;
            float rs = 0.f;
            #pragma unroll
            for (int n = 0; n < 8; n++) rs += Km[m * 8 + n];
            tmp[tid] = Km[tid] / rs;
        }
        __syncthreads();
        if (tid < 64) {
            int n = tid & 7;
            float cs = 0.f;
            #pragma unroll
            for (int m = 0; m < 8; m++) cs += tmp[m * 8 + n];
            Km[tid] = tmp[tid] / cs;
        }
        __syncthreads();
    }
    if (tid < 128) {
        int b = tid >> 6, r = tid & 63, n = r & 7;
        W[b * 64 + r] = Km[r] * gbuf[b][n];
    }
}

// ---------------- K3: RMSNorm (block per row, fp16 output) -------------------
__global__ void rmsnorm_kernel(const float* __restrict__ x,
                               const float* __restrict__ w,
                               __half* __restrict__ y) {
    int row = blockIdx.x;
    int tid = threadIdx.x;
    const float4* xr = (const float4*)(x + (size_t)row * D_);
    float4 v = xr[tid];
    float ss = v.x * v.x + v.y * v.y + v.z * v.z + v.w * v.w;
    __shared__ float red[8];
    #pragma unroll
    for (int off = 16; off >= 1; off >>= 1)
        ss += __shfl_xor_sync(0xffffffffu, ss, off);
    if ((tid & 31) == 0) red[tid >> 5] = ss;
    __syncthreads();
    if (tid < 8) {
        float t = red[tid];
        #pragma unroll
        for (int off = 4; off >= 1; off >>= 1)
            t += __shfl_xor_sync(0xffu, t, off);
        if (tid == 0) red[0] = t;
    }
    __syncthreads();
    float scale = rsqrtf(red[0] * (1.f / (float)D_) + 1e-6f);
    float4 wv = ((const float4*)w)[tid];
    __half2* yp = (__half2*)(y + (size_t)row * D_);
    yp[2 * tid]     = __floats2half2_rn(v.x * scale * wv.x, v.y * scale * wv.y);
    yp[2 * tid + 1] = __floats2half2_rn(v.z * scale * wv.z, v.w * scale * wv.w);
}

// ---------------- FP16 GEMM NT: C = A[M,K]*B[N,K]^T + bias (+res)(+gelu) -----
// Block 128x128, 4 warps each 64x64, mma m16n8k16 f16, ldmatrix fragment loads.
// EPI: 0 = fp32 out, bias (+res); 1 = fp16 out, bias+GELU; 2 = fp16 out, bias.
#define HP  40          // halves per smem row (80 B pitch)
#define HSTG 5120       // halves per stage (128 * 40)
#define GEMM_SMEM_H (4 * HSTG * 2)     // 40960 bytes

__device__ __forceinline__ void ld_chunk_f16(unsigned int abuf, unsigned int bbuf,
                                             const __half* __restrict__ A,
                                             const __half* __restrict__ Bm,
                                             int bm, int bn, int K, int k0, int tid) {
    #pragma unroll
    for (int i = 0; i < 4; i++) {
        int c = i * 128 + tid;
        int r = c >> 2, q = c & 3;
        cp_async16s(abuf + r * 80 + q * 16, A + (size_t)(bm + r) * K + k0 + q * 8);
        cp_async16s(bbuf + r * 80 + q * 16, Bm + (size_t)(bn + r) * K + k0 + q * 8);
    }
    asm volatile("cp.async.commit_group;\n" ::: "memory");
}

template <int EPI>
__global__ __launch_bounds__(128, 2)
void gemm_f16_kernel(const __half* __restrict__ A, const __half* __restrict__ Bm,
                     const float* __restrict__ bias, const float* __restrict__ res,
                     void* __restrict__ Cv, int M, int N, int K) {
    extern __shared__ __align__(16) char smemc[];
    unsigned int sbase = (unsigned int)__cvta_generic_to_shared(smemc);

    int bm = blockIdx.y * 128;
    int bn = blockIdx.x * 128;
    int tid = threadIdx.x;
    int warp = tid >> 5, lane = tid & 31;
    int wm = (warp & 1) * 64;
    int wn = (warp >> 1) * 64;
    int g = lane >> 2, t = lane & 3;

    // ldmatrix per-lane address offsets (bytes)
    int arow_off = (wm + (lane & 15)) * 80 + ((lane >> 4) * 16);
    int brow_off = (wn + (lane & 7) + ((lane >> 4) & 1) * 8) * 80
                   + (((lane >> 3) & 1) * 16);

    float acc[4][8][4];
    #pragma unroll
    for (int mi = 0; mi < 4; mi++)
        #pragma unroll
        for (int ni = 0; ni < 8; ni++)
            #pragma unroll
            for (int r = 0; r < 4; r++) acc[mi][ni][r] = 0.f;

    int KT = K >> 5;
    ld_chunk_f16(sbase, sbase + 20480, A, Bm, bm, bn, K, 0, tid);

    int buf = 0;
    for (int kt = 0; kt < KT; kt++) {
        if (kt + 1 < KT) {
            int boff = (buf ^ 1) * 10240;
            ld_chunk_f16(sbase + boff, sbase + 20480 + boff,
                         A, Bm, bm, bn, K, (kt + 1) << 5, tid);
            asm volatile("cp.async.wait_group 1;\n" ::: "memory");
        } else {
            asm volatile("cp.async.wait_group 0;\n" ::: "memory");
        }
        __syncthreads();

        unsigned int abase = sbase + buf * 10240;
        unsigned int bbase = sbase + 20480 + buf * 10240;
        #pragma unroll
        for (int s = 0; s < 2; s++) {
            unsigned int af[4][4], bf[8][2];
            #pragma unroll
            for (int mi = 0; mi < 4; mi++)
                ldsm_x4(af[mi][0], af[mi][1], af[mi][2], af[mi][3],
                        abase + arow_off + mi * 1280 + s * 32);
            #pragma unroll
            for (int p = 0; p < 4; p++)
                ldsm_x4(bf[2 * p][0], bf[2 * p][1], bf[2 * p + 1][0], bf[2 * p + 1][1],
                        bbase + brow_off + p * 1280 + s * 32);
            #pragma unroll
            for (int mi = 0; mi < 4; mi++)
                #pragma unroll
                for (int ni = 0; ni < 8; ni++)
                    mma_f16(acc[mi][ni], af[mi], bf[ni]);
        }
        __syncthreads();
        buf ^= 1;
    }

    // epilogue
    #pragma unroll
    for (int mi = 0; mi < 4; mi++) {
        #pragma unroll
        for (int ni = 0; ni < 8; ni++) {
            int col = bn + wn + ni * 8 + t * 2;
            #pragma unroll
            for (int half = 0; half < 2; half++) {
                int row = bm + wm + mi * 16 + g + half * 8;
                float vx = acc[mi][ni][half * 2 + 0] + bias[col + 0];
                float vy = acc[mi][ni][half * 2 + 1] + bias[col + 1];
                if (EPI == 1) {
                    vx = 0.5f * vx * (1.f + erff(vx * 0.7071067811865476f));
                    vy = 0.5f * vy * (1.f + erff(vy * 0.7071067811865476f));
                }
                if (EPI >= 1) {
                    __half2* C = (__half2*)((__half*)Cv + (size_t)row * N + col);
                    *C = __floats2half2_rn(vx, vy);
                } else {
                    if (res != nullptr) {
                        float2 r = *(const float2*)(res + (size_t)row * N + col);
                        vx += r.x; vy += r.y;
                    }
                    float2 v; v.x = vx; v.y = vy;
                    *(float2*)((float*)Cv + (size_t)row * N + col) = v;
                }
            }
        }
    }
}

// ---------------- K5: FP16 tensor-core flash causal attention ----------------
// q-tile 128, kv-tile 64, 8 warps x 16 q-rows, mma m16n8k16 f16, fp32 softmax.
// ldmatrix fragment loads; V kept row-major [kv][hd], B-fragments via
// ldmatrix.trans (no transpose scatter). Pitch 72 halves (144 B), conflict-free.
#define AHP 72
#define ATT_SMEM ((128*AHP + 64*AHP + 64*AHP + 128*AHP) * 2)   // 55296 B

__global__ __launch_bounds__(256)
void attn_f16_kernel(const __half* __restrict__ qkv, __half* __restrict__ o) {
    extern __shared__ __align__(16) char smc[];
    __half* Qh = (__half*)smc;               // [128][AHP]
    __half* Kh = Qh + 128 * AHP;             // [64][AHP]
    __half* Vh = Kh + 64 * AHP;              // [64][AHP]  row-major [kv][hd]
    __half* Ph = Vh + 64 * AHP;              // [128][AHP]
    unsigned int sb = (unsigned int)__cvta_generic_to_shared(smc);
    const unsigned int qb = sb;
    const unsigned int kb = sb + 128 * AHP * 2;   // 18432
    const unsigned int vb = kb + 64 * AHP * 2;    // +9216
    const unsigned int pb = vb + 64 * AHP * 2;    // +9216

    int qt = blockIdx.x, h = blockIdx.y, b = blockIdx.z;
    int tid = threadIdx.x;
    int warp = tid >> 5, lane = tid & 31;
    int g = lane >> 2, t = lane & 3;
    int qr0 = qt * 128;
    const __half* base = qkv + (size_t)b * S_ * (3 * D_);

    // ldmatrix per-lane offsets (bytes)
    int qrow_off = (warp * 16 + (lane & 15)) * 144 + ((lane >> 4) * 16);
    int krow_off = ((lane & 7) + ((lane >> 4) & 1) * 8) * 144
                   + (((lane >> 3) & 1) * 16);
    int vrow_off = ((lane & 7) + ((lane >> 3) & 1) * 8) * 144
                   + ((lane >> 4) * 16);

    // load Q tile (scaled by 1/8)
    {
        __half2 sc = __floats2half2_rn(0.125f, 0.125f);
        for (int i = tid; i < 128 * 32; i += 256) {
            int r = i >> 5, c2 = i & 31;
            __half2 v = *(const __half2*)(base + (size_t)(qr0 + r) * (3 * D_)
                                          + h * HD + 2 * c2);
            *(__half2*)(Qh + r * AHP + 2 * c2) = __hmul2(v, sc);
        }
    }

    int row0 = warp * 16 + g;
    int row1 = row0 + 8;

    float oacc[8][4];
    float m0 = -1e30f, m1 = -1e30f, l0 = 0.f, l1 = 0.f;
    #pragma unroll
    for (int ni = 0; ni < 8; ni++)
        #pragma unroll
        for (int r = 0; r < 4; r++) oacc[ni][r] = 0.f;

    int jt_max = 2 * qt + 1;
    for (int jt = 0; jt <= jt_max; jt++) {
        int jr0 = jt * 64;
        __syncthreads();
        // K tile [kv][hd], V tile [kv][hd]
        for (int i = tid; i < 64 * 32; i += 256) {
            int r = i >> 5, c2 = i & 31;
            *(__half2*)(Kh + r * AHP + 2 * c2) =
                *(const __half2*)(base + (size_t)(jr0 + r) * (3 * D_) + D_
                                  + h * HD + 2 * c2);
            *(__half2*)(Vh + r * AHP + 2 * c2) =
                *(const __half2*)(base + (size_t)(jr0 + r) * (3 * D_) + 2 * D_
                                  + h * HD + 2 * c2);
        }
        __syncthreads();

        if (jr0 > qr0 + warp * 16 + 15) continue;

        // S = Q @ K^T
        float sacc[8][4];
        #pragma unroll
        for (int ni = 0; ni < 8; ni++)
            #pragma unroll
            for (int r = 0; r < 4; r++) sacc[ni][r] = 0.f;

        #pragma unroll
        for (int s = 0; s < 4; s++) {
            unsigned int aq[4], bk[8][2];
            ldsm_x4(aq[0], aq[1], aq[2], aq[3], qb + qrow_off + s * 32);
            #pragma unroll
            for (int p = 0; p < 4; p++)
                ldsm_x4(bk[2 * p][0], bk[2 * p][1], bk[2 * p + 1][0], bk[2 * p + 1][1],
                        kb + krow_off + p * 2304 + s * 32);
            #pragma unroll
            for (int ni = 0; ni < 8; ni++)
                mma_f16(sacc[ni], aq, bk[ni]);
        }

        // causal mask
        if (jr0 + 63 > qr0 + warp * 16) {
            int gr0 = qr0 + row0, gr1 = qr0 + row1;
            #pragma unroll
            for (int ni = 0; ni < 8; ni++) {
                int c0 = jr0 + ni * 8 + 2 * t;
                if (c0 > gr0)     sacc[ni][0] = -1e30f;
                if (c0 + 1 > gr0) sacc[ni][1] = -1e30f;
                if (c0 > gr1)     sacc[ni][2] = -1e30f;
                if (c0 + 1 > gr1) sacc[ni][3] = -1e30f;
            }
        }

        // online softmax (fp32)
        float mx0 = -1e30f, mx1 = -1e30f;
        #pragma unroll
        for (int ni = 0; ni < 8; ni++) {
            mx0 = fmaxf(mx0, fmaxf(sacc[ni][0], sacc[ni][1]));
            mx1 = fmaxf(mx1, fmaxf(sacc[ni][2], sacc[ni][3]));
        }
        #pragma unroll
        for (int off = 1; off < 4; off <<= 1) {
            mx0 = fmaxf(mx0, __shfl_xor_sync(0xffffffffu, mx0, off));
            mx1 = fmaxf(mx1, __shfl_xor_sync(0xffffffffu, mx1, off));
        }
        float nm0 = fmaxf(m0, mx0), nm1 = fmaxf(m1, mx1);
        float ps0 = 0.f, ps1 = 0.f;
        #pragma unroll
        for (int ni = 0; ni < 8; ni++) {
            sacc[ni][0] = __expf(sacc[ni][0] - nm0);
            sacc[ni][1] = __expf(sacc[ni][1] - nm0);
            sacc[ni][2] = __expf(sacc[ni][2] - nm1);
            sacc[ni][3] = __expf(sacc[ni][3] - nm1);
            ps0 += sacc[ni][0] + sacc[ni][1];
            ps1 += sacc[ni][2] + sacc[ni][3];
        }
        #pragma unroll
        for (int off = 1; off < 4; off <<= 1) {
            ps0 += __shfl_xor_sync(0xffffffffu, ps0, off);
            ps1 += __shfl_xor_sync(0xffffffffu, ps1, off);
        }
        float al0 = __expf(m0 - nm0), al1 = __expf(m1 - nm1);
        l0 = l0 * al0 + ps0;  m0 = nm0;
        l1 = l1 * al1 + ps1;  m1 = nm1;
        #pragma unroll
        for (int ni = 0; ni < 8; ni++) {
            oacc[ni][0] *= al0; oacc[ni][1] *= al0;
            oacc[ni][2] *= al1; oacc[ni][3] *= al1;
        }

        // P -> smem (fp16); warp-private rows
        #pragma unroll
        for (int ni = 0; ni < 8; ni++) {
            *(__half2*)(Ph + row0 * AHP + ni * 8 + 2 * t) =
                __floats2half2_rn(sacc[ni][0], sacc[ni][1]);
            *(__half2*)(Ph + row1 * AHP + ni * 8 + 2 * t) =
                __floats2half2_rn(sacc[ni][2], sacc[ni][3]);
        }
        __syncwarp();

        // O += P @ V  (V row-major, fragments via ldmatrix.trans)
        #pragma unroll
        for (int s = 0; s < 4; s++) {
            unsigned int ap[4], bv[8][2];
            ldsm_x4(ap[0], ap[1], ap[2], ap[3], pb + qrow_off + s * 32);
            #pragma unroll
            for (int p = 0; p < 4; p++)
                ldsm_x4_t(bv[2 * p][0], bv[2 * p][1], bv[2 * p + 1][0], bv[2 * p + 1][1],
                          vb + vrow_off + s * 2304 + p * 32);
            #pragma unroll
            for (int ni = 0; ni < 8; ni++)
                mma_f16(oacc[ni], ap, bv[ni]);
        }
        __syncwarp();
    }

    // O feeds the fp16 out-proj GEMM -> write half2
    float inv0 = 1.f / l0, inv1 = 1.f / l1;
    size_t gr0 = (size_t)(b * S_ + qr0 + row0) * D_ + h * HD;
    size_t gr1 = (size_t)(b * S_ + qr0 + row1) * D_ + h * HD;
    #pragma unroll
    for (int ni = 0; ni < 8; ni++) {
        int c = ni * 8 + 2 * t;
        *(__half2*)(o + gr0 + c) = __floats2half2_rn(oacc[ni][0] * inv0,
                                                     oacc[ni][1] * inv0);
        *(__half2*)(o + gr1 + c) = __floats2half2_rn(oacc[ni][2] * inv1,
                                                     oacc[ni][3] * inv1);
    }
}

// ---------------- K10: final sum + mhc mix ----------------------------------
__global__ void final_kernel(const float* __restrict__ attnres,
                             const float* __restrict__ ffn,
                             const float* __restrict__ xd,
                             const float* __restrict__ W,
                             float* __restrict__ out) {
    __shared__ float row[D_];
    __shared__ float Ws[64];
    int r = blockIdx.x;
    int b = r >> 11;
    int tid = threadIdx.x;
    ((float4*)row)[tid] = ((const float4*)(xd + (size_t)r * D_))[tid];
    if (tid < 64) Ws[tid] = W[b * 64 + tid];
    __syncthreads();

    int c0 = tid * 4;
    int m = c0 >> 7;
    int dp = c0 & 127;
    float mh0 = 0.f, mh1 = 0.f, mh2 = 0.f, mh3 = 0.f;
    #pragma unroll
    for (int n = 0; n < 8; n++) {
        float w = Ws[m * 8 + n];
        const float* rp = row + n * 128 + dp;
        mh0 += w * rp[0]; mh1 += w * rp[1]; mh2 += w * rp[2]; mh3 += w * rp[3];
    }
    float4 a = ((const float4*)(attnres + (size_t)r * D_))[tid];
    float4 f = ((const float4*)(ffn + (size_t)r * D_))[tid];
    float4 ov;
    ov.x = a.x + f.x + mh0;
    ov.y = a.y + f.y + mh1;
    ov.z = a.z + f.z + mh2;
    ov.w = a.w + f.w + mh3;
    ((float4*)(out + (size_t)r * D_))[tid] = ov;
}

// ---------------- launch ----------------------------------------------------
extern "C" void kernel_launch(void* const* d_in, const int* in_sizes, int n_in,
                              void* d_out, int out_size) {
    const float* x        = (const float*)d_in[0];
    const float* decay    = (const float*)d_in[3];
    const float* gate_w   = (const float*)d_in[4];
    const float* gate_b   = (const float*)d_in[5];
    const float* phi      = (const float*)d_in[6];
    const float* ln1_w    = (const float*)d_in[7];
    const float* ln2_w    = (const float*)d_in[8];
    const float* w1       = (const float*)d_in[9];
    const float* b1       = (const float*)d_in[10];
    const float* w2       = (const float*)d_in[11];
    const float* b2       = (const float*)d_in[12];
    const float* in_proj_w= (const float*)d_in[13];
    const float* in_proj_b= (const float*)d_in[14];
    const float* out_w    = (const float*)d_in[15];
    const float* out_b    = (const float*)d_in[16];
    float* out = (float*)d_out;

    void *p_xdelta, *p_xstate, *p_W, *p_qkvh, *p_attnres, *p_ffn,
         *p_normed, *p_normed2, *p_oh, *p_hh, *p_wqkv, *p_wout, *p_w1, *p_w2;
    cudaGetSymbolAddress(&p_xdelta, g_xdelta);
    cudaGetSymbolAddress(&p_xstate, g_xstate);
    cudaGetSymbolAddress(&p_W, g_W);
    cudaGetSymbolAddress(&p_qkvh, g_qkv_h);
    cudaGetSymbolAddress(&p_attnres, g_attnres);
    cudaGetSymbolAddress(&p_ffn, g_ffn);
    cudaGetSymbolAddress(&p_normed, g_normed_h);
    cudaGetSymbolAddress(&p_normed2, g_normed2_h);
    cudaGetSymbolAddress(&p_oh, g_o_h);
    cudaGetSymbolAddress(&p_hh, g_h_h);
    cudaGetSymbolAddress(&p_wqkv, g_wqkv_h);
    cudaGetSymbolAddress(&p_wout, g_wout_h);
    cudaGetSymbolAddress(&p_w1, g_w1_h);
    cudaGetSymbolAddress(&p_w2, g_w2_h);

    float*  xdelta   = (float*)p_xdelta;
    float*  xstate   = (float*)p_xstate;
    float*  Wm       = (float*)p_W;
    __half* qkv_h    = (__half*)p_qkvh;
    float*  attnres  = (float*)p_attnres;
    float*  ffn      = (float*)p_ffn;
    __half* normed_h = (__half*)p_normed;
    __half* normed2_h= (__half*)p_normed2;
    __half* o_h      = (__half*)p_oh;
    __half* h_h      = (__half*)p_hh;
    __half* wqkv_h   = (__half*)p_wqkv;
    __half* wout_h   = (__half*)p_wout;
    __half* w1_h     = (__half*)p_w1;
    __half* w2_h     = (__half*)p_w2;

    cudaFuncSetAttribute(gemm_f16_kernel<0>,
                         cudaFuncAttributeMaxDynamicSharedMemorySize, GEMM_SMEM_H);
    cudaFuncSetAttribute(gemm_f16_kernel<1>,
                         cudaFuncAttributeMaxDynamicSharedMemorySize, GEMM_SMEM_H);
    cudaFuncSetAttribute(gemm_f16_kernel<2>,
                         cudaFuncAttributeMaxDynamicSharedMemorySize, GEMM_SMEM_H);
    cudaFuncSetAttribute(attn_f16_kernel,
                         cudaFuncAttributeMaxDynamicSharedMemorySize, ATT_SMEM);

    // 0) convert weights to fp16
    tohalf_kernel<<<1024, 256>>>((const float4*)in_proj_w, (__half2*)wqkv_h,
                                 3 * D_ * D_ / 4);
    tohalf_kernel<<<1024, 256>>>((const float4*)out_w, (__half2*)wout_h,
                                 D_ * D_ / 4);
    tohalf_kernel<<<1024, 256>>>((const float4*)w1, (__half2*)w1_h,
                                 4 * D_ * D_ / 4);
    tohalf_kernel<<<1024, 256>>>((const float4*)w2, (__half2*)w2_h,
                                 4 * D_ * D_ / 4);

    // 1) delta scan
    delta_scan_kernel<<<256, 256>>>(x, decay, xdelta, xstate);
    // 2) gates + sinkhorn
    gate_sinkhorn_kernel<<<1, 256>>>(xstate, gate_w, gate_b, phi, Wm);
    // 3) rmsnorm1 (fp16 output)
    rmsnorm_kernel<<<NTOK, 256>>>(xdelta, ln1_w, normed_h);
    // 4) qkv projection (fp16 mma, fp16 out)
    gemm_f16_kernel<2><<<dim3(3 * D_ / 128, NTOK / 128), 128, GEMM_SMEM_H>>>(
        normed_h, wqkv_h, in_proj_b, nullptr, qkv_h, NTOK, 3 * D_, D_);
    // 5) attention (fp16 flash), fp16 output
    attn_f16_kernel<<<dim3(S_ / 128, NH, B_), 256, ATT_SMEM>>>(qkv_h, o_h);
    // 6) out projection + residual(x_delta), fp32 out
    gemm_f16_kernel<0><<<dim3(D_ / 128, NTOK / 128), 128, GEMM_SMEM_H>>>(
        o_h, wout_h, out_b, xdelta, attnres, NTOK, D_, D_);
    // 7) rmsnorm2 (fp16 output)
    rmsnorm_kernel<<<NTOK, 256>>>(attnres, ln2_w, normed2_h);
    // 8) FFN1 + gelu (fp16 out)
    gemm_f16_kernel<1><<<dim3(4 * D_ / 128, NTOK / 128), 128, GEMM_SMEM_H>>>(
        normed2_h, w1_h, b1, nullptr, h_h, NTOK, 4 * D_, D_);
    // 9) FFN2 (fp32 out)
    gemm_f16_kernel<0><<<dim3(D_ / 128, NTOK / 128), 128, GEMM_SMEM_H>>>(
        h_h, w2_h, b2, nullptr, ffn, NTOK, D_, 4 * D_);
    // 10) final
    final_kernel<<<NTOK, 256>>>(attnres, ffn, xdelta, Wm, out);
}

// round 16
// speedup vs baseline: 5.5836x; 1.0412x over previous
#include <cuda_runtime.h>
#include <cuda_fp16.h>
#include <cuda_bf16.h>
#include <math.h>
#include <stdint.h>

// Problem constants
#define B_  2
#define S_  2048
#define D_  1024
#define NH  16
#define HD  64
#define NTOK (B_*S_)          // 4096

// ---------------- scratch (static __device__, no allocation) ----------------
__device__ float  g_xdelta[NTOK * D_];
__device__ float  g_xstate[B_ * D_];
__device__ float  g_W[B_ * 8 * 8];
__device__ float  g_attnres[NTOK * D_];
__device__ float  g_ffn[NTOK * D_];
// fp16 activations
__device__ __half g_qkv_h[NTOK * 3 * D_];
__device__ __half g_normed_h[NTOK * D_];
__device__ __half g_normed2_h[NTOK * D_];
__device__ __half g_o_h[NTOK * D_];
__device__ __half g_h_h[NTOK * 4 * D_];
// fp16 weight copies
__device__ __half g_wqkv_h[3 * D_ * D_];
__device__ __half g_wout_h[D_ * D_];
__device__ __half g_w1_h[4 * D_ * D_];
__device__ __half g_w2_h[4 * D_ * D_];

// ---------------- helpers ----------------------------------------------------
__device__ __forceinline__ void mma_f16(float* c, const unsigned int* a,
                                        const unsigned int* b) {
    asm volatile(
        "mma.sync.aligned.m16n8k16.row.col.f32.f16.f16.f32 "
        "{%0,%1,%2,%3}, {%4,%5,%6,%7}, {%8,%9}, {%0,%1,%2,%3};"
        : "+f"(c[0]), "+f"(c[1]), "+f"(c[2]), "+f"(c[3])
        : "r"(a[0]), "r"(a[1]), "r"(a[2]), "r"(a[3]), "r"(b[0]), "r"(b[1]));
}
__device__ __forceinline__ void ldsm_x4(unsigned int& r0, unsigned int& r1,
                                        unsigned int& r2, unsigned int& r3,
                                        unsigned int addr) {
    asm volatile("ldmatrix.sync.aligned.m8n8.x4.shared.b16 {%0,%1,%2,%3}, [%4];"
                 : "=r"(r0), "=r"(r1), "=r"(r2), "=r"(r3) : "r"(addr));
}
__device__ __forceinline__ void ldsm_x4_t(unsigned int& r0, unsigned int& r1,
                                          unsigned int& r2, unsigned int& r3,
                                          unsigned int addr) {
    asm volatile("ldmatrix.sync.aligned.m8n8.x4.trans.shared.b16 {%0,%1,%2,%3}, [%4];"
                 : "=r"(r0), "=r"(r1), "=r"(r2), "=r"(r3) : "r"(addr));
}
__device__ __forceinline__ void cp_async16s(unsigned int saddr, const void* g) {
    asm volatile("cp.async.cg.shared.global [%0], [%1], 16;\n" :: "r"(saddr), "l"(g));
}

// ---------------- K0: convert all 4 weight matrices to fp16 (one launch) -----
__global__ void tohalf4_kernel(const float4* __restrict__ s0, __half2* __restrict__ d0, int n0,
                               const float4* __restrict__ s1, __half2* __restrict__ d1, int n1,
                               const float4* __restrict__ s2, __half2* __restrict__ d2, int n2,
                               const float4* __restrict__ s3, __half2* __restrict__ d3, int n3) {
    int i = blockIdx.x * blockDim.x + threadIdx.x;
    int stride = gridDim.x * blockDim.x;
    int total = n0 + n1 + n2 + n3;
    for (; i < total; i += stride) {
        const float4* s; __half2* d; int k = i;
        if (k < n0) { s = s0; d = d0; }
        else if ((k -= n0) < n1) { s = s1; d = d1; }
        else if ((k -= n1) < n2) { s = s2; d = d2; }
        else { k -= n2; s = s3; d = d3; }
        float4 v = s[k];
        d[2 * k]     = __floats2half2_rn(v.x, v.y);
        d[2 * k + 1] = __floats2half2_rn(v.z, v.w);
    }
}

// ---------------- K1: delta EMA scan (coalesced, smem-staged transpose) ------
// Block = 32 channels of one batch; 512 threads (16 warps x 2 channels).
// Tiles of 128 timesteps staged through smem (pitch 129: conflict-free both
// for the [t][ch] cooperative load/store and the [ch][t] scan access).
// Scan math identical to previous rounds: chunk-of-32 affine warp-scan w/ carry.
__global__ __launch_bounds__(512)
void delta_scan_kernel(const float* __restrict__ x,
                       const float* __restrict__ decay,
                       float* __restrict__ xd,
                       float* __restrict__ xstate) {
    __shared__ float T[32][129];
    int blk = blockIdx.x;                 // 0..63
    int b = blk >> 5;                     // 32 channel-groups per batch
    int c0 = (blk & 31) * 32;
    int tid = threadIdx.x;
    int warp = tid >> 5, lane = tid & 31;

    float beta[2], onem[2], carry[2] = {0.f, 0.f}, sum[2] = {0.f, 0.f};
    #pragma unroll
    for (int j = 0; j < 2; j++) {
        float dl = decay[c0 + warp * 2 + j];
        beta[j] = 1.f / (1.f + __expf(-dl));
        onem[j] = 1.f - beta[j];
    }
    const float* xb  = x  + (size_t)b * S_ * D_;
    float*       xdb = xd + (size_t)b * S_ * D_;

    for (int t0 = 0; t0 < S_; t0 += 128) {
        // load tile [128 t][32 ch] -> T[ch][t]
        #pragma unroll
        for (int i = 0; i < 2; i++) {
            int idx = i * 512 + tid;
            int r = idx >> 3, q = idx & 7;
            float4 v = *(const float4*)(xb + (size_t)(t0 + r) * D_ + c0 + q * 4);
            T[q * 4 + 0][r] = v.x;
            T[q * 4 + 1][r] = v.y;
            T[q * 4 + 2][r] = v.z;
            T[q * 4 + 3][r] = v.w;
        }
        __syncthreads();

        // scan 2 channels per warp, chunks of 32 (identical math to before)
        #pragma unroll
        for (int j = 0; j < 2; j++) {
            int ch = warp * 2 + j;
            #pragma unroll
            for (int tt = 0; tt < 128; tt += 32) {
                float xt = T[ch][tt + lane];
                float a = beta[j], bb = onem[j] * xt;
                #pragma unroll
                for (int off = 1; off < 32; off <<= 1) {
                    float pa = __shfl_up_sync(0xffffffffu, a, off);
                    float pb = __shfl_up_sync(0xffffffffu, bb, off);
                    if (lane >= off) { bb = a * pb + bb; a = a * pa; }
                }
                float s_incl = a * carry[j] + bb;
                float s_prev = __shfl_up_sync(0xffffffffu, s_incl, 1);
                if (lane == 0) s_prev = carry[j];
                float out = xt - s_prev;
                T[ch][tt + lane] = out;
                sum[j] += out;
                carry[j] = __shfl_sync(0xffffffffu, s_incl, 31);
            }
        }
        __syncthreads();

        // store tile back (coalesced)
        #pragma unroll
        for (int i = 0; i < 2; i++) {
            int idx = i * 512 + tid;
            int r = idx >> 3, q = idx & 7;
            float4 v;
            v.x = T[q * 4 + 0][r];
            v.y = T[q * 4 + 1][r];
            v.z = T[q * 4 + 2][r];
            v.w = T[q * 4 + 3][r];
            *(float4*)(xdb + (size_t)(t0 + r) * D_ + c0 + q * 4) = v;
        }
        __syncthreads();
    }

    // reduce per-channel sums across lanes
    #pragma unroll
    for (int j = 0; j < 2; j++) {
        float s = sum[j];
        #pragma unroll
        for (int off = 16; off >= 1; off >>= 1)
            s += __shfl_xor_sync(0xffffffffu, s, off);
        if (lane == 0)
            xstate[b * D_ + c0 + warp * 2 + j] = s * (1.f / (float)S_);
    }
}

// ---------------- K2: gates + sinkhorn + W --------------------------------
__global__ void gate_sinkhorn_kernel(const float* __restrict__ xstate,
                                     const float* __restrict__ gate_w,
                                     const float* __restrict__ gate_b,
                                     const float* __restrict__ phi,
                                     float* __restrict__ W) {
    __shared__ float gbuf[B_][8];
    __shared__ float Km[64];
    __shared__ float tmp[64];
    int tid = threadIdx.x;
    int wid = tid >> 5, lane = tid & 31;

    for (int idx = wid; idx < 16; idx += 8) {
        int b = idx >> 3;
        int j = 16 + (idx & 7);
        float s = 0.f;
        for (int k = lane; k < D_; k += 32)
            s += xstate[b * D_ + k] * gate_w[j * D_ + k];
        #pragma unroll
        for (int off = 16; off >= 1; off >>= 1)
            s += __shfl_xor_sync(0xffffffffu, s, off);
        if (lane == 0)
            gbuf[b][idx & 7] = 1.f / (1.f + __expf(-(s + gate_b[j])));
    }
    if (tid < 64) Km[tid] = __expf(phi[tid]);
    __syncthreads();

    for (int it = 0; it < 15; it++) {
        if (tid < 64) {
            int m = tid >> 3;
            float rs = 0.f;
            #pragma unroll
            for (int n = 0; n < 8; n++) rs += Km[m * 8 + n];
            tmp[tid] = Km[tid] / rs;
        }
        __syncthreads();
        if (tid < 64) {
            int n = tid & 7;
            float cs = 0.f;
            #pragma unroll
            for (int m = 0; m < 8; m++) cs += tmp[m * 8 + n];
            Km[tid] = tmp[tid] / cs;
        }
        __syncthreads();
    }
    if (tid < 128) {
        int b = tid >> 6, r = tid & 63, n = r & 7;
        W[b * 64 + r] = Km[r] * gbuf[b][n];
    }
}

// ---------------- K3: RMSNorm (block per row, fp16 output) -------------------
__global__ void rmsnorm_kernel(const float* __restrict__ x,
                               const float* __restrict__ w,
                               __half* __restrict__ y) {
    int row = blockIdx.x;
    int tid = threadIdx.x;
    const float4* xr = (const float4*)(x + (size_t)row * D_);
    float4 v = xr[tid];
    float ss = v.x * v.x + v.y * v.y + v.z * v.z + v.w * v.w;
    __shared__ float red[8];
    #pragma unroll
    for (int off = 16; off >= 1; off >>= 1)
        ss += __shfl_xor_sync(0xffffffffu, ss, off);
    if ((tid & 31) == 0) red[tid >> 5] = ss;
    __syncthreads();
    if (tid < 8) {
        float t = red[tid];
        #pragma unroll
        for (int off = 4; off >= 1; off >>= 1)
            t += __shfl_xor_sync(0xffu, t, off);
        if (tid == 0) red[0] = t;
    }
    __syncthreads();
    float scale = rsqrtf(red[0] * (1.f / (float)D_) + 1e-6f);
    float4 wv = ((const float4*)w)[tid];
    __half2* yp = (__half2*)(y + (size_t)row * D_);
    yp[2 * tid]     = __floats2half2_rn(v.x * scale * wv.x, v.y * scale * wv.y);
    yp[2 * tid + 1] = __floats2half2_rn(v.z * scale * wv.z, v.w * scale * wv.w);
}

// ---------------- FP16 GEMM NT: C = A[M,K]*B[N,K]^T + bias (+res)(+gelu) -----
// Block 128x128, 4 warps each 64x64, mma m16n8k16 f16, ldmatrix fragment loads.
// EPI: 0 = fp32 out, bias (+res); 1 = fp16 out, bias+GELU; 2 = fp16 out, bias.
#define HP  40          // halves per smem row (80 B pitch)
#define HSTG 5120       // halves per stage (128 * 40)
#define GEMM_SMEM_H (4 * HSTG * 2)     // 40960 bytes

__device__ __forceinline__ void ld_chunk_f16(unsigned int abuf, unsigned int bbuf,
                                             const __half* __restrict__ A,
                                             const __half* __restrict__ Bm,
                                             int bm, int bn, int K, int k0, int tid) {
    #pragma unroll
    for (int i = 0; i < 4; i++) {
        int c = i * 128 + tid;
        int r = c >> 2, q = c & 3;
        cp_async16s(abuf + r * 80 + q * 16, A + (size_t)(bm + r) * K + k0 + q * 8);
        cp_async16s(bbuf + r * 80 + q * 16, Bm + (size_t)(bn + r) * K + k0 + q * 8);
    }
    asm volatile("cp.async.commit_group;\n" ::: "memory");
}

template <int EPI>
__global__ __launch_bounds__(128, 2)
void gemm_f16_kernel(const __half* __restrict__ A, const __half* __restrict__ Bm,
                     const float* __restrict__ bias, const float* __restrict__ res,
                     void* __restrict__ Cv, int M, int N, int K) {
    extern __shared__ __align__(16) char smemc[];
    unsigned int sbase = (unsigned int)__cvta_generic_to_shared(smemc);

    int bm = blockIdx.y * 128;
    int bn = blockIdx.x * 128;
    int tid = threadIdx.x;
    int warp = tid >> 5, lane = tid & 31;
    int wm = (warp & 1) * 64;
    int wn = (warp >> 1) * 64;
    int g = lane >> 2, t = lane & 3;

    // ldmatrix per-lane address offsets (bytes)
    int arow_off = (wm + (lane & 15)) * 80 + ((lane >> 4) * 16);
    int brow_off = (wn + (lane & 7) + ((lane >> 4) & 1) * 8) * 80
                   + (((lane >> 3) & 1) * 16);

    float acc[4][8][4];
    #pragma unroll
    for (int mi = 0; mi < 4; mi++)
        #pragma unroll
        for (int ni = 0; ni < 8; ni++)
            #pragma unroll
            for (int r = 0; r < 4; r++) acc[mi][ni][r] = 0.f;

    int KT = K >> 5;
    ld_chunk_f16(sbase, sbase + 20480, A, Bm, bm, bn, K, 0, tid);

    int buf = 0;
    for (int kt = 0; kt < KT; kt++) {
        if (kt + 1 < KT) {
            int boff = (buf ^ 1) * 10240;
            ld_chunk_f16(sbase + boff, sbase + 20480 + boff,
                         A, Bm, bm, bn, K, (kt + 1) << 5, tid);
            asm volatile("cp.async.wait_group 1;\n" ::: "memory");
        } else {
            asm volatile("cp.async.wait_group 0;\n" ::: "memory");
        }
        __syncthreads();

        unsigned int abase = sbase + buf * 10240;
        unsigned int bbase = sbase + 20480 + buf * 10240;
        #pragma unroll
        for (int s = 0; s < 2; s++) {
            unsigned int af[4][4], bf[8][2];
            #pragma unroll
            for (int mi = 0; mi < 4; mi++)
                ldsm_x4(af[mi][0], af[mi][1], af[mi][2], af[mi][3],
                        abase + arow_off + mi * 1280 + s * 32);
            #pragma unroll
            for (int p = 0; p < 4; p++)
                ldsm_x4(bf[2 * p][0], bf[2 * p][1], bf[2 * p + 1][0], bf[2 * p + 1][1],
                        bbase + brow_off + p * 1280 + s * 32);
            #pragma unroll
            for (int mi = 0; mi < 4; mi++)
                #pragma unroll
                for (int ni = 0; ni < 8; ni++)
                    mma_f16(acc[mi][ni], af[mi], bf[ni]);
        }
        __syncthreads();
        buf ^= 1;
    }

    // epilogue
    #pragma unroll
    for (int mi = 0; mi < 4; mi++) {
        #pragma unroll
        for (int ni = 0; ni < 8; ni++) {
            int col = bn + wn + ni * 8 + t * 2;
            #pragma unroll
            for (int half = 0; half < 2; half++) {
                int row = bm + wm + mi * 16 + g + half * 8;
                float vx = acc[mi][ni][half * 2 + 0] + bias[col + 0];
                float vy = acc[mi][ni][half * 2 + 1] + bias[col + 1];
                if (EPI == 1) {
                    vx = 0.5f * vx * (1.f + erff(vx * 0.7071067811865476f));
                    vy = 0.5f * vy * (1.f + erff(vy * 0.7071067811865476f));
                }
                if (EPI >= 1) {
                    __half2* C = (__half2*)((__half*)Cv + (size_t)row * N + col);
                    *C = __floats2half2_rn(vx, vy);
                } else {
                    if (res != nullptr) {
                        float2 r = *(const float2*)(res + (size_t)row * N + col);
                        vx += r.x; vy += r.y;
                    }
                    float2 v; v.x = vx; v.y = vy;
                    *(float2*)((float*)Cv + (size_t)row * N + col) = v;
                }
            }
        }
    }
}

// ---------------- K5: FP16 tensor-core flash causal attention ----------------
// q-tile 128, kv-tile 64, 8 warps x 16 q-rows, mma m16n8k16 f16, fp32 softmax.
// ldmatrix fragment loads; V kept row-major [kv][hd], B-fragments via
// ldmatrix.trans (no transpose scatter). Pitch 72 halves (144 B), conflict-free.
#define AHP 72
#define ATT_SMEM ((128*AHP + 64*AHP + 64*AHP + 128*AHP) * 2)   // 55296 B

__global__ __launch_bounds__(256)
void attn_f16_kernel(const __half* __restrict__ qkv, __half* __restrict__ o) {
    extern __shared__ __align__(16) char smc[];
    __half* Qh = (__half*)smc;               // [128][AHP]
    __half* Kh = Qh + 128 * AHP;             // [64][AHP]
    __half* Vh = Kh + 64 * AHP;              // [64][AHP]  row-major [kv][hd]
    __half* Ph = Vh + 64 * AHP;              // [128][AHP]
    unsigned int sb = (unsigned int)__cvta_generic_to_shared(smc);
    const unsigned int qb = sb;
    const unsigned int kb = sb + 128 * AHP * 2;
    const unsigned int vb = kb + 64 * AHP * 2;
    const unsigned int pb = vb + 64 * AHP * 2;

    int qt = blockIdx.x, h = blockIdx.y, b = blockIdx.z;
    int tid = threadIdx.x;
    int warp = tid >> 5, lane = tid & 31;
    int g = lane >> 2, t = lane & 3;
    int qr0 = qt * 128;
    const __half* base = qkv + (size_t)b * S_ * (3 * D_);

    // ldmatrix per-lane offsets (bytes)
    int qrow_off = (warp * 16 + (lane & 15)) * 144 + ((lane >> 4) * 16);
    int krow_off = ((lane & 7) + ((lane >> 4) & 1) * 8) * 144
                   + (((lane >> 3) & 1) * 16);
    int vrow_off = ((lane & 7) + ((lane >> 3) & 1) * 8) * 144
                   + ((lane >> 4) * 16);

    // load Q tile (scaled by 1/8)
    {
        __half2 sc = __floats2half2_rn(0.125f, 0.125f);
        for (int i = tid; i < 128 * 32; i += 256) {
            int r = i >> 5, c2 = i & 31;
            __half2 v = *(const __half2*)(base + (size_t)(qr0 + r) * (3 * D_)
                                          + h * HD + 2 * c2);
            *(__half2*)(Qh + r * AHP + 2 * c2) = __hmul2(v, sc);
        }
    }

    int row0 = warp * 16 + g;
    int row1 = row0 + 8;

    float oacc[8][4];
    float m0 = -1e30f, m1 = -1e30f, l0 = 0.f, l1 = 0.f;
    #pragma unroll
    for (int ni = 0; ni < 8; ni++)
        #pragma unroll
        for (int r = 0; r < 4; r++) oacc[ni][r] = 0.f;

    int jt_max = 2 * qt + 1;
    for (int jt = 0; jt <= jt_max; jt++) {
        int jr0 = jt * 64;
        __syncthreads();
        for (int i = tid; i < 64 * 32; i += 256) {
            int r = i >> 5, c2 = i & 31;
            *(__half2*)(Kh + r * AHP + 2 * c2) =
                *(const __half2*)(base + (size_t)(jr0 + r) * (3 * D_) + D_
                                  + h * HD + 2 * c2);
            *(__half2*)(Vh + r * AHP + 2 * c2) =
                *(const __half2*)(base + (size_t)(jr0 + r) * (3 * D_) + 2 * D_
                                  + h * HD + 2 * c2);
        }
        __syncthreads();

        if (jr0 > qr0 + warp * 16 + 15) continue;

        // S = Q @ K^T
        float sacc[8][4];
        #pragma unroll
        for (int ni = 0; ni < 8; ni++)
            #pragma unroll
            for (int r = 0; r < 4; r++) sacc[ni][r] = 0.f;

        #pragma unroll
        for (int s = 0; s < 4; s++) {
            unsigned int aq[4], bk[8][2];
            ldsm_x4(aq[0], aq[1], aq[2], aq[3], qb + qrow_off + s * 32);
            #pragma unroll
            for (int p = 0; p < 4; p++)
                ldsm_x4(bk[2 * p][0], bk[2 * p][1], bk[2 * p + 1][0], bk[2 * p + 1][1],
                        kb + krow_off + p * 2304 + s * 32);
            #pragma unroll
            for (int ni = 0; ni < 8; ni++)
                mma_f16(sacc[ni], aq, bk[ni]);
        }

        // causal mask
        if (jr0 + 63 > qr0 + warp * 16) {
            int gr0 = qr0 + row0, gr1 = qr0 + row1;
            #pragma unroll
            for (int ni = 0; ni < 8; ni++) {
                int c0 = jr0 + ni * 8 + 2 * t;
                if (c0 > gr0)     sacc[ni][0] = -1e30f;
                if (c0 + 1 > gr0) sacc[ni][1] = -1e30f;
                if (c0 > gr1)     sacc[ni][2] = -1e30f;
                if (c0 + 1 > gr1) sacc[ni][3] = -1e30f;
            }
        }

        // online softmax (fp32)
        float mx0 = -1e30f, mx1 = -1e30f;
        #pragma unroll
        for (int ni = 0; ni < 8; ni++) {
            mx0 = fmaxf(mx0, fmaxf(sacc[ni][0], sacc[ni][1]));
            mx1 = fmaxf(mx1, fmaxf(sacc[ni][2], sacc[ni][3]));
        }
        #pragma unroll
        for (int off = 1; off < 4; off <<= 1) {
            mx0 = fmaxf(mx0, __shfl_xor_sync(0xffffffffu, mx0, off));
            mx1 = fmaxf(mx1, __shfl_xor_sync(0xffffffffu, mx1, off));
        }
        float nm0 = fmaxf(m0, mx0), nm1 = fmaxf(m1, mx1);
        float ps0 = 0.f, ps1 = 0.f;
        #pragma unroll
        for (int ni = 0; ni < 8; ni++) {
            sacc[ni][0] = __expf(sacc[ni][0] - nm0);
            sacc[ni][1] = __expf(sacc[ni][1] - nm0);
            sacc[ni][2] = __expf(sacc[ni][2] - nm1);
            sacc[ni][3] = __expf(sacc[ni][3] - nm1);
            ps0 += sacc[ni][0] + sacc[ni][1];
            ps1 += sacc[ni][2] + sacc[ni][3];
        }
        #pragma unroll
        for (int off = 1; off < 4; off <<= 1) {
            ps0 += __shfl_xor_sync(0xffffffffu, ps0, off);
            ps1 += __shfl_xor_sync(0xffffffffu, ps1, off);
        }
        float al0 = __expf(m0 - nm0), al1 = __expf(m1 - nm1);
        l0 = l0 * al0 + ps0;  m0 = nm0;
        l1 = l1 * al1 + ps1;  m1 = nm1;
        #pragma unroll
        for (int ni = 0; ni < 8; ni++) {
            oacc[ni][0] *= al0; oacc[ni][1] *= al0;
            oacc[ni][2] *= al1; oacc[ni][3] *= al1;
        }

        // P -> smem (fp16); warp-private rows
        #pragma unroll
        for (int ni = 0; ni < 8; ni++) {
            *(__half2*)(Ph + row0 * AHP + ni * 8 + 2 * t) =
                __floats2half2_rn(sacc[ni][0], sacc[ni][1]);
            *(__half2*)(Ph + row1 * AHP + ni * 8 + 2 * t) =
                __floats2half2_rn(sacc[ni][2], sacc[ni][3]);
        }
        __syncwarp();

        // O += P @ V  (V row-major, fragments via ldmatrix.trans)
        #pragma unroll
        for (int s = 0; s < 4; s++) {
            unsigned int ap[4], bv[8][2];
            ldsm_x4(ap[0], ap[1], ap[2], ap[3], pb + qrow_off + s * 32);
            #pragma unroll
            for (int p = 0; p < 4; p++)
                ldsm_x4_t(bv[2 * p][0], bv[2 * p][1], bv[2 * p + 1][0], bv[2 * p + 1][1],
                          vb + vrow_off + s * 2304 + p * 32);
            #pragma unroll
            for (int ni = 0; ni < 8; ni++)
                mma_f16(oacc[ni], ap, bv[ni]);
        }
        __syncwarp();
    }

    // O feeds the fp16 out-proj GEMM -> write half2
    float inv0 = 1.f / l0, inv1 = 1.f / l1;
    size_t gr0 = (size_t)(b * S_ + qr0 + row0) * D_ + h * HD;
    size_t gr1 = (size_t)(b * S_ + qr0 + row1) * D_ + h * HD;
    #pragma unroll
    for (int ni = 0; ni < 8; ni++) {
        int c = ni * 8 + 2 * t;
        *(__half2*)(o + gr0 + c) = __floats2half2_rn(oacc[ni][0] * inv0,
                                                     oacc[ni][1] * inv0);
        *(__half2*)(o + gr1 + c) = __floats2half2_rn(oacc[ni][2] * inv1,
                                                     oacc[ni][3] * inv1);
    }
}

// ---------------- K10: final sum + mhc mix ----------------------------------
__global__ void final_kernel(const float* __restrict__ attnres,
                             const float* __restrict__ ffn,
                             const float* __restrict__ xd,
                             const float* __restrict__ W,
                             float* __restrict__ out) {
    __shared__ float row[D_];
    __shared__ float Ws[64];
    int r = blockIdx.x;
    int b = r >> 11;
    int tid = threadIdx.x;
    ((float4*)row)[tid] = ((const float4*)(xd + (size_t)r * D_))[tid];
    if (tid < 64) Ws[tid] = W[b * 64 + tid];
    __syncthreads();

    int c0 = tid * 4;
    int m = c0 >> 7;
    int dp = c0 & 127;
    float mh0 = 0.f, mh1 = 0.f, mh2 = 0.f, mh3 = 0.f;
    #pragma unroll
    for (int n = 0; n < 8; n++) {
        float w = Ws[m * 8 + n];
        const float* rp = row + n * 128 + dp;
        mh0 += w * rp[0]; mh1 += w * rp[1]; mh2 += w * rp[2]; mh3 += w * rp[3];
    }
    float4 a = ((const float4*)(attnres + (size_t)r * D_))[tid];
    float4 f = ((const float4*)(ffn + (size_t)r * D_))[tid];
    float4 ov;
    ov.x = a.x + f.x + mh0;
    ov.y = a.y + f.y + mh1;
    ov.z = a.z + f.z + mh2;
    ov.w = a.w + f.w + mh3;
    ((float4*)(out + (size_t)r * D_))[tid] = ov;
}

// ---------------- launch ----------------------------------------------------
extern "C" void kernel_launch(void* const* d_in, const int* in_sizes, int n_in,
                              void* d_out, int out_size) {
    const float* x        = (const float*)d_in[0];
    const float* decay    = (const float*)d_in[3];
    const float* gate_w   = (const float*)d_in[4];
    const float* gate_b   = (const float*)d_in[5];
    const float* phi      = (const float*)d_in[6];
    const float* ln1_w    = (const float*)d_in[7];
    const float* ln2_w    = (const float*)d_in[8];
    const float* w1       = (const float*)d_in[9];
    const float* b1       = (const float*)d_in[10];
    const float* w2       = (const float*)d_in[11];
    const float* b2       = (const float*)d_in[12];
    const float* in_proj_w= (const float*)d_in[13];
    const float* in_proj_b= (const float*)d_in[14];
    const float* out_w    = (const float*)d_in[15];
    const float* out_b    = (const float*)d_in[16];
    float* out = (float*)d_out;

    void *p_xdelta, *p_xstate, *p_W, *p_qkvh, *p_attnres, *p_ffn,
         *p_normed, *p_normed2, *p_oh, *p_hh, *p_wqkv, *p_wout, *p_w1, *p_w2;
    cudaGetSymbolAddress(&p_xdelta, g_xdelta);
    cudaGetSymbolAddress(&p_xstate, g_xstate);
    cudaGetSymbolAddress(&p_W, g_W);
    cudaGetSymbolAddress(&p_qkvh, g_qkv_h);
    cudaGetSymbolAddress(&p_attnres, g_attnres);
    cudaGetSymbolAddress(&p_ffn, g_ffn);
    cudaGetSymbolAddress(&p_normed, g_normed_h);
    cudaGetSymbolAddress(&p_normed2, g_normed2_h);
    cudaGetSymbolAddress(&p_oh, g_o_h);
    cudaGetSymbolAddress(&p_hh, g_h_h);
    cudaGetSymbolAddress(&p_wqkv, g_wqkv_h);
    cudaGetSymbolAddress(&p_wout, g_wout_h);
    cudaGetSymbolAddress(&p_w1, g_w1_h);
    cudaGetSymbolAddress(&p_w2, g_w2_h);

    float*  xdelta   = (float*)p_xdelta;
    float*  xstate   = (float*)p_xstate;
    float*  Wm       = (float*)p_W;
    __half* qkv_h    = (__half*)p_qkvh;
    float*  attnres  = (float*)p_attnres;
    float*  ffn      = (float*)p_ffn;
    __half* normed_h = (__half*)p_normed;
    __half* normed2_h= (__half*)p_normed2;
    __half* o_h      = (__half*)p_oh;
    __half* h_h      = (__half*)p_hh;
    __half* wqkv_h   = (__half*)p_wqkv;
    __half* wout_h   = (__half*)p_wout;
    __half* w1_h     = (__half*)p_w1;
    __half* w2_h     = (__half*)p_w2;

    cudaFuncSetAttribute(gemm_f16_kernel<0>,
                         cudaFuncAttributeMaxDynamicSharedMemorySize, GEMM_SMEM_H);
    cudaFuncSetAttribute(gemm_f16_kernel<1>,
                         cudaFuncAttributeMaxDynamicSharedMemorySize, GEMM_SMEM_H);
    cudaFuncSetAttribute(gemm_f16_kernel<2>,
                         cudaFuncAttributeMaxDynamicSharedMemorySize, GEMM_SMEM_H);
    cudaFuncSetAttribute(attn_f16_kernel,
                         cudaFuncAttributeMaxDynamicSharedMemorySize, ATT_SMEM);

    // 0) convert all weights to fp16 (single launch)
    tohalf4_kernel<<<2048, 256>>>(
        (const float4*)in_proj_w, (__half2*)wqkv_h, 3 * D_ * D_ / 4,
        (const float4*)out_w,     (__half2*)wout_h, D_ * D_ / 4,
        (const float4*)w1,        (__half2*)w1_h,   4 * D_ * D_ / 4,
        (const float4*)w2,        (__half2*)w2_h,   4 * D_ * D_ / 4);

    // 1) delta scan (coalesced)
    delta_scan_kernel<<<B_ * D_ / 32, 512>>>(x, decay, xdelta, xstate);
    // 2) gates + sinkhorn
    gate_sinkhorn_kernel<<<1, 256>>>(xstate, gate_w, gate_b, phi, Wm);
    // 3) rmsnorm1 (fp16 output)
    rmsnorm_kernel<<<NTOK, 256>>>(xdelta, ln1_w, normed_h);
    // 4) qkv projection (fp16 mma, fp16 out)
    gemm_f16_kernel<2><<<dim3(3 * D_ / 128, NTOK / 128), 128, GEMM_SMEM_H>>>(
        normed_h, wqkv_h, in_proj_b, nullptr, qkv_h, NTOK, 3 * D_, D_);
    // 5) attention (fp16 flash), fp16 output
    attn_f16_kernel<<<dim3(S_ / 128, NH, B_), 256, ATT_SMEM>>>(qkv_h, o_h);
    // 6) out projection + residual(x_delta), fp32 out
    gemm_f16_kernel<0><<<dim3(D_ / 128, NTOK / 128), 128, GEMM_SMEM_H>>>(
        o_h, wout_h, out_b, xdelta, attnres, NTOK, D_, D_);
    // 7) rmsnorm2 (fp16 output)
    rmsnorm_kernel<<<NTOK, 256>>>(attnres, ln2_w, normed2_h);
    // 8) FFN1 + gelu (fp16 out)
    gemm_f16_kernel<1><<<dim3(4 * D_ / 128, NTOK / 128), 128, GEMM_SMEM_H>>>(
        normed2_h, w1_h, b1, nullptr, h_h, NTOK, 4 * D_, D_);
    // 9) FFN2 (fp32 out)
    gemm_f16_kernel<0><<<dim3(D_ / 128, NTOK / 128), 128, GEMM_SMEM_H>>>(
        h_h, w2_h, b2, nullptr, ffn, NTOK, D_, 4 * D_);
    // 10) final
    final_kernel<<<NTOK, 256>>>(attnres, ffn, xdelta, Wm, out);
}

// round 17
// speedup vs baseline: 5.7297x; 1.0262x over previous
#include <cuda_runtime.h>
#include <cuda_fp16.h>
#include <cuda_bf16.h>
#include <math.h>
#include <stdint.h>

// Problem constants
#define B_  2
#define S_  2048
#define D_  1024
#define NH  16
#define HD  64
#define NTOK (B_*S_)          // 4096

// ---------------- scratch (static __device__, no allocation) ----------------
__device__ float  g_xdelta[NTOK * D_];
__device__ float  g_xstate[B_ * D_];
__device__ float  g_W[B_ * 8 * 8];
__device__ float  g_attnres[NTOK * D_];
__device__ float  g_ffn[NTOK * D_];
// fp16 activations
__device__ __half g_qkv_h[NTOK * 3 * D_];
__device__ __half g_normed_h[NTOK * D_];
__device__ __half g_normed2_h[NTOK * D_];
__device__ __half g_o_h[NTOK * D_];
__device__ __half g_h_h[NTOK * 4 * D_];
// fp16 weight copies
__device__ __half g_wqkv_h[3 * D_ * D_];
__device__ __half g_wout_h[D_ * D_];
__device__ __half g_w1_h[4 * D_ * D_];
__device__ __half g_w2_h[4 * D_ * D_];

// ---------------- helpers ----------------------------------------------------
__device__ __forceinline__ void mma_f16(float* c, const unsigned int* a,
                                        const unsigned int* b) {
    asm volatile(
        "mma.sync.aligned.m16n8k16.row.col.f32.f16.f16.f32 "
        "{%0,%1,%2,%3}, {%4,%5,%6,%7}, {%8,%9}, {%0,%1,%2,%3};"
        : "+f"(c[0]), "+f"(c[1]), "+f"(c[2]), "+f"(c[3])
        : "r"(a[0]), "r"(a[1]), "r"(a[2]), "r"(a[3]), "r"(b[0]), "r"(b[1]));
}
__device__ __forceinline__ void ldsm_x4(unsigned int& r0, unsigned int& r1,
                                        unsigned int& r2, unsigned int& r3,
                                        unsigned int addr) {
    asm volatile("ldmatrix.sync.aligned.m8n8.x4.shared.b16 {%0,%1,%2,%3}, [%4];"
                 : "=r"(r0), "=r"(r1), "=r"(r2), "=r"(r3) : "r"(addr));
}
__device__ __forceinline__ void ldsm_x4_t(unsigned int& r0, unsigned int& r1,
                                          unsigned int& r2, unsigned int& r3,
                                          unsigned int addr) {
    asm volatile("ldmatrix.sync.aligned.m8n8.x4.trans.shared.b16 {%0,%1,%2,%3}, [%4];"
                 : "=r"(r0), "=r"(r1), "=r"(r2), "=r"(r3) : "r"(addr));
}
__device__ __forceinline__ void cp_async16s(unsigned int saddr, const void* g) {
    asm volatile("cp.async.cg.shared.global [%0], [%1], 16;\n" :: "r"(saddr), "l"(g));
}

// ---------------- K0: convert all 4 weight matrices to fp16 (one launch) -----
__global__ void tohalf4_kernel(const float4* __restrict__ s0, __half2* __restrict__ d0, int n0,
                               const float4* __restrict__ s1, __half2* __restrict__ d1, int n1,
                               const float4* __restrict__ s2, __half2* __restrict__ d2, int n2,
                               const float4* __restrict__ s3, __half2* __restrict__ d3, int n3) {
    int i = blockIdx.x * blockDim.x + threadIdx.x;
    int stride = gridDim.x * blockDim.x;
    int total = n0 + n1 + n2 + n3;
    for (; i < total; i += stride) {
        const float4* s; __half2* d; int k = i;
        if (k < n0) { s = s0; d = d0; }
        else if ((k -= n0) < n1) { s = s1; d = d1; }
        else if ((k -= n1) < n2) { s = s2; d = d2; }
        else { k -= n2; s = s3; d = d3; }
        float4 v = s[k];
        d[2 * k]     = __floats2half2_rn(v.x, v.y);
        d[2 * k + 1] = __floats2half2_rn(v.z, v.w);
    }
}

// ---------------- K1: delta EMA scan (coalesced, smem-staged transpose) ------
__global__ __launch_bounds__(512)
void delta_scan_kernel(const float* __restrict__ x,
                       const float* __restrict__ decay,
                       float* __restrict__ xd,
                       float* __restrict__ xstate) {
    __shared__ float T[32][129];
    int blk = blockIdx.x;                 // 0..63
    int b = blk >> 5;
    int c0 = (blk & 31) * 32;
    int tid = threadIdx.x;
    int warp = tid >> 5, lane = tid & 31;

    float beta[2], onem[2], carry[2] = {0.f, 0.f}, sum[2] = {0.f, 0.f};
    #pragma unroll
    for (int j = 0; j < 2; j++) {
        float dl = decay[c0 + warp * 2 + j];
        beta[j] = 1.f / (1.f + __expf(-dl));
        onem[j] = 1.f - beta[j];
    }
    const float* xb  = x  + (size_t)b * S_ * D_;
    float*       xdb = xd + (size_t)b * S_ * D_;

    for (int t0 = 0; t0 < S_; t0 += 128) {
        #pragma unroll
        for (int i = 0; i < 2; i++) {
            int idx = i * 512 + tid;
            int r = idx >> 3, q = idx & 7;
            float4 v = *(const float4*)(xb + (size_t)(t0 + r) * D_ + c0 + q * 4);
            T[q * 4 + 0][r] = v.x;
            T[q * 4 + 1][r] = v.y;
            T[q * 4 + 2][r] = v.z;
            T[q * 4 + 3][r] = v.w;
        }
        __syncthreads();

        #pragma unroll
        for (int j = 0; j < 2; j++) {
            int ch = warp * 2 + j;
            #pragma unroll
            for (int tt = 0; tt < 128; tt += 32) {
                float xt = T[ch][tt + lane];
                float a = beta[j], bb = onem[j] * xt;
                #pragma unroll
                for (int off = 1; off < 32; off <<= 1) {
                    float pa = __shfl_up_sync(0xffffffffu, a, off);
                    float pb = __shfl_up_sync(0xffffffffu, bb, off);
                    if (lane >= off) { bb = a * pb + bb; a = a * pa; }
                }
                float s_incl = a * carry[j] + bb;
                float s_prev = __shfl_up_sync(0xffffffffu, s_incl, 1);
                if (lane == 0) s_prev = carry[j];
                float out = xt - s_prev;
                T[ch][tt + lane] = out;
                sum[j] += out;
                carry[j] = __shfl_sync(0xffffffffu, s_incl, 31);
            }
        }
        __syncthreads();

        #pragma unroll
        for (int i = 0; i < 2; i++) {
            int idx = i * 512 + tid;
            int r = idx >> 3, q = idx & 7;
            float4 v;
            v.x = T[q * 4 + 0][r];
            v.y = T[q * 4 + 1][r];
            v.z = T[q * 4 + 2][r];
            v.w = T[q * 4 + 3][r];
            *(float4*)(xdb + (size_t)(t0 + r) * D_ + c0 + q * 4) = v;
        }
        __syncthreads();
    }

    #pragma unroll
    for (int j = 0; j < 2; j++) {
        float s = sum[j];
        #pragma unroll
        for (int off = 16; off >= 1; off >>= 1)
            s += __shfl_xor_sync(0xffffffffu, s, off);
        if (lane == 0)
            xstate[b * D_ + c0 + warp * 2 + j] = s * (1.f / (float)S_);
    }
}

// ---------------- K2: gates + sinkhorn + W --------------------------------
__global__ void gate_sinkhorn_kernel(const float* __restrict__ xstate,
                                     const float* __restrict__ gate_w,
                                     const float* __restrict__ gate_b,
                                     const float* __restrict__ phi,
                                     float* __restrict__ W) {
    __shared__ float gbuf[B_][8];
    __shared__ float Km[64];
    __shared__ float tmp[64];
    int tid = threadIdx.x;
    int wid = tid >> 5, lane = tid & 31;

    for (int idx = wid; idx < 16; idx += 8) {
        int b = idx >> 3;
        int j = 16 + (idx & 7);
        float s = 0.f;
        for (int k = lane; k < D_; k += 32)
            s += xstate[b * D_ + k] * gate_w[j * D_ + k];
        #pragma unroll
        for (int off = 16; off >= 1; off >>= 1)
            s += __shfl_xor_sync(0xffffffffu, s, off);
        if (lane == 0)
            gbuf[b][idx & 7] = 1.f / (1.f + __expf(-(s + gate_b[j])));
    }
    if (tid < 64) Km[tid] = __expf(phi[tid]);
    __syncthreads();

    for (int it = 0; it < 15; it++) {
        if (tid < 64) {
            int m = tid >> 3;
            float rs = 0.f;
            #pragma unroll
            for (int n = 0; n < 8; n++) rs += Km[m * 8 + n];
            tmp[tid] = Km[tid] / rs;
        }
        __syncthreads();
        if (tid < 64) {
            int n = tid & 7;
            float cs = 0.f;
            #pragma unroll
            for (int m = 0; m < 8; m++) cs += tmp[m * 8 + n];
            Km[tid] = tmp[tid] / cs;
        }
        __syncthreads();
    }
    if (tid < 128) {
        int b = tid >> 6, r = tid & 63, n = r & 7;
        W[b * 64 + r] = Km[r] * gbuf[b][n];
    }
}

// ---------------- K3: RMSNorm (block per row, fp16 output) -------------------
__global__ void rmsnorm_kernel(const float* __restrict__ x,
                               const float* __restrict__ w,
                               __half* __restrict__ y) {
    int row = blockIdx.x;
    int tid = threadIdx.x;
    const float4* xr = (const float4*)(x + (size_t)row * D_);
    float4 v = xr[tid];
    float ss = v.x * v.x + v.y * v.y + v.z * v.z + v.w * v.w;
    __shared__ float red[8];
    #pragma unroll
    for (int off = 16; off >= 1; off >>= 1)
        ss += __shfl_xor_sync(0xffffffffu, ss, off);
    if ((tid & 31) == 0) red[tid >> 5] = ss;
    __syncthreads();
    if (tid < 8) {
        float t = red[tid];
        #pragma unroll
        for (int off = 4; off >= 1; off >>= 1)
            t += __shfl_xor_sync(0xffu, t, off);
        if (tid == 0) red[0] = t;
    }
    __syncthreads();
    float scale = rsqrtf(red[0] * (1.f / (float)D_) + 1e-6f);
    float4 wv = ((const float4*)w)[tid];
    __half2* yp = (__half2*)(y + (size_t)row * D_);
    yp[2 * tid]     = __floats2half2_rn(v.x * scale * wv.x, v.y * scale * wv.y);
    yp[2 * tid + 1] = __floats2half2_rn(v.z * scale * wv.z, v.w * scale * wv.w);
}

// ---------------- FP16 GEMM NT, 3-stage cp.async pipeline --------------------
// Block 128x128, 4 warps each 64x64, mma m16n8k16 f16, ldmatrix fragment loads.
// EPI: 0 = fp32 out, bias (+res); 1 = fp16 out, bias+GELU; 2 = fp16 out, bias.
#define HP  40          // halves per smem row (80 B pitch)
#define GEMM_SMEM_H 61440     // 3 stages x (10240 A + 10240 B)

__device__ __forceinline__ void ld_chunk_f16(unsigned int sbase, int buf,
                                             const __half* __restrict__ A,
                                             const __half* __restrict__ Bm,
                                             int bm, int bn, int K, int k0, int tid) {
    unsigned int abuf = sbase + buf * 10240;
    unsigned int bbuf = sbase + 30720 + buf * 10240;
    #pragma unroll
    for (int i = 0; i < 4; i++) {
        int c = i * 128 + tid;
        int r = c >> 2, q = c & 3;
        cp_async16s(abuf + r * 80 + q * 16, A + (size_t)(bm + r) * K + k0 + q * 8);
        cp_async16s(bbuf + r * 80 + q * 16, Bm + (size_t)(bn + r) * K + k0 + q * 8);
    }
    asm volatile("cp.async.commit_group;\n" ::: "memory");
}

template <int EPI>
__global__ __launch_bounds__(128, 2)
void gemm_f16_kernel(const __half* __restrict__ A, const __half* __restrict__ Bm,
                     const float* __restrict__ bias, const float* __restrict__ res,
                     void* __restrict__ Cv, int M, int N, int K) {
    extern __shared__ __align__(16) char smemc[];
    unsigned int sbase = (unsigned int)__cvta_generic_to_shared(smemc);

    int bm = blockIdx.y * 128;
    int bn = blockIdx.x * 128;
    int tid = threadIdx.x;
    int warp = tid >> 5, lane = tid & 31;
    int wm = (warp & 1) * 64;
    int wn = (warp >> 1) * 64;
    int g = lane >> 2, t = lane & 3;

    int arow_off = (wm + (lane & 15)) * 80 + ((lane >> 4) * 16);
    int brow_off = (wn + (lane & 7) + ((lane >> 4) & 1) * 8) * 80
                   + (((lane >> 3) & 1) * 16);

    float acc[4][8][4];
    #pragma unroll
    for (int mi = 0; mi < 4; mi++)
        #pragma unroll
        for (int ni = 0; ni < 8; ni++)
            #pragma unroll
            for (int r = 0; r < 4; r++) acc[mi][ni][r] = 0.f;

    int KT = K >> 5;
    ld_chunk_f16(sbase, 0, A, Bm, bm, bn, K, 0, tid);
    ld_chunk_f16(sbase, 1, A, Bm, bm, bn, K, 32, tid);

    int buf = 0;
    for (int kt = 0; kt < KT; kt++) {
        if (kt + 2 < KT) {
            ld_chunk_f16(sbase, (kt + 2) % 3, A, Bm, bm, bn, K, (kt + 2) << 5, tid);
            asm volatile("cp.async.wait_group 2;\n" ::: "memory");
        } else if (kt + 1 < KT) {
            asm volatile("cp.async.wait_group 1;\n" ::: "memory");
        } else {
            asm volatile("cp.async.wait_group 0;\n" ::: "memory");
        }
        __syncthreads();

        unsigned int abase = sbase + buf * 10240;
        unsigned int bbase = sbase + 30720 + buf * 10240;
        #pragma unroll
        for (int s = 0; s < 2; s++) {
            unsigned int af[4][4], bf[8][2];
            #pragma unroll
            for (int mi = 0; mi < 4; mi++)
                ldsm_x4(af[mi][0], af[mi][1], af[mi][2], af[mi][3],
                        abase + arow_off + mi * 1280 + s * 32);
            #pragma unroll
            for (int p = 0; p < 4; p++)
                ldsm_x4(bf[2 * p][0], bf[2 * p][1], bf[2 * p + 1][0], bf[2 * p + 1][1],
                        bbase + brow_off + p * 1280 + s * 32);
            #pragma unroll
            for (int mi = 0; mi < 4; mi++)
                #pragma unroll
                for (int ni = 0; ni < 8; ni++)
                    mma_f16(acc[mi][ni], af[mi], bf[ni]);
        }
        __syncthreads();
        buf = (buf + 1) % 3;
    }

    // epilogue
    #pragma unroll
    for (int mi = 0; mi < 4; mi++) {
        #pragma unroll
        for (int ni = 0; ni < 8; ni++) {
            int col = bn + wn + ni * 8 + t * 2;
            #pragma unroll
            for (int half = 0; half < 2; half++) {
                int row = bm + wm + mi * 16 + g + half * 8;
                float vx = acc[mi][ni][half * 2 + 0] + bias[col + 0];
                float vy = acc[mi][ni][half * 2 + 1] + bias[col + 1];
                if (EPI == 1) {
                    vx = 0.5f * vx * (1.f + erff(vx * 0.7071067811865476f));
                    vy = 0.5f * vy * (1.f + erff(vy * 0.7071067811865476f));
                }
                if (EPI >= 1) {
                    __half2* C = (__half2*)((__half*)Cv + (size_t)row * N + col);
                    *C = __floats2half2_rn(vx, vy);
                } else {
                    if (res != nullptr) {
                        float2 r = *(const float2*)(res + (size_t)row * N + col);
                        vx += r.x; vy += r.y;
                    }
                    float2 v; v.x = vx; v.y = vy;
                    *(float2*)((float*)Cv + (size_t)row * N + col) = v;
                }
            }
        }
    }
}

// ---------------- K5: FP16 flash attention, double-buffered cp.async K/V -----
// q-tile 128, kv-tile 64, 8 warps x 16 q-rows, mma m16n8k16 f16, fp32 softmax.
// smem halves: Q[128*72] | K0 K1 [64*72 ea] | V0 V1 [64*72 ea] | P[128*72]
#define AHP 72
#define ATT_SMEM (512 * AHP * 2)   // 73728 B

__device__ __forceinline__ void attn_ld_kv(unsigned int kbuf, unsigned int vbuf,
                                           const __half* __restrict__ base,
                                           int jr0, int h, int tid) {
    #pragma unroll
    for (int i = 0; i < 2; i++) {
        int c = i * 256 + tid;
        int r = c >> 3, q = c & 7;
        const __half* src = base + (size_t)(jr0 + r) * (3 * D_) + h * HD + q * 8;
        cp_async16s(kbuf + r * 144 + q * 16, src + D_);
        cp_async16s(vbuf + r * 144 + q * 16, src + 2 * D_);
    }
    asm volatile("cp.async.commit_group;\n" ::: "memory");
}

__global__ __launch_bounds__(256)
void attn_f16_kernel(const __half* __restrict__ qkv, __half* __restrict__ o) {
    extern __shared__ __align__(16) char smc[];
    __half* Qh = (__half*)smc;                     // [128][AHP]
    __half* Ph = (__half*)smc + 384 * AHP;         // [128][AHP]
    unsigned int sb = (unsigned int)__cvta_generic_to_shared(smc);
    const unsigned int qb = sb;
    const unsigned int kb0 = sb + 128 * AHP * 2;   // K buffers
    const unsigned int vb0 = sb + 256 * AHP * 2;   // V buffers
    const unsigned int pb  = sb + 384 * AHP * 2;

    int qt = blockIdx.x, h = blockIdx.y, b = blockIdx.z;
    int tid = threadIdx.x;
    int warp = tid >> 5, lane = tid & 31;
    int g = lane >> 2, t = lane & 3;
    int qr0 = qt * 128;
    const __half* base = qkv + (size_t)b * S_ * (3 * D_);

    int qrow_off = (warp * 16 + (lane & 15)) * 144 + ((lane >> 4) * 16);
    int krow_off = ((lane & 7) + ((lane >> 4) & 1) * 8) * 144
                   + (((lane >> 3) & 1) * 16);
    int vrow_off = ((lane & 7) + ((lane >> 3) & 1) * 8) * 144
                   + ((lane >> 4) * 16);

    // prologue: start K/V tile 0, then fill Q while it flies
    attn_ld_kv(kb0, vb0, base, 0, h, tid);
    {
        __half2 sc = __floats2half2_rn(0.125f, 0.125f);
        for (int i = tid; i < 128 * 32; i += 256) {
            int r = i >> 5, c2 = i & 31;
            __half2 v = *(const __half2*)(base + (size_t)(qr0 + r) * (3 * D_)
                                          + h * HD + 2 * c2);
            *(__half2*)(Qh + r * AHP + 2 * c2) = __hmul2(v, sc);
        }
    }

    int row0 = warp * 16 + g;
    int row1 = row0 + 8;

    float oacc[8][4];
    float m0 = -1e30f, m1 = -1e30f, l0 = 0.f, l1 = 0.f;
    #pragma unroll
    for (int ni = 0; ni < 8; ni++)
        #pragma unroll
        for (int r = 0; r < 4; r++) oacc[ni][r] = 0.f;

    int jt_max = 2 * qt + 1;
    int buf = 0;
    for (int jt = 0; jt <= jt_max; jt++) {
        int jr0 = jt * 64;
        if (jt < jt_max) {
            attn_ld_kv(kb0 + (buf ^ 1) * 64 * AHP * 2,
                       vb0 + (buf ^ 1) * 64 * AHP * 2,
                       base, jr0 + 64, h, tid);
            asm volatile("cp.async.wait_group 1;\n" ::: "memory");
        } else {
            asm volatile("cp.async.wait_group 0;\n" ::: "memory");
        }
        __syncthreads();

        bool active = (jr0 <= qr0 + warp * 16 + 15);
        if (active) {
            unsigned int kb = kb0 + buf * 64 * AHP * 2;
            unsigned int vb = vb0 + buf * 64 * AHP * 2;

            // S = Q @ K^T
            float sacc[8][4];
            #pragma unroll
            for (int ni = 0; ni < 8; ni++)
                #pragma unroll
                for (int r = 0; r < 4; r++) sacc[ni][r] = 0.f;

            #pragma unroll
            for (int s = 0; s < 4; s++) {
                unsigned int aq[4], bk[8][2];
                ldsm_x4(aq[0], aq[1], aq[2], aq[3], qb + qrow_off + s * 32);
                #pragma unroll
                for (int p = 0; p < 4; p++)
                    ldsm_x4(bk[2 * p][0], bk[2 * p][1],
                            bk[2 * p + 1][0], bk[2 * p + 1][1],
                            kb + krow_off + p * 2304 + s * 32);
                #pragma unroll
                for (int ni = 0; ni < 8; ni++)
                    mma_f16(sacc[ni], aq, bk[ni]);
            }

            // causal mask
            if (jr0 + 63 > qr0 + warp * 16) {
                int gr0 = qr0 + row0, gr1 = qr0 + row1;
                #pragma unroll
                for (int ni = 0; ni < 8; ni++) {
                    int c0 = jr0 + ni * 8 + 2 * t;
                    if (c0 > gr0)     sacc[ni][0] = -1e30f;
                    if (c0 + 1 > gr0) sacc[ni][1] = -1e30f;
                    if (c0 > gr1)     sacc[ni][2] = -1e30f;
                    if (c0 + 1 > gr1) sacc[ni][3] = -1e30f;
                }
            }

            // online softmax (fp32)
            float mx0 = -1e30f, mx1 = -1e30f;
            #pragma unroll
            for (int ni = 0; ni < 8; ni++) {
                mx0 = fmaxf(mx0, fmaxf(sacc[ni][0], sacc[ni][1]));
                mx1 = fmaxf(mx1, fmaxf(sacc[ni][2], sacc[ni][3]));
            }
            #pragma unroll
            for (int off = 1; off < 4; off <<= 1) {
                mx0 = fmaxf(mx0, __shfl_xor_sync(0xffffffffu, mx0, off));
                mx1 = fmaxf(mx1, __shfl_xor_sync(0xffffffffu, mx1, off));
            }
            float nm0 = fmaxf(m0, mx0), nm1 = fmaxf(m1, mx1);
            float ps0 = 0.f, ps1 = 0.f;
            #pragma unroll
            for (int ni = 0; ni < 8; ni++) {
                sacc[ni][0] = __expf(sacc[ni][0] - nm0);
                sacc[ni][1] = __expf(sacc[ni][1] - nm0);
                sacc[ni][2] = __expf(sacc[ni][2] - nm1);
                sacc[ni][3] = __expf(sacc[ni][3] - nm1);
                ps0 += sacc[ni][0] + sacc[ni][1];
                ps1 += sacc[ni][2] + sacc[ni][3];
            }
            #pragma unroll
            for (int off = 1; off < 4; off <<= 1) {
                ps0 += __shfl_xor_sync(0xffffffffu, ps0, off);
                ps1 += __shfl_xor_sync(0xffffffffu, ps1, off);
            }
            float al0 = __expf(m0 - nm0), al1 = __expf(m1 - nm1);
            l0 = l0 * al0 + ps0;  m0 = nm0;
            l1 = l1 * al1 + ps1;  m1 = nm1;
            #pragma unroll
            for (int ni = 0; ni < 8; ni++) {
                oacc[ni][0] *= al0; oacc[ni][1] *= al0;
                oacc[ni][2] *= al1; oacc[ni][3] *= al1;
            }

            // P -> smem (fp16); warp-private rows
            #pragma unroll
            for (int ni = 0; ni < 8; ni++) {
                *(__half2*)(Ph + row0 * AHP + ni * 8 + 2 * t) =
                    __floats2half2_rn(sacc[ni][0], sacc[ni][1]);
                *(__half2*)(Ph + row1 * AHP + ni * 8 + 2 * t) =
                    __floats2half2_rn(sacc[ni][2], sacc[ni][3]);
            }
            __syncwarp();

            // O += P @ V  (V row-major, fragments via ldmatrix.trans)
            #pragma unroll
            for (int s = 0; s < 4; s++) {
                unsigned int ap[4], bv[8][2];
                ldsm_x4(ap[0], ap[1], ap[2], ap[3], pb + qrow_off + s * 32);
                #pragma unroll
                for (int p = 0; p < 4; p++)
                    ldsm_x4_t(bv[2 * p][0], bv[2 * p][1],
                              bv[2 * p + 1][0], bv[2 * p + 1][1],
                              vb + vrow_off + s * 2304 + p * 32);
                #pragma unroll
                for (int ni = 0; ni < 8; ni++)
                    mma_f16(oacc[ni], ap, bv[ni]);
            }
        }
        __syncthreads();   // all reads of buf done before next-iter overwrite
        buf ^= 1;
    }

    // O feeds the fp16 out-proj GEMM -> write half2
    float inv0 = 1.f / l0, inv1 = 1.f / l1;
    size_t gr0 = (size_t)(b * S_ + qr0 + row0) * D_ + h * HD;
    size_t gr1 = (size_t)(b * S_ + qr0 + row1) * D_ + h * HD;
    #pragma unroll
    for (int ni = 0; ni < 8; ni++) {
        int c = ni * 8 + 2 * t;
        *(__half2*)(o + gr0 + c) = __floats2half2_rn(oacc[ni][0] * inv0,
                                                     oacc[ni][1] * inv0);
        *(__half2*)(o + gr1 + c) = __floats2half2_rn(oacc[ni][2] * inv1,
                                                     oacc[ni][3] * inv1);
    }
}

// ---------------- K10: final sum + mhc mix ----------------------------------
__global__ void final_kernel(const float* __restrict__ attnres,
                             const float* __restrict__ ffn,
                             const float* __restrict__ xd,
                             const float* __restrict__ W,
                             float* __restrict__ out) {
    __shared__ float row[D_];
    __shared__ float Ws[64];
    int r = blockIdx.x;
    int b = r >> 11;
    int tid = threadIdx.x;
    ((float4*)row)[tid] = ((const float4*)(xd + (size_t)r * D_))[tid];
    if (tid < 64) Ws[tid] = W[b * 64 + tid];
    __syncthreads();

    int c0 = tid * 4;
    int m = c0 >> 7;
    int dp = c0 & 127;
    float mh0 = 0.f, mh1 = 0.f, mh2 = 0.f, mh3 = 0.f;
    #pragma unroll
    for (int n = 0; n < 8; n++) {
        float w = Ws[m * 8 + n];
        const float* rp = row + n * 128 + dp;
        mh0 += w * rp[0]; mh1 += w * rp[1]; mh2 += w * rp[2]; mh3 += w * rp[3];
    }
    float4 a = ((const float4*)(attnres + (size_t)r * D_))[tid];
    float4 f = ((const float4*)(ffn + (size_t)r * D_))[tid];
    float4 ov;
    ov.x = a.x + f.x + mh0;
    ov.y = a.y + f.y + mh1;
    ov.z = a.z + f.z + mh2;
    ov.w = a.w + f.w + mh3;
    ((float4*)(out + (size_t)r * D_))[tid] = ov;
}

// ---------------- launch ----------------------------------------------------
extern "C" void kernel_launch(void* const* d_in, const int* in_sizes, int n_in,
                              void* d_out, int out_size) {
    const float* x        = (const float*)d_in[0];
    const float* decay    = (const float*)d_in[3];
    const float* gate_w   = (const float*)d_in[4];
    const float* gate_b   = (const float*)d_in[5];
    const float* phi      = (const float*)d_in[6];
    const float* ln1_w    = (const float*)d_in[7];
    const float* ln2_w    = (const float*)d_in[8];
    const float* w1       = (const float*)d_in[9];
    const float* b1       = (const float*)d_in[10];
    const float* w2       = (const float*)d_in[11];
    const float* b2       = (const float*)d_in[12];
    const float* in_proj_w= (const float*)d_in[13];
    const float* in_proj_b= (const float*)d_in[14];
    const float* out_w    = (const float*)d_in[15];
    const float* out_b    = (const float*)d_in[16];
    float* out = (float*)d_out;

    void *p_xdelta, *p_xstate, *p_W, *p_qkvh, *p_attnres, *p_ffn,
         *p_normed, *p_normed2, *p_oh, *p_hh, *p_wqkv, *p_wout, *p_w1, *p_w2;
    cudaGetSymbolAddress(&p_xdelta, g_xdelta);
    cudaGetSymbolAddress(&p_xstate, g_xstate);
    cudaGetSymbolAddress(&p_W, g_W);
    cudaGetSymbolAddress(&p_qkvh, g_qkv_h);
    cudaGetSymbolAddress(&p_attnres, g_attnres);
    cudaGetSymbolAddress(&p_ffn, g_ffn);
    cudaGetSymbolAddress(&p_normed, g_normed_h);
    cudaGetSymbolAddress(&p_normed2, g_normed2_h);
    cudaGetSymbolAddress(&p_oh, g_o_h);
    cudaGetSymbolAddress(&p_hh, g_h_h);
    cudaGetSymbolAddress(&p_wqkv, g_wqkv_h);
    cudaGetSymbolAddress(&p_wout, g_wout_h);
    cudaGetSymbolAddress(&p_w1, g_w1_h);
    cudaGetSymbolAddress(&p_w2, g_w2_h);

    float*  xdelta   = (float*)p_xdelta;
    float*  xstate   = (float*)p_xstate;
    float*  Wm       = (float*)p_W;
    __half* qkv_h    = (__half*)p_qkvh;
    float*  attnres  = (float*)p_attnres;
    float*  ffn      = (float*)p_ffn;
    __half* normed_h = (__half*)p_normed;
    __half* normed2_h= (__half*)p_normed2;
    __half* o_h      = (__half*)p_oh;
    __half* h_h      = (__half*)p_hh;
    __half* wqkv_h   = (__half*)p_wqkv;
    __half* wout_h   = (__half*)p_wout;
    __half* w1_h     = (__half*)p_w1;
    __half* w2_h     = (__half*)p_w2;

    cudaFuncSetAttribute(gemm_f16_kernel<0>,
                         cudaFuncAttributeMaxDynamicSharedMemorySize, GEMM_SMEM_H);
    cudaFuncSetAttribute(gemm_f16_kernel<1>,
                         cudaFuncAttributeMaxDynamicSharedMemorySize, GEMM_SMEM_H);
    cudaFuncSetAttribute(gemm_f16_kernel<2>,
                         cudaFuncAttributeMaxDynamicSharedMemorySize, GEMM_SMEM_H);
    cudaFuncSetAttribute(attn_f16_kernel,
                         cudaFuncAttributeMaxDynamicSharedMemorySize, ATT_SMEM);

    // 0) convert all weights to fp16 (single launch)
    tohalf4_kernel<<<2048, 256>>>(
        (const float4*)in_proj_w, (__half2*)wqkv_h, 3 * D_ * D_ / 4,
        (const float4*)out_w,     (__half2*)wout_h, D_ * D_ / 4,
        (const float4*)w1,        (__half2*)w1_h,   4 * D_ * D_ / 4,
        (const float4*)w2,        (__half2*)w2_h,   4 * D_ * D_ / 4);

    // 1) delta scan (coalesced)
    delta_scan_kernel<<<B_ * D_ / 32, 512>>>(x, decay, xdelta, xstate);
    // 2) gates + sinkhorn
    gate_sinkhorn_kernel<<<1, 256>>>(xstate, gate_w, gate_b, phi, Wm);
    // 3) rmsnorm1 (fp16 output)
    rmsnorm_kernel<<<NTOK, 256>>>(xdelta, ln1_w, normed_h);
    // 4) qkv projection (fp16 mma, fp16 out)
    gemm_f16_kernel<2><<<dim3(3 * D_ / 128, NTOK / 128), 128, GEMM_SMEM_H>>>(
        normed_h, wqkv_h, in_proj_b, nullptr, qkv_h, NTOK, 3 * D_, D_);
    // 5) attention (fp16 flash), fp16 output
    attn_f16_kernel<<<dim3(S_ / 128, NH, B_), 256, ATT_SMEM>>>(qkv_h, o_h);
    // 6) out projection + residual(x_delta), fp32 out
    gemm_f16_kernel<0><<<dim3(D_ / 128, NTOK / 128), 128, GEMM_SMEM_H>>>(
        o_h, wout_h, out_b, xdelta, attnres, NTOK, D_, D_);
    // 7) rmsnorm2 (fp16 output)
    rmsnorm_kernel<<<NTOK, 256>>>(attnres, ln2_w, normed2_h);
    // 8) FFN1 + gelu (fp16 out)
    gemm_f16_kernel<1><<<dim3(4 * D_ / 128, NTOK / 128), 128, GEMM_SMEM_H>>>(
        normed2_h, w1_h, b1, nullptr, h_h, NTOK, 4 * D_, D_);
    // 9) FFN2 (fp32 out)
    gemm_f16_kernel<0><<<dim3(D_ / 128, NTOK / 128), 128, GEMM_SMEM_H>>>(
        h_h, w2_h, b2, nullptr, ffn, NTOK, D_, 4 * D_);
    // 10) final
    final_kernel<<<NTOK, 256>>>(attnres, ffn, xdelta, Wm, out);
}